// round 2
// baseline (speedup 1.0000x reference)
#include <cuda_runtime.h>
#include <cuda_bf16.h>
#include <cstdint>
#include <math.h>

// ---------------------------------------------------------------------------
// IntraSentenceGNN: 3-node GATv2 stack, B=32768, D=H=1024, HEADS=8, DH=128
//
// Pipeline (all fp32 this round):
//  1. Fuse modality projection into layer-1 GAT weights:
//       Wf[c] = W_m @ W{l|r}1  (6x 1024^3 GEMM),  bf[c] = b_m @ W{l|r}1
//  2. gl1/gr1 = feat_m @ Wf + bf   (6x [32768,1024]x[1024,1024])
//  3. GAT1 attention (8 heads, dh=128) + b1 + ELU -> x1 [B,3,1024]
//  4. gl2/gr2 = x1 @ W{l|r}2       (2x [98304,1024]x[1024,1024])
//  5. GAT2 attention (1 head, d=1024) + b2 + mean over nodes -> out [B,1024]
// ---------------------------------------------------------------------------

#define BATCH 32768
#define HDIM  1024

// Scratch (device globals: allocation-free per harness rules)
__device__ float g_Wf[6 * 1024 * 1024];          // 24 MB fused weights
__device__ float g_bf[6 * 1024];                 // fused biases
__device__ float g_gl1[BATCH * 3 * HDIM];        // 402 MB
__device__ float g_gr1[BATCH * 3 * HDIM];
__device__ float g_x1 [BATCH * 3 * HDIM];
__device__ float g_gl2[BATCH * 3 * HDIM];
__device__ float g_gr2[BATCH * 3 * HDIM];

// ---------------------------------------------------------------------------
// SGEMM: C[M,N] = A[M,K] @ B[K,N] (+ bias[N]), all row-major.
// 128x128 block tile, BK=16, 256 threads, 8x8 per thread, float4 everywhere.
// ---------------------------------------------------------------------------
#define BM 128
#define BN 128
#define BK 16
#define TM 8
#define TN 8

__global__ __launch_bounds__(256) void sgemm_kernel(
    int M, int N, int K,
    const float* __restrict__ A, int lda,
    const float* __restrict__ B, int ldb,
    float* __restrict__ C, int ldc,
    const float* __restrict__ bias)
{
    __shared__ float As[BK][BM + 4];   // padded; row stride 132 floats = 528B (16B aligned)
    __shared__ float Bs[BK][BN];

    const int crow = blockIdx.y * BM;
    const int ccol = blockIdx.x * BN;
    const int tid  = threadIdx.x;

    const int tRow = (tid / 16) * TM;
    const int tCol = (tid % 16) * TN;

    // A tile loads: 128 rows x 16 cols, 2 float4 per thread
    const int aRow = tid / 4;            // 0..63
    const int aCol = (tid % 4) * 4;      // 0,4,8,12
    // B tile loads: 16 rows x 128 cols, 2 float4 per thread
    const int bRow = tid / 32;           // 0..7
    const int bCol = (tid % 32) * 4;     // 0..124

    float acc[TM][TN];
    #pragma unroll
    for (int i = 0; i < TM; i++)
        #pragma unroll
        for (int j = 0; j < TN; j++) acc[i][j] = 0.0f;

    const float* Aptr = A + (size_t)crow * lda;
    const float* Bptr = B + ccol;

    for (int k0 = 0; k0 < K; k0 += BK) {
        #pragma unroll
        for (int r = 0; r < 2; r++) {
            const int row = aRow + 64 * r;
            float4 v = *reinterpret_cast<const float4*>(Aptr + (size_t)row * lda + k0 + aCol);
            As[aCol + 0][row] = v.x;
            As[aCol + 1][row] = v.y;
            As[aCol + 2][row] = v.z;
            As[aCol + 3][row] = v.w;
        }
        #pragma unroll
        for (int r = 0; r < 2; r++) {
            const int row = bRow + 8 * r;
            float4 v = *reinterpret_cast<const float4*>(Bptr + (size_t)(k0 + row) * ldb + bCol);
            *reinterpret_cast<float4*>(&Bs[row][bCol]) = v;
        }
        __syncthreads();

        #pragma unroll
        for (int k = 0; k < BK; k++) {
            float regM[TM], regN[TN];
            float4 m0 = *reinterpret_cast<const float4*>(&As[k][tRow]);
            float4 m1 = *reinterpret_cast<const float4*>(&As[k][tRow + 4]);
            regM[0]=m0.x; regM[1]=m0.y; regM[2]=m0.z; regM[3]=m0.w;
            regM[4]=m1.x; regM[5]=m1.y; regM[6]=m1.z; regM[7]=m1.w;
            float4 n0 = *reinterpret_cast<const float4*>(&Bs[k][tCol]);
            float4 n1 = *reinterpret_cast<const float4*>(&Bs[k][tCol + 4]);
            regN[0]=n0.x; regN[1]=n0.y; regN[2]=n0.z; regN[3]=n0.w;
            regN[4]=n1.x; regN[5]=n1.y; regN[6]=n1.z; regN[7]=n1.w;
            #pragma unroll
            for (int i = 0; i < TM; i++)
                #pragma unroll
                for (int j = 0; j < TN; j++)
                    acc[i][j] += regM[i] * regN[j];
        }
        __syncthreads();
    }

    #pragma unroll
    for (int i = 0; i < TM; i++) {
        float* cp = C + (size_t)(crow + tRow + i) * ldc + ccol + tCol;
        #pragma unroll
        for (int j = 0; j < TN; j += 4) {
            float4 v;
            v.x = acc[i][j + 0];
            v.y = acc[i][j + 1];
            v.z = acc[i][j + 2];
            v.w = acc[i][j + 3];
            if (bias) {
                const float4 bv = *reinterpret_cast<const float4*>(bias + ccol + tCol + j);
                v.x += bv.x; v.y += bv.y; v.z += bv.z; v.w += bv.w;
            }
            *reinterpret_cast<float4*>(cp + j) = v;
        }
    }
}

// ---------------------------------------------------------------------------
// Fused bias precompute: bf[c][j] = sum_k bmod[c%3][k] * W{l|r}1[k][j]
// combos c: 0..2 -> l-side (t,a,v), 3..5 -> r-side
// ---------------------------------------------------------------------------
__global__ void bias_fold_kernel(
    const float* __restrict__ bt, const float* __restrict__ ba,
    const float* __restrict__ bv,
    const float* __restrict__ Wl1, const float* __restrict__ Wr1,
    float* __restrict__ bf)
{
    int g = blockIdx.x * blockDim.x + threadIdx.x;   // 0..6143
    if (g >= 6 * 1024) return;
    int combo = g >> 10;
    int j = g & 1023;
    int m = combo % 3;
    const float* bvec = (m == 0) ? bt : (m == 1) ? ba : bv;
    const float* W = (combo < 3) ? Wl1 : Wr1;
    float s = 0.0f;
    for (int k = 0; k < 1024; k++) s += bvec[k] * W[k * 1024 + j];
    bf[g] = s;
}

// ---------------------------------------------------------------------------
// GAT1: 8 heads, dh=128. One block per sentence, one warp per head.
// e[i][j] = sum_d att1[h][d] * lrelu(gl[j,h,d] + gr[i,h,d]); softmax over j;
// x1[i,h,d] = elu(sum_j alpha[i][j] * gl[j,h,d] + b1[h*128+d])
// ---------------------------------------------------------------------------
__device__ __forceinline__ float lrelu02(float x) {
    return x > 0.0f ? x : 0.2f * x;
}

__global__ __launch_bounds__(256) void gat1_kernel(
    const float* __restrict__ gl, const float* __restrict__ gr,
    const float* __restrict__ att, const float* __restrict__ b1,
    float* __restrict__ x1)
{
    const int b = blockIdx.x;
    const int h = threadIdx.x >> 5;
    const int lane = threadIdx.x & 31;
    const int dbase = lane * 4;

    const size_t base = (size_t)b * 3072 + h * 128 + dbase;
    float4 glv[3], grv[3];
    #pragma unroll
    for (int j = 0; j < 3; j++)
        glv[j] = *reinterpret_cast<const float4*>(gl + base + j * 1024);
    #pragma unroll
    for (int i = 0; i < 3; i++)
        grv[i] = *reinterpret_cast<const float4*>(gr + base + i * 1024);
    const float4 av = *reinterpret_cast<const float4*>(att + h * 128 + dbase);

    float e[3][3];
    #pragma unroll
    for (int i = 0; i < 3; i++) {
        #pragma unroll
        for (int j = 0; j < 3; j++) {
            float s = av.x * lrelu02(glv[j].x + grv[i].x);
            s += av.y * lrelu02(glv[j].y + grv[i].y);
            s += av.z * lrelu02(glv[j].z + grv[i].z);
            s += av.w * lrelu02(glv[j].w + grv[i].w);
            e[i][j] = s;
        }
    }
    // full butterfly reduce: every lane ends with the warp sum
    #pragma unroll
    for (int i = 0; i < 3; i++)
        #pragma unroll
        for (int j = 0; j < 3; j++)
            #pragma unroll
            for (int o = 16; o > 0; o >>= 1)
                e[i][j] += __shfl_xor_sync(0xFFFFFFFFu, e[i][j], o);

    float alpha[3][3];
    #pragma unroll
    for (int i = 0; i < 3; i++) {
        float mx = fmaxf(e[i][0], fmaxf(e[i][1], e[i][2]));
        float p0 = expf(e[i][0] - mx);
        float p1 = expf(e[i][1] - mx);
        float p2 = expf(e[i][2] - mx);
        float inv = 1.0f / (p0 + p1 + p2);
        alpha[i][0] = p0 * inv; alpha[i][1] = p1 * inv; alpha[i][2] = p2 * inv;
    }

    const float4 bb = *reinterpret_cast<const float4*>(b1 + h * 128 + dbase);
    #pragma unroll
    for (int i = 0; i < 3; i++) {
        float4 o;
        o.x = alpha[i][0]*glv[0].x + alpha[i][1]*glv[1].x + alpha[i][2]*glv[2].x + bb.x;
        o.y = alpha[i][0]*glv[0].y + alpha[i][1]*glv[1].y + alpha[i][2]*glv[2].y + bb.y;
        o.z = alpha[i][0]*glv[0].z + alpha[i][1]*glv[1].z + alpha[i][2]*glv[2].z + bb.z;
        o.w = alpha[i][0]*glv[0].w + alpha[i][1]*glv[1].w + alpha[i][2]*glv[2].w + bb.w;
        // ELU (alpha=1)
        o.x = o.x > 0.0f ? o.x : (expf(o.x) - 1.0f);
        o.y = o.y > 0.0f ? o.y : (expf(o.y) - 1.0f);
        o.z = o.z > 0.0f ? o.z : (expf(o.z) - 1.0f);
        o.w = o.w > 0.0f ? o.w : (expf(o.w) - 1.0f);
        *reinterpret_cast<float4*>(x1 + (size_t)b * 3072 + i * 1024 + h * 128 + dbase) = o;
    }
}

// ---------------------------------------------------------------------------
// GAT2: 1 head, d=1024, concat=False (mean over the single head = identity),
// then global mean pool over the 3 nodes.
// out[b,d] = sum_j w[j]*gl2[b,j,d] + b2[d], with w[j] = (1/3) sum_i alpha[i][j]
// One warp per sentence; lanes stride over d in float4 chunks.
// ---------------------------------------------------------------------------
__global__ __launch_bounds__(256) void gat2_kernel(
    const float* __restrict__ gl, const float* __restrict__ gr,
    const float* __restrict__ att, const float* __restrict__ b2,
    float* __restrict__ out)
{
    const int b = blockIdx.x * 8 + (threadIdx.x >> 5);
    const int lane = threadIdx.x & 31;
    const float* glb = gl + (size_t)b * 3072;
    const float* grb = gr + (size_t)b * 3072;

    float e[9] = {0,0,0,0,0,0,0,0,0};
    #pragma unroll
    for (int c = 0; c < 8; c++) {
        const int d = c * 128 + lane * 4;
        const float4 av = *reinterpret_cast<const float4*>(att + d);
        float4 glv[3], grv[3];
        #pragma unroll
        for (int j = 0; j < 3; j++)
            glv[j] = *reinterpret_cast<const float4*>(glb + j * 1024 + d);
        #pragma unroll
        for (int i = 0; i < 3; i++)
            grv[i] = *reinterpret_cast<const float4*>(grb + i * 1024 + d);
        #pragma unroll
        for (int i = 0; i < 3; i++)
            #pragma unroll
            for (int j = 0; j < 3; j++) {
                float s = av.x * lrelu02(glv[j].x + grv[i].x);
                s += av.y * lrelu02(glv[j].y + grv[i].y);
                s += av.z * lrelu02(glv[j].z + grv[i].z);
                s += av.w * lrelu02(glv[j].w + grv[i].w);
                e[i * 3 + j] += s;
            }
    }
    #pragma unroll
    for (int k = 0; k < 9; k++)
        #pragma unroll
        for (int o = 16; o > 0; o >>= 1)
            e[k] += __shfl_xor_sync(0xFFFFFFFFu, e[k], o);

    float w[3] = {0.0f, 0.0f, 0.0f};
    #pragma unroll
    for (int i = 0; i < 3; i++) {
        float mx = fmaxf(e[i*3+0], fmaxf(e[i*3+1], e[i*3+2]));
        float p0 = expf(e[i*3+0] - mx);
        float p1 = expf(e[i*3+1] - mx);
        float p2 = expf(e[i*3+2] - mx);
        float inv = 1.0f / (p0 + p1 + p2);
        w[0] += p0 * inv; w[1] += p1 * inv; w[2] += p2 * inv;
    }
    w[0] *= (1.0f / 3.0f); w[1] *= (1.0f / 3.0f); w[2] *= (1.0f / 3.0f);

    #pragma unroll
    for (int c = 0; c < 8; c++) {
        const int d = c * 128 + lane * 4;
        const float4 bv = *reinterpret_cast<const float4*>(b2 + d);
        float4 g0 = *reinterpret_cast<const float4*>(glb + 0 * 1024 + d);
        float4 g1 = *reinterpret_cast<const float4*>(glb + 1 * 1024 + d);
        float4 g2 = *reinterpret_cast<const float4*>(glb + 2 * 1024 + d);
        float4 o;
        o.x = w[0]*g0.x + w[1]*g1.x + w[2]*g2.x + bv.x;
        o.y = w[0]*g0.y + w[1]*g1.y + w[2]*g2.y + bv.y;
        o.z = w[0]*g0.z + w[1]*g1.z + w[2]*g2.z + bv.z;
        o.w = w[0]*g0.w + w[1]*g1.w + w[2]*g2.w + bv.w;
        *reinterpret_cast<float4*>(out + (size_t)b * 1024 + d) = o;
    }
}

// ---------------------------------------------------------------------------
// Launch
// ---------------------------------------------------------------------------
extern "C" void kernel_launch(void* const* d_in, const int* in_sizes, int n_in,
                              void* d_out, int out_size)
{
    const float* feats[3] = { (const float*)d_in[0], (const float*)d_in[1], (const float*)d_in[2] };
    const float* Wm[3]    = { (const float*)d_in[3], (const float*)d_in[5], (const float*)d_in[7] };
    const float* bt   = (const float*)d_in[4];
    const float* ba   = (const float*)d_in[6];
    const float* bv   = (const float*)d_in[8];
    const float* Wl1  = (const float*)d_in[9];
    const float* Wr1  = (const float*)d_in[10];
    const float* att1 = (const float*)d_in[11];
    const float* b1   = (const float*)d_in[12];
    const float* Wl2  = (const float*)d_in[13];
    const float* Wr2  = (const float*)d_in[14];
    const float* att2 = (const float*)d_in[15];
    const float* b2   = (const float*)d_in[16];
    float* out = (float*)d_out;

    float *Wf, *bf, *gl1, *gr1, *x1, *gl2, *gr2;
    cudaGetSymbolAddress((void**)&Wf,  g_Wf);
    cudaGetSymbolAddress((void**)&bf,  g_bf);
    cudaGetSymbolAddress((void**)&gl1, g_gl1);
    cudaGetSymbolAddress((void**)&gr1, g_gr1);
    cudaGetSymbolAddress((void**)&x1,  g_x1);
    cudaGetSymbolAddress((void**)&gl2, g_gl2);
    cudaGetSymbolAddress((void**)&gr2, g_gr2);

    // 1. Fused weights: Wf[c] = Wm[c%3] @ (c<3 ? Wl1 : Wr1)
    {
        dim3 grid(1024 / BN, 1024 / BM);
        for (int c = 0; c < 6; c++) {
            const float* Bmat = (c < 3) ? Wl1 : Wr1;
            sgemm_kernel<<<grid, 256>>>(1024, 1024, 1024,
                Wm[c % 3], 1024, Bmat, 1024,
                Wf + (size_t)c * 1024 * 1024, 1024, nullptr);
        }
    }
    // fused biases
    bias_fold_kernel<<<24, 256>>>(bt, ba, bv, Wl1, Wr1, bf);

    // 2. gl1/gr1 = feat_m @ Wf[c] + bf[c]  (written interleaved into [B,3,H])
    {
        dim3 grid(1024 / BN, BATCH / BM);
        for (int m = 0; m < 3; m++) {
            sgemm_kernel<<<grid, 256>>>(BATCH, 1024, 1024,
                feats[m], 1024, Wf + (size_t)m * 1024 * 1024, 1024,
                gl1 + m * 1024, 3 * 1024, bf + m * 1024);
            sgemm_kernel<<<grid, 256>>>(BATCH, 1024, 1024,
                feats[m], 1024, Wf + (size_t)(3 + m) * 1024 * 1024, 1024,
                gr1 + m * 1024, 3 * 1024, bf + (3 + m) * 1024);
        }
    }

    // 3. GAT1 attention + b1 + ELU -> x1
    gat1_kernel<<<BATCH, 256>>>(gl1, gr1, att1, b1, x1);

    // 4. gl2/gr2 = x1 @ W{l|r}2 over [3B, 1024]
    {
        dim3 grid(1024 / BN, (3 * BATCH) / BM);
        sgemm_kernel<<<grid, 256>>>(3 * BATCH, 1024, 1024,
            x1, 1024, Wl2, 1024, gl2, 1024, nullptr);
        sgemm_kernel<<<grid, 256>>>(3 * BATCH, 1024, 1024,
            x1, 1024, Wr2, 1024, gr2, 1024, nullptr);
    }

    // 5. GAT2 attention + b2 + mean-pool -> out
    gat2_kernel<<<BATCH / 8, 256>>>(gl2, gr2, att2, b2, out);
}

// round 4
// speedup vs baseline: 2.7014x; 2.7014x over previous
#include <cuda_runtime.h>
#include <cuda_bf16.h>
#include <cstdint>
#include <math.h>

// ---------------------------------------------------------------------------
// IntraSentenceGNN on GB300 (sm_103 base ISA): all GEMMs via mma.sync bf16
// (legacy HMMA pipe; tcgen05 PTX not accepted by this toolchain target)
// with hi/lo 3-term split for fp32-equivalent precision (~2^-16).
//
//  1. split/transpose weights -> bf16 hi/lo [N,K] K-major
//  2. fold: Wf[c] = Wm[c%3] @ W{l|r}1  (6x 1024^3)
//  3. gl1/gr1 = feat_m @ Wf + bf      (6x 32768x1024x1024)
//  4. GAT1 attention + ELU -> x1 (emitted directly as bf16 hi/lo)
//  5. gl2/gr2 = x1 @ W{l|r}2          (2x 98304x1024x1024)
//  6. GAT2 attention + mean-pool -> out
// ---------------------------------------------------------------------------

#define BATCH 32768
#define HDIM  1024

typedef __nv_bfloat16 bf16;

// ------------------------------ scratch -----------------------------------
__device__ __align__(256) float g_Wf [6 * 1024 * 1024];
__device__ __align__(256) float g_bf [6 * 1024];
__device__ __align__(256) float g_gl1[BATCH * 3 * HDIM];
__device__ __align__(256) float g_gr1[BATCH * 3 * HDIM];
__device__ __align__(256) float g_gl2[BATCH * 3 * HDIM];
__device__ __align__(256) float g_gr2[BATCH * 3 * HDIM];

__device__ __align__(256) bf16 g_WmH [3 * 1024 * 1024];
__device__ __align__(256) bf16 g_WmL [3 * 1024 * 1024];
__device__ __align__(256) bf16 g_WT1H[2 * 1024 * 1024];
__device__ __align__(256) bf16 g_WT1L[2 * 1024 * 1024];
__device__ __align__(256) bf16 g_WT2H[2 * 1024 * 1024];
__device__ __align__(256) bf16 g_WT2L[2 * 1024 * 1024];
__device__ __align__(256) bf16 g_WfTH[6 * 1024 * 1024];
__device__ __align__(256) bf16 g_WfTL[6 * 1024 * 1024];
__device__ __align__(256) bf16 g_featH[3 * BATCH * 1024];
__device__ __align__(256) bf16 g_featL[3 * BATCH * 1024];
__device__ __align__(256) bf16 g_x1H[BATCH * 3 * 1024];
__device__ __align__(256) bf16 g_x1L[BATCH * 3 * 1024];

// --------------------------- PTX helpers ----------------------------------
__device__ __forceinline__ uint32_t smem_u32(const void* p) {
    uint32_t a;
    asm("{ .reg .u64 t; cvta.to.shared.u64 t, %1; cvt.u32.u64 %0, t; }"
        : "=r"(a) : "l"(p));
    return a;
}
__device__ __forceinline__ void cp16(uint32_t sdst, const void* gsrc) {
    asm volatile("cp.async.cg.shared.global [%0], [%1], 16;" :: "r"(sdst), "l"(gsrc));
}
__device__ __forceinline__ void cp_commit() {
    asm volatile("cp.async.commit_group;" ::: "memory");
}
__device__ __forceinline__ void cp_wait1() {
    asm volatile("cp.async.wait_group 1;" ::: "memory");
}
__device__ __forceinline__ void cp_wait0() {
    asm volatile("cp.async.wait_group 0;" ::: "memory");
}

// swizzled 32-bit shared load: tile rows are 128B (64 bf16), SW128 pattern
__device__ __forceinline__ uint32_t lds32_sw(uint32_t base, int row, int col) {
    uint32_t off = (uint32_t)(row * 128 + col * 2);
    off ^= (off >> 3) & 0x70;
    uint32_t v;
    asm volatile("ld.shared.b32 %0, [%1];" : "=r"(v) : "r"(base + off));
    return v;
}

__device__ __forceinline__ void mma16816(float* c, const uint32_t* a, const uint32_t* b) {
    asm volatile(
        "mma.sync.aligned.m16n8k16.row.col.f32.bf16.bf16.f32 "
        "{%0,%1,%2,%3}, {%4,%5,%6,%7}, {%8,%9}, {%0,%1,%2,%3};"
        : "+f"(c[0]), "+f"(c[1]), "+f"(c[2]), "+f"(c[3])
        : "r"(a[0]), "r"(a[1]), "r"(a[2]), "r"(a[3]), "r"(b[0]), "r"(b[1]));
}

// ---------------------------------------------------------------------------
// bf16x3 GEMM: C[M,N] = sum_k A[m,k]*BT[n,k] (+ bias[n])
//   A = Ah + Al, BT = Bh + Bl; accumulate AhBh + AhBl + AlBh in fp32.
// CTA tile 128x128, BK=64, 3-stage cp.async, 8 warps (4m x 2n), warp 32x64.
// smem/stage: Ah,Al,Bh,Bl each 128x64 bf16 (16KB) = 64KB; 3 stages = 192KB.
// ---------------------------------------------------------------------------
#define GEMM_SMEM (3 * 65536)

__global__ __launch_bounds__(256, 1) void gemm_bf16x3(
    int M, int N, int K,
    const bf16* __restrict__ Ah, const bf16* __restrict__ Al, int lda,
    const bf16* __restrict__ Bh, const bf16* __restrict__ Bl, int ldb,
    float* __restrict__ C, int ldc, const float* __restrict__ bias)
{
    extern __shared__ char smem[];
    const uint32_t sbase = smem_u32(smem);
    const int tid  = threadIdx.x;
    const int wid  = tid >> 5;
    const int lane = tid & 31;
    const int warp_m = wid & 3;        // 0..3 -> 32-row slices
    const int warp_n = wid >> 2;       // 0..1 -> 64-col slices

    const int mblk = blockIdx.y * 128;
    const int nblk = blockIdx.x * 128;

    const int KT = K >> 6;             // K/64 tiles

    // load one 64KB stage: 4 sub-tiles (Ah,Al,Bh,Bl), each 128 rows x 128B
    auto load_tile = [&](int kt, int s) {
        const uint32_t st = sbase + s * 65536;
        const int kofs = kt * 64;
        #pragma unroll
        for (int v = 0; v < 4; v++) {
            const bf16* src = (v == 0) ? Ah : (v == 1) ? Al : (v == 2) ? Bh : Bl;
            const int blk  = (v < 2) ? mblk : nblk;
            const int ld   = (v < 2) ? lda : ldb;
            const uint32_t rb = st + v * 16384;
            #pragma unroll
            for (int i = 0; i < 4; i++) {
                const int c = tid + i * 256;          // 0..1023
                const int row = c >> 3, kc = c & 7;   // kc: 16B chunk
                const void* g = src + (size_t)(blk + row) * ld + kofs + kc * 8;
                uint32_t off = (uint32_t)(row * 128 + kc * 16);
                off ^= (off >> 3) & 0x70;
                cp16(rb + off, g);
            }
        }
        cp_commit();
    };

    float acc[2][8][4];
    #pragma unroll
    for (int mt = 0; mt < 2; mt++)
        #pragma unroll
        for (int nt = 0; nt < 8; nt++)
            #pragma unroll
            for (int q = 0; q < 4; q++) acc[mt][nt][q] = 0.0f;

    load_tile(0, 0);
    load_tile(1, 1);

    for (int kt = 0; kt < KT; kt++) {
        if (kt + 1 < KT) cp_wait1(); else cp_wait0();
        __syncthreads();

        const uint32_t st  = sbase + (kt % 3) * 65536;
        const uint32_t sAh = st,         sAl = st + 16384;
        const uint32_t sBh = st + 32768, sBl = st + 49152;

        const int r0 = warp_m * 32 + (lane >> 2);
        const int n0 = warp_n * 64 + (lane >> 2);
        const int c0 = (lane & 3) * 2;

        #pragma unroll
        for (int ks = 0; ks < 4; ks++) {
            const int kb = ks * 16 + c0;
            uint32_t afr[2][2][4];     // [half][mtile][reg]
            #pragma unroll
            for (int mt = 0; mt < 2; mt++) {
                const int rr = r0 + mt * 16;
                afr[0][mt][0] = lds32_sw(sAh, rr,     kb);
                afr[0][mt][1] = lds32_sw(sAh, rr + 8, kb);
                afr[0][mt][2] = lds32_sw(sAh, rr,     kb + 8);
                afr[0][mt][3] = lds32_sw(sAh, rr + 8, kb + 8);
                afr[1][mt][0] = lds32_sw(sAl, rr,     kb);
                afr[1][mt][1] = lds32_sw(sAl, rr + 8, kb);
                afr[1][mt][2] = lds32_sw(sAl, rr,     kb + 8);
                afr[1][mt][3] = lds32_sw(sAl, rr + 8, kb + 8);
            }
            uint32_t bfr[2][8][2];
            #pragma unroll
            for (int nt = 0; nt < 8; nt++) {
                const int nr = n0 + nt * 8;
                bfr[0][nt][0] = lds32_sw(sBh, nr, kb);
                bfr[0][nt][1] = lds32_sw(sBh, nr, kb + 8);
                bfr[1][nt][0] = lds32_sw(sBl, nr, kb);
                bfr[1][nt][1] = lds32_sw(sBl, nr, kb + 8);
            }
            #pragma unroll
            for (int mt = 0; mt < 2; mt++)
                #pragma unroll
                for (int nt = 0; nt < 8; nt++) {
                    mma16816(acc[mt][nt], afr[0][mt], bfr[0][nt]);
                    mma16816(acc[mt][nt], afr[0][mt], bfr[1][nt]);
                    mma16816(acc[mt][nt], afr[1][mt], bfr[0][nt]);
                }
        }
        __syncthreads();
        if (kt + 2 < KT) load_tile(kt + 2, (kt + 2) % 3);
    }

    // epilogue: direct fragment stores (float2), optional bias
    #pragma unroll
    for (int mt = 0; mt < 2; mt++) {
        const int row = mblk + warp_m * 32 + mt * 16 + (lane >> 2);
        #pragma unroll
        for (int nt = 0; nt < 8; nt++) {
            const int col = nblk + warp_n * 64 + nt * 8 + (lane & 3) * 2;
            float b0 = 0.0f, b1 = 0.0f;
            if (bias) { b0 = bias[col]; b1 = bias[col + 1]; }
            float2 v0 = make_float2(acc[mt][nt][0] + b0, acc[mt][nt][1] + b1);
            float2 v1 = make_float2(acc[mt][nt][2] + b0, acc[mt][nt][3] + b1);
            *reinterpret_cast<float2*>(C + (size_t)row * ldc + col) = v0;
            *reinterpret_cast<float2*>(C + (size_t)(row + 8) * ldc + col) = v1;
        }
    }
}

// ---------------------------------------------------------------------------
// fp32 -> bf16 hi/lo split (elementwise, float4)
// ---------------------------------------------------------------------------
__device__ __forceinline__ void split1(float x, bf16& h, bf16& l) {
    h = __float2bfloat16(x);
    l = __float2bfloat16(x - __bfloat162float(h));
}

__global__ void split_kernel(const float* __restrict__ in,
                             bf16* __restrict__ hi, bf16* __restrict__ lo, int n)
{
    int i = (blockIdx.x * blockDim.x + threadIdx.x) * 4;
    if (i >= n) return;
    float4 v = *reinterpret_cast<const float4*>(in + i);
    bf16 h[4], l[4];
    split1(v.x, h[0], l[0]); split1(v.y, h[1], l[1]);
    split1(v.z, h[2], l[2]); split1(v.w, h[3], l[3]);
    *reinterpret_cast<__nv_bfloat162*>(hi + i)     = __nv_bfloat162(h[0], h[1]);
    *reinterpret_cast<__nv_bfloat162*>(hi + i + 2) = __nv_bfloat162(h[2], h[3]);
    *reinterpret_cast<__nv_bfloat162*>(lo + i)     = __nv_bfloat162(l[0], l[1]);
    *reinterpret_cast<__nv_bfloat162*>(lo + i + 2) = __nv_bfloat162(l[2], l[3]);
}

// fp32 [1024,1024] -> transposed bf16 hi/lo [1024,1024]
__global__ void splitT_kernel(const float* __restrict__ in,
                              bf16* __restrict__ hi, bf16* __restrict__ lo)
{
    __shared__ float t[32][33];
    const int x0 = blockIdx.x * 32, y0 = blockIdx.y * 32;
    const int tx = threadIdx.x, ty = threadIdx.y;
    #pragma unroll
    for (int r = ty; r < 32; r += 8)
        t[r][tx] = in[(size_t)(y0 + r) * 1024 + x0 + tx];
    __syncthreads();
    #pragma unroll
    for (int r = ty; r < 32; r += 8) {
        float v = t[tx][r];
        bf16 h, l;
        split1(v, h, l);
        hi[(size_t)(x0 + r) * 1024 + y0 + tx] = h;
        lo[(size_t)(x0 + r) * 1024 + y0 + tx] = l;
    }
}

// ---------------------------------------------------------------------------
// bf[c][j] = sum_k bmod[c%3][k] * W{l|r}1[k][j]
// ---------------------------------------------------------------------------
__global__ void bias_fold_kernel(
    const float* __restrict__ bt, const float* __restrict__ ba,
    const float* __restrict__ bv,
    const float* __restrict__ Wl1, const float* __restrict__ Wr1,
    float* __restrict__ bf)
{
    int g = blockIdx.x * blockDim.x + threadIdx.x;
    if (g >= 6 * 1024) return;
    int combo = g >> 10;
    int j = g & 1023;
    int m = combo % 3;
    const float* bvec = (m == 0) ? bt : (m == 1) ? ba : bv;
    const float* W = (combo < 3) ? Wl1 : Wr1;
    float s = 0.0f;
    for (int k = 0; k < 1024; k++) s += bvec[k] * W[k * 1024 + j];
    bf[g] = s;
}

// ---------------------------------------------------------------------------
// GAT1 (8 heads, dh=128): block per sentence, warp per head.
// Emits x1 directly as bf16 hi/lo for the layer-2 GEMM.
// ---------------------------------------------------------------------------
__device__ __forceinline__ float lrelu02(float x) { return x > 0.0f ? x : 0.2f * x; }

__global__ __launch_bounds__(256) void gat1_kernel(
    const float* __restrict__ gl, const float* __restrict__ gr,
    const float* __restrict__ att, const float* __restrict__ b1,
    bf16* __restrict__ x1h, bf16* __restrict__ x1l)
{
    const int b = blockIdx.x;
    const int h = threadIdx.x >> 5;
    const int lane = threadIdx.x & 31;
    const int dbase = lane * 4;

    const size_t base = (size_t)b * 3072 + h * 128 + dbase;
    float4 glv[3], grv[3];
    #pragma unroll
    for (int j = 0; j < 3; j++)
        glv[j] = *reinterpret_cast<const float4*>(gl + base + j * 1024);
    #pragma unroll
    for (int i = 0; i < 3; i++)
        grv[i] = *reinterpret_cast<const float4*>(gr + base + i * 1024);
    const float4 av = *reinterpret_cast<const float4*>(att + h * 128 + dbase);

    float e[3][3];
    #pragma unroll
    for (int i = 0; i < 3; i++)
        #pragma unroll
        for (int j = 0; j < 3; j++) {
            float s = av.x * lrelu02(glv[j].x + grv[i].x);
            s += av.y * lrelu02(glv[j].y + grv[i].y);
            s += av.z * lrelu02(glv[j].z + grv[i].z);
            s += av.w * lrelu02(glv[j].w + grv[i].w);
            e[i][j] = s;
        }
    #pragma unroll
    for (int i = 0; i < 3; i++)
        #pragma unroll
        for (int j = 0; j < 3; j++)
            #pragma unroll
            for (int o = 16; o > 0; o >>= 1)
                e[i][j] += __shfl_xor_sync(0xFFFFFFFFu, e[i][j], o);

    float alpha[3][3];
    #pragma unroll
    for (int i = 0; i < 3; i++) {
        float mx = fmaxf(e[i][0], fmaxf(e[i][1], e[i][2]));
        float p0 = expf(e[i][0] - mx);
        float p1 = expf(e[i][1] - mx);
        float p2 = expf(e[i][2] - mx);
        float inv = 1.0f / (p0 + p1 + p2);
        alpha[i][0] = p0 * inv; alpha[i][1] = p1 * inv; alpha[i][2] = p2 * inv;
    }

    const float4 bb = *reinterpret_cast<const float4*>(b1 + h * 128 + dbase);
    #pragma unroll
    for (int i = 0; i < 3; i++) {
        float o[4];
        o[0] = alpha[i][0]*glv[0].x + alpha[i][1]*glv[1].x + alpha[i][2]*glv[2].x + bb.x;
        o[1] = alpha[i][0]*glv[0].y + alpha[i][1]*glv[1].y + alpha[i][2]*glv[2].y + bb.y;
        o[2] = alpha[i][0]*glv[0].z + alpha[i][1]*glv[1].z + alpha[i][2]*glv[2].z + bb.z;
        o[3] = alpha[i][0]*glv[0].w + alpha[i][1]*glv[1].w + alpha[i][2]*glv[2].w + bb.w;
        #pragma unroll
        for (int q = 0; q < 4; q++)
            o[q] = o[q] > 0.0f ? o[q] : (expf(o[q]) - 1.0f);
        bf16 hh[4], ll[4];
        #pragma unroll
        for (int q = 0; q < 4; q++) split1(o[q], hh[q], ll[q]);
        const size_t idx = (size_t)b * 3072 + i * 1024 + h * 128 + dbase;
        *reinterpret_cast<__nv_bfloat162*>(x1h + idx)     = __nv_bfloat162(hh[0], hh[1]);
        *reinterpret_cast<__nv_bfloat162*>(x1h + idx + 2) = __nv_bfloat162(hh[2], hh[3]);
        *reinterpret_cast<__nv_bfloat162*>(x1l + idx)     = __nv_bfloat162(ll[0], ll[1]);
        *reinterpret_cast<__nv_bfloat162*>(x1l + idx + 2) = __nv_bfloat162(ll[2], ll[3]);
    }
}

// ---------------------------------------------------------------------------
// GAT2 (1 head, d=1024) + mean pool. One warp per sentence.
// ---------------------------------------------------------------------------
__global__ __launch_bounds__(256) void gat2_kernel(
    const float* __restrict__ gl, const float* __restrict__ gr,
    const float* __restrict__ att, const float* __restrict__ b2,
    float* __restrict__ out)
{
    const int b = blockIdx.x * 8 + (threadIdx.x >> 5);
    const int lane = threadIdx.x & 31;
    const float* glb = gl + (size_t)b * 3072;
    const float* grb = gr + (size_t)b * 3072;

    float e[9] = {0,0,0,0,0,0,0,0,0};
    #pragma unroll
    for (int c = 0; c < 8; c++) {
        const int d = c * 128 + lane * 4;
        const float4 av = *reinterpret_cast<const float4*>(att + d);
        float4 glv[3], grv[3];
        #pragma unroll
        for (int j = 0; j < 3; j++)
            glv[j] = *reinterpret_cast<const float4*>(glb + j * 1024 + d);
        #pragma unroll
        for (int i = 0; i < 3; i++)
            grv[i] = *reinterpret_cast<const float4*>(grb + i * 1024 + d);
        #pragma unroll
        for (int i = 0; i < 3; i++)
            #pragma unroll
            for (int j = 0; j < 3; j++) {
                float s = av.x * lrelu02(glv[j].x + grv[i].x);
                s += av.y * lrelu02(glv[j].y + grv[i].y);
                s += av.z * lrelu02(glv[j].z + grv[i].z);
                s += av.w * lrelu02(glv[j].w + grv[i].w);
                e[i * 3 + j] += s;
            }
    }
    #pragma unroll
    for (int k = 0; k < 9; k++)
        #pragma unroll
        for (int o = 16; o > 0; o >>= 1)
            e[k] += __shfl_xor_sync(0xFFFFFFFFu, e[k], o);

    float w[3] = {0.0f, 0.0f, 0.0f};
    #pragma unroll
    for (int i = 0; i < 3; i++) {
        float mx = fmaxf(e[i*3+0], fmaxf(e[i*3+1], e[i*3+2]));
        float p0 = expf(e[i*3+0] - mx);
        float p1 = expf(e[i*3+1] - mx);
        float p2 = expf(e[i*3+2] - mx);
        float inv = 1.0f / (p0 + p1 + p2);
        w[0] += p0 * inv; w[1] += p1 * inv; w[2] += p2 * inv;
    }
    w[0] *= (1.0f/3.0f); w[1] *= (1.0f/3.0f); w[2] *= (1.0f/3.0f);

    #pragma unroll
    for (int c = 0; c < 8; c++) {
        const int d = c * 128 + lane * 4;
        const float4 bv = *reinterpret_cast<const float4*>(b2 + d);
        float4 g0 = *reinterpret_cast<const float4*>(glb + 0 * 1024 + d);
        float4 g1 = *reinterpret_cast<const float4*>(glb + 1 * 1024 + d);
        float4 g2 = *reinterpret_cast<const float4*>(glb + 2 * 1024 + d);
        float4 o;
        o.x = w[0]*g0.x + w[1]*g1.x + w[2]*g2.x + bv.x;
        o.y = w[0]*g0.y + w[1]*g1.y + w[2]*g2.y + bv.y;
        o.z = w[0]*g0.z + w[1]*g1.z + w[2]*g2.z + bv.z;
        o.w = w[0]*g0.w + w[1]*g1.w + w[2]*g2.w + bv.w;
        *reinterpret_cast<float4*>(out + (size_t)b * 1024 + d) = o;
    }
}

// ---------------------------------------------------------------------------
// Launch
// ---------------------------------------------------------------------------
extern "C" void kernel_launch(void* const* d_in, const int* in_sizes, int n_in,
                              void* d_out, int out_size)
{
    const float* feats[3] = { (const float*)d_in[0], (const float*)d_in[1], (const float*)d_in[2] };
    const float* Wm[3]    = { (const float*)d_in[3], (const float*)d_in[5], (const float*)d_in[7] };
    const float* bt   = (const float*)d_in[4];
    const float* ba   = (const float*)d_in[6];
    const float* bv   = (const float*)d_in[8];
    const float* Wl1  = (const float*)d_in[9];
    const float* Wr1  = (const float*)d_in[10];
    const float* att1 = (const float*)d_in[11];
    const float* b1   = (const float*)d_in[12];
    const float* Wl2  = (const float*)d_in[13];
    const float* Wr2  = (const float*)d_in[14];
    const float* att2 = (const float*)d_in[15];
    const float* b2   = (const float*)d_in[16];
    float* out = (float*)d_out;

    float *Wf, *bf, *gl1, *gr1, *gl2, *gr2;
    bf16 *WmH, *WmL, *WT1H, *WT1L, *WT2H, *WT2L, *WfTH, *WfTL, *featH, *featL, *x1H, *x1L;
    cudaGetSymbolAddress((void**)&Wf,  g_Wf);
    cudaGetSymbolAddress((void**)&bf,  g_bf);
    cudaGetSymbolAddress((void**)&gl1, g_gl1);
    cudaGetSymbolAddress((void**)&gr1, g_gr1);
    cudaGetSymbolAddress((void**)&gl2, g_gl2);
    cudaGetSymbolAddress((void**)&gr2, g_gr2);
    cudaGetSymbolAddress((void**)&WmH,  g_WmH);
    cudaGetSymbolAddress((void**)&WmL,  g_WmL);
    cudaGetSymbolAddress((void**)&WT1H, g_WT1H);
    cudaGetSymbolAddress((void**)&WT1L, g_WT1L);
    cudaGetSymbolAddress((void**)&WT2H, g_WT2H);
    cudaGetSymbolAddress((void**)&WT2L, g_WT2L);
    cudaGetSymbolAddress((void**)&WfTH, g_WfTH);
    cudaGetSymbolAddress((void**)&WfTL, g_WfTL);
    cudaGetSymbolAddress((void**)&featH, g_featH);
    cudaGetSymbolAddress((void**)&featL, g_featL);
    cudaGetSymbolAddress((void**)&x1H, g_x1H);
    cudaGetSymbolAddress((void**)&x1L, g_x1L);

    cudaFuncSetAttribute(gemm_bf16x3, cudaFuncAttributeMaxDynamicSharedMemorySize, GEMM_SMEM);

    const size_t M1 = 1024 * 1024;
    const dim3 tB(32, 8);
    const dim3 tG(32, 32);

    // 1. weight splits
    splitT_kernel<<<tG, tB>>>(Wl1, WT1H, WT1L);
    splitT_kernel<<<tG, tB>>>(Wr1, WT1H + M1, WT1L + M1);
    splitT_kernel<<<tG, tB>>>(Wl2, WT2H, WT2L);
    splitT_kernel<<<tG, tB>>>(Wr2, WT2H + M1, WT2L + M1);
    for (int m = 0; m < 3; m++)
        split_kernel<<<1024, 256>>>(Wm[m], WmH + m * M1, WmL + m * M1, 1024 * 1024);

    // 2. fold GEMMs: Wf[c] = Wm[c%3] @ W{l|r}1
    {
        dim3 grid(8, 8);
        for (int c = 0; c < 6; c++) {
            const bf16* Bh = WT1H + (c < 3 ? 0 : M1);
            const bf16* Bl = WT1L + (c < 3 ? 0 : M1);
            gemm_bf16x3<<<grid, 256, GEMM_SMEM>>>(1024, 1024, 1024,
                WmH + (c % 3) * M1, WmL + (c % 3) * M1, 1024,
                Bh, Bl, 1024, Wf + (size_t)c * M1, 1024, nullptr);
        }
    }
    bias_fold_kernel<<<24, 256>>>(bt, ba, bv, Wl1, Wr1, bf);
    for (int c = 0; c < 6; c++)
        splitT_kernel<<<tG, tB>>>(Wf + (size_t)c * M1, WfTH + c * M1, WfTL + c * M1);

    // 3. feature splits
    for (int m = 0; m < 3; m++)
        split_kernel<<<BATCH, 256>>>(feats[m], featH + (size_t)m * BATCH * 1024,
                                     featL + (size_t)m * BATCH * 1024, BATCH * 1024);

    // 4. layer-1 GEMMs: gl1/gr1 (interleaved [B,3,H], ldc=3072)
    {
        dim3 grid(8, BATCH / 128);
        for (int m = 0; m < 3; m++) {
            const bf16* Ah = featH + (size_t)m * BATCH * 1024;
            const bf16* Al = featL + (size_t)m * BATCH * 1024;
            gemm_bf16x3<<<grid, 256, GEMM_SMEM>>>(BATCH, 1024, 1024,
                Ah, Al, 1024, WfTH + m * M1, WfTL + m * M1, 1024,
                gl1 + m * 1024, 3072, bf + m * 1024);
            gemm_bf16x3<<<grid, 256, GEMM_SMEM>>>(BATCH, 1024, 1024,
                Ah, Al, 1024, WfTH + (3 + m) * M1, WfTL + (3 + m) * M1, 1024,
                gr1 + m * 1024, 3072, bf + (3 + m) * 1024);
        }
    }

    // 5. GAT1 -> x1 (bf16 hi/lo)
    gat1_kernel<<<BATCH, 256>>>(gl1, gr1, att1, b1, x1H, x1L);

    // 6. layer-2 GEMMs
    {
        dim3 grid(8, (3 * BATCH) / 128);
        gemm_bf16x3<<<grid, 256, GEMM_SMEM>>>(3 * BATCH, 1024, 1024,
            x1H, x1L, 1024, WT2H, WT2L, 1024, gl2, 1024, nullptr);
        gemm_bf16x3<<<grid, 256, GEMM_SMEM>>>(3 * BATCH, 1024, 1024,
            x1H, x1L, 1024, WT2H + M1, WT2L + M1, 1024, gr2, 1024, nullptr);
    }

    // 7. GAT2 -> out
    gat2_kernel<<<BATCH / 8, 256>>>(gl2, gr2, att2, b2, out);
}

// round 5
// speedup vs baseline: 3.7206x; 1.3773x over previous
#include <cuda_runtime.h>
#include <cuda_fp16.h>
#include <cstdint>
#include <math.h>

// ---------------------------------------------------------------------------
// IntraSentenceGNN on GB300 (sm_103 base ISA): GEMMs via mma.sync fp16
// (legacy HMMA pipe). Weights (B side) carried as fp16 hi/lo split
// (fp32-equivalent ~2^-21); activations (A side) single fp16.
// 2 MMA terms per logical FLOP for the big GEMMs (3 for the tiny fold).
//
//  1. split/transpose weights -> fp16 hi/lo [N,K] K-major (pre-scaled to
//     avoid fp16 subnormals in the lo part; rescaled in fp32 epilogue)
//  2. fold: Wf[c] = Wm[c%3] @ W{l|r}1  (6x 1024^3, 3-term)
//  3. gl1/gr1 = feat_m @ Wf + bf      (6x 32768x1024x1024, 2-term)
//  4. GAT1 attention + ELU -> x1 (fp16)
//  5. gl2/gr2 = x1 @ W{l|r}2          (2x 98304x1024x1024, 2-term)
//  6. GAT2 attention + mean-pool -> out
// ---------------------------------------------------------------------------

#define BATCH 32768
#define HDIM  1024

typedef __half fp16;

// ------------------------------ scratch -----------------------------------
__device__ __align__(256) float g_Wf [6 * 1024 * 1024];
__device__ __align__(256) float g_bf [6 * 1024];
__device__ __align__(256) float g_gl1[BATCH * 3 * HDIM];
__device__ __align__(256) float g_gr1[BATCH * 3 * HDIM];
__device__ __align__(256) float g_gl2[BATCH * 3 * HDIM];
__device__ __align__(256) float g_gr2[BATCH * 3 * HDIM];

__device__ __align__(256) fp16 g_WmH [3 * 1024 * 1024];
__device__ __align__(256) fp16 g_WmL [3 * 1024 * 1024];
__device__ __align__(256) fp16 g_WT1H[2 * 1024 * 1024];
__device__ __align__(256) fp16 g_WT1L[2 * 1024 * 1024];
__device__ __align__(256) fp16 g_WT2H[2 * 1024 * 1024];
__device__ __align__(256) fp16 g_WT2L[2 * 1024 * 1024];
__device__ __align__(256) fp16 g_WfTH[6 * 1024 * 1024];
__device__ __align__(256) fp16 g_WfTL[6 * 1024 * 1024];
__device__ __align__(256) fp16 g_feat[3 * BATCH * 1024];
__device__ __align__(256) fp16 g_x1  [BATCH * 3 * 1024];

// --------------------------- PTX helpers ----------------------------------
__device__ __forceinline__ uint32_t smem_u32(const void* p) {
    uint32_t a;
    asm("{ .reg .u64 t; cvta.to.shared.u64 t, %1; cvt.u32.u64 %0, t; }"
        : "=r"(a) : "l"(p));
    return a;
}
__device__ __forceinline__ void cp16(uint32_t sdst, const void* gsrc) {
    asm volatile("cp.async.cg.shared.global [%0], [%1], 16;" :: "r"(sdst), "l"(gsrc));
}
__device__ __forceinline__ void cp_commit() {
    asm volatile("cp.async.commit_group;" ::: "memory");
}
__device__ __forceinline__ void cp_wait1() {
    asm volatile("cp.async.wait_group 1;" ::: "memory");
}
__device__ __forceinline__ void cp_wait0() {
    asm volatile("cp.async.wait_group 0;" ::: "memory");
}

// swizzled 32-bit shared load: tile rows are 128B (64 fp16), SW128 pattern
__device__ __forceinline__ uint32_t lds32_sw(uint32_t base, int row, int col) {
    uint32_t off = (uint32_t)(row * 128 + col * 2);
    off ^= (off >> 3) & 0x70;
    uint32_t v;
    asm volatile("ld.shared.b32 %0, [%1];" : "=r"(v) : "r"(base + off));
    return v;
}

__device__ __forceinline__ void mma16816(float* c, const uint32_t* a, const uint32_t* b) {
    asm volatile(
        "mma.sync.aligned.m16n8k16.row.col.f32.f16.f16.f32 "
        "{%0,%1,%2,%3}, {%4,%5,%6,%7}, {%8,%9}, {%0,%1,%2,%3};"
        : "+f"(c[0]), "+f"(c[1]), "+f"(c[2]), "+f"(c[3])
        : "r"(a[0]), "r"(a[1]), "r"(a[2]), "r"(a[3]), "r"(b[0]), "r"(b[1]));
}

// ---------------------------------------------------------------------------
// fp16 GEMM: C[M,N] = scale * sum_k A[m,k]*BT[n,k] (+ bias[n])
//   SA: A = Ah + Al (extra Al*Bh term). SB: BT = Bh + Bl (extra Ah*Bl term).
// CTA tile 128x128, BK=64, 3-stage cp.async, 8 warps (4m x 2n), warp 32x64.
// ---------------------------------------------------------------------------
template<bool SA, bool SB>
__global__ __launch_bounds__(256, 1) void gemm_fp16(
    int M, int N, int K,
    const fp16* __restrict__ Ah, const fp16* __restrict__ Al, int lda,
    const fp16* __restrict__ Bh, const fp16* __restrict__ Bl, int ldb,
    float* __restrict__ C, int ldc, float scale, const float* __restrict__ bias)
{
    constexpr int NSUB  = 2 + (SA ? 1 : 0) + (SB ? 1 : 0);
    constexpr int STAGE = NSUB * 16384;

    extern __shared__ char smem[];
    const uint32_t sbase = smem_u32(smem);
    const int tid  = threadIdx.x;
    const int wid  = tid >> 5;
    const int lane = tid & 31;
    const int warp_m = wid & 3;
    const int warp_n = wid >> 2;

    const int mblk = blockIdx.y * 128;
    const int nblk = blockIdx.x * 128;
    const int KT = K >> 6;

    auto load_sub = [&](const fp16* src, int blk, int ld, uint32_t rb, int kofs) {
        #pragma unroll
        for (int i = 0; i < 4; i++) {
            const int c = tid + i * 256;
            const int row = c >> 3, kc = c & 7;
            const void* g = src + (size_t)(blk + row) * ld + kofs + kc * 8;
            uint32_t off = (uint32_t)(row * 128 + kc * 16);
            off ^= (off >> 3) & 0x70;
            cp16(rb + off, g);
        }
    };

    auto load_tile = [&](int kt, int s) {
        const uint32_t st = sbase + s * STAGE;
        const int kofs = kt * 64;
        load_sub(Ah, mblk, lda, st, kofs);
        if (SA) load_sub(Al, mblk, lda, st + 16384, kofs);
        load_sub(Bh, nblk, ldb, st + (1 + (SA ? 1 : 0)) * 16384, kofs);
        if (SB) load_sub(Bl, nblk, ldb, st + (2 + (SA ? 1 : 0)) * 16384, kofs);
        cp_commit();
    };

    float acc[2][8][4];
    #pragma unroll
    for (int mt = 0; mt < 2; mt++)
        #pragma unroll
        for (int nt = 0; nt < 8; nt++)
            #pragma unroll
            for (int q = 0; q < 4; q++) acc[mt][nt][q] = 0.0f;

    load_tile(0, 0);
    load_tile(1, 1);

    for (int kt = 0; kt < KT; kt++) {
        if (kt + 1 < KT) cp_wait1(); else cp_wait0();
        __syncthreads();

        const uint32_t st  = sbase + (kt % 3) * STAGE;
        const uint32_t sAh = st;
        const uint32_t sAl = st + 16384;
        const uint32_t sBh = st + (1 + (SA ? 1 : 0)) * 16384;
        const uint32_t sBl = sBh + 16384;

        const int r0 = warp_m * 32 + (lane >> 2);
        const int n0 = warp_n * 64 + (lane >> 2);
        const int c0 = (lane & 3) * 2;

        #pragma unroll
        for (int ks = 0; ks < 4; ks++) {
            const int kb = ks * 16 + c0;
            uint32_t afr[SA ? 2 : 1][2][4];
            #pragma unroll
            for (int mt = 0; mt < 2; mt++) {
                const int rr = r0 + mt * 16;
                afr[0][mt][0] = lds32_sw(sAh, rr,     kb);
                afr[0][mt][1] = lds32_sw(sAh, rr + 8, kb);
                afr[0][mt][2] = lds32_sw(sAh, rr,     kb + 8);
                afr[0][mt][3] = lds32_sw(sAh, rr + 8, kb + 8);
                if (SA) {
                    afr[SA ? 1 : 0][mt][0] = lds32_sw(sAl, rr,     kb);
                    afr[SA ? 1 : 0][mt][1] = lds32_sw(sAl, rr + 8, kb);
                    afr[SA ? 1 : 0][mt][2] = lds32_sw(sAl, rr,     kb + 8);
                    afr[SA ? 1 : 0][mt][3] = lds32_sw(sAl, rr + 8, kb + 8);
                }
            }
            uint32_t bfr[SB ? 2 : 1][8][2];
            #pragma unroll
            for (int nt = 0; nt < 8; nt++) {
                const int nr = n0 + nt * 8;
                bfr[0][nt][0] = lds32_sw(sBh, nr, kb);
                bfr[0][nt][1] = lds32_sw(sBh, nr, kb + 8);
                if (SB) {
                    bfr[SB ? 1 : 0][nt][0] = lds32_sw(sBl, nr, kb);
                    bfr[SB ? 1 : 0][nt][1] = lds32_sw(sBl, nr, kb + 8);
                }
            }
            #pragma unroll
            for (int mt = 0; mt < 2; mt++)
                #pragma unroll
                for (int nt = 0; nt < 8; nt++) {
                    mma16816(acc[mt][nt], afr[0][mt], bfr[0][nt]);
                    if (SB) mma16816(acc[mt][nt], afr[0][mt], bfr[SB ? 1 : 0][nt]);
                    if (SA) mma16816(acc[mt][nt], afr[SA ? 1 : 0][mt], bfr[0][nt]);
                }
        }
        __syncthreads();
        if (kt + 2 < KT) load_tile(kt + 2, (kt + 2) % 3);
    }

    #pragma unroll
    for (int mt = 0; mt < 2; mt++) {
        const int row = mblk + warp_m * 32 + mt * 16 + (lane >> 2);
        #pragma unroll
        for (int nt = 0; nt < 8; nt++) {
            const int col = nblk + warp_n * 64 + nt * 8 + (lane & 3) * 2;
            float b0 = 0.0f, b1 = 0.0f;
            if (bias) { b0 = bias[col]; b1 = bias[col + 1]; }
            float2 v0 = make_float2(acc[mt][nt][0] * scale + b0, acc[mt][nt][1] * scale + b1);
            float2 v1 = make_float2(acc[mt][nt][2] * scale + b0, acc[mt][nt][3] * scale + b1);
            *reinterpret_cast<float2*>(C + (size_t)row * ldc + col) = v0;
            *reinterpret_cast<float2*>(C + (size_t)(row + 8) * ldc + col) = v1;
        }
    }
}

// ---------------------------------------------------------------------------
// fp32 -> fp16 hi/lo split with pre-scale (elementwise, float4)
// ---------------------------------------------------------------------------
__device__ __forceinline__ void split1(float x, fp16& h, fp16& l) {
    h = __float2half(x);
    l = __float2half(x - __half2float(h));
}

__global__ void split_fp16(const float* __restrict__ in,
                           fp16* __restrict__ hi, fp16* __restrict__ lo,
                           int n, float scale)
{
    int i = (blockIdx.x * blockDim.x + threadIdx.x) * 4;
    if (i >= n) return;
    float4 v = *reinterpret_cast<const float4*>(in + i);
    fp16 h[4], l[4];
    split1(v.x * scale, h[0], l[0]); split1(v.y * scale, h[1], l[1]);
    split1(v.z * scale, h[2], l[2]); split1(v.w * scale, h[3], l[3]);
    *reinterpret_cast<__half2*>(hi + i)     = __halves2half2(h[0], h[1]);
    *reinterpret_cast<__half2*>(hi + i + 2) = __halves2half2(h[2], h[3]);
    *reinterpret_cast<__half2*>(lo + i)     = __halves2half2(l[0], l[1]);
    *reinterpret_cast<__half2*>(lo + i + 2) = __halves2half2(l[2], l[3]);
}

// fp32 [1024,1024] -> transposed fp16 hi/lo [1024,1024] with pre-scale
__global__ void splitT_fp16(const float* __restrict__ in,
                            fp16* __restrict__ hi, fp16* __restrict__ lo,
                            float scale)
{
    __shared__ float t[32][33];
    const int x0 = blockIdx.x * 32, y0 = blockIdx.y * 32;
    const int tx = threadIdx.x, ty = threadIdx.y;
    #pragma unroll
    for (int r = ty; r < 32; r += 8)
        t[r][tx] = in[(size_t)(y0 + r) * 1024 + x0 + tx];
    __syncthreads();
    #pragma unroll
    for (int r = ty; r < 32; r += 8) {
        float v = t[tx][r] * scale;
        fp16 h, l;
        split1(v, h, l);
        hi[(size_t)(x0 + r) * 1024 + y0 + tx] = h;
        lo[(size_t)(x0 + r) * 1024 + y0 + tx] = l;
    }
}

// fp32 -> single fp16 (activations)
__global__ void tofp16_kernel(const float* __restrict__ in,
                              fp16* __restrict__ out, int n)
{
    int i = (blockIdx.x * blockDim.x + threadIdx.x) * 4;
    if (i >= n) return;
    float4 v = *reinterpret_cast<const float4*>(in + i);
    *reinterpret_cast<__half2*>(out + i)     = __halves2half2(__float2half(v.x), __float2half(v.y));
    *reinterpret_cast<__half2*>(out + i + 2) = __halves2half2(__float2half(v.z), __float2half(v.w));
}

// ---------------------------------------------------------------------------
// bf[c][j] = sum_k bmod[c%3][k] * W{l|r}1[k][j]
// ---------------------------------------------------------------------------
__global__ void bias_fold_kernel(
    const float* __restrict__ bt, const float* __restrict__ ba,
    const float* __restrict__ bv,
    const float* __restrict__ Wl1, const float* __restrict__ Wr1,
    float* __restrict__ bf)
{
    int g = blockIdx.x * blockDim.x + threadIdx.x;
    if (g >= 6 * 1024) return;
    int combo = g >> 10;
    int j = g & 1023;
    int m = combo % 3;
    const float* bvec = (m == 0) ? bt : (m == 1) ? ba : bv;
    const float* W = (combo < 3) ? Wl1 : Wr1;
    float s = 0.0f;
    for (int k = 0; k < 1024; k++) s += bvec[k] * W[k * 1024 + j];
    bf[g] = s;
}

// ---------------------------------------------------------------------------
// GAT1 (8 heads, dh=128): block per sentence, warp per head. x1 -> fp16.
// ---------------------------------------------------------------------------
__device__ __forceinline__ float lrelu02(float x) { return x > 0.0f ? x : 0.2f * x; }

__global__ __launch_bounds__(256) void gat1_kernel(
    const float* __restrict__ gl, const float* __restrict__ gr,
    const float* __restrict__ att, const float* __restrict__ b1,
    fp16* __restrict__ x1)
{
    const int b = blockIdx.x;
    const int h = threadIdx.x >> 5;
    const int lane = threadIdx.x & 31;
    const int dbase = lane * 4;

    const size_t base = (size_t)b * 3072 + h * 128 + dbase;
    float4 glv[3], grv[3];
    #pragma unroll
    for (int j = 0; j < 3; j++)
        glv[j] = *reinterpret_cast<const float4*>(gl + base + j * 1024);
    #pragma unroll
    for (int i = 0; i < 3; i++)
        grv[i] = *reinterpret_cast<const float4*>(gr + base + i * 1024);
    const float4 av = *reinterpret_cast<const float4*>(att + h * 128 + dbase);

    float e[3][3];
    #pragma unroll
    for (int i = 0; i < 3; i++)
        #pragma unroll
        for (int j = 0; j < 3; j++) {
            float s = av.x * lrelu02(glv[j].x + grv[i].x);
            s += av.y * lrelu02(glv[j].y + grv[i].y);
            s += av.z * lrelu02(glv[j].z + grv[i].z);
            s += av.w * lrelu02(glv[j].w + grv[i].w);
            e[i][j] = s;
        }
    #pragma unroll
    for (int i = 0; i < 3; i++)
        #pragma unroll
        for (int j = 0; j < 3; j++)
            #pragma unroll
            for (int o = 16; o > 0; o >>= 1)
                e[i][j] += __shfl_xor_sync(0xFFFFFFFFu, e[i][j], o);

    float alpha[3][3];
    #pragma unroll
    for (int i = 0; i < 3; i++) {
        float mx = fmaxf(e[i][0], fmaxf(e[i][1], e[i][2]));
        float p0 = expf(e[i][0] - mx);
        float p1 = expf(e[i][1] - mx);
        float p2 = expf(e[i][2] - mx);
        float inv = 1.0f / (p0 + p1 + p2);
        alpha[i][0] = p0 * inv; alpha[i][1] = p1 * inv; alpha[i][2] = p2 * inv;
    }

    const float4 bb = *reinterpret_cast<const float4*>(b1 + h * 128 + dbase);
    #pragma unroll
    for (int i = 0; i < 3; i++) {
        float o[4];
        o[0] = alpha[i][0]*glv[0].x + alpha[i][1]*glv[1].x + alpha[i][2]*glv[2].x + bb.x;
        o[1] = alpha[i][0]*glv[0].y + alpha[i][1]*glv[1].y + alpha[i][2]*glv[2].y + bb.y;
        o[2] = alpha[i][0]*glv[0].z + alpha[i][1]*glv[1].z + alpha[i][2]*glv[2].z + bb.z;
        o[3] = alpha[i][0]*glv[0].w + alpha[i][1]*glv[1].w + alpha[i][2]*glv[2].w + bb.w;
        #pragma unroll
        for (int q = 0; q < 4; q++)
            o[q] = o[q] > 0.0f ? o[q] : (expf(o[q]) - 1.0f);
        const size_t idx = (size_t)b * 3072 + i * 1024 + h * 128 + dbase;
        *reinterpret_cast<__half2*>(x1 + idx) =
            __halves2half2(__float2half(o[0]), __float2half(o[1]));
        *reinterpret_cast<__half2*>(x1 + idx + 2) =
            __halves2half2(__float2half(o[2]), __float2half(o[3]));
    }
}

// ---------------------------------------------------------------------------
// GAT2 (1 head, d=1024) + mean pool. One warp per sentence.
// ---------------------------------------------------------------------------
__global__ __launch_bounds__(256) void gat2_kernel(
    const float* __restrict__ gl, const float* __restrict__ gr,
    const float* __restrict__ att, const float* __restrict__ b2,
    float* __restrict__ out)
{
    const int b = blockIdx.x * 8 + (threadIdx.x >> 5);
    const int lane = threadIdx.x & 31;
    const float* glb = gl + (size_t)b * 3072;
    const float* grb = gr + (size_t)b * 3072;

    float e[9] = {0,0,0,0,0,0,0,0,0};
    #pragma unroll
    for (int c = 0; c < 8; c++) {
        const int d = c * 128 + lane * 4;
        const float4 av = *reinterpret_cast<const float4*>(att + d);
        float4 glv[3], grv[3];
        #pragma unroll
        for (int j = 0; j < 3; j++)
            glv[j] = *reinterpret_cast<const float4*>(glb + j * 1024 + d);
        #pragma unroll
        for (int i = 0; i < 3; i++)
            grv[i] = *reinterpret_cast<const float4*>(grb + i * 1024 + d);
        #pragma unroll
        for (int i = 0; i < 3; i++)
            #pragma unroll
            for (int j = 0; j < 3; j++) {
                float s = av.x * lrelu02(glv[j].x + grv[i].x);
                s += av.y * lrelu02(glv[j].y + grv[i].y);
                s += av.z * lrelu02(glv[j].z + grv[i].z);
                s += av.w * lrelu02(glv[j].w + grv[i].w);
                e[i * 3 + j] += s;
            }
    }
    #pragma unroll
    for (int k = 0; k < 9; k++)
        #pragma unroll
        for (int o = 16; o > 0; o >>= 1)
            e[k] += __shfl_xor_sync(0xFFFFFFFFu, e[k], o);

    float w[3] = {0.0f, 0.0f, 0.0f};
    #pragma unroll
    for (int i = 0; i < 3; i++) {
        float mx = fmaxf(e[i*3+0], fmaxf(e[i*3+1], e[i*3+2]));
        float p0 = expf(e[i*3+0] - mx);
        float p1 = expf(e[i*3+1] - mx);
        float p2 = expf(e[i*3+2] - mx);
        float inv = 1.0f / (p0 + p1 + p2);
        w[0] += p0 * inv; w[1] += p1 * inv; w[2] += p2 * inv;
    }
    w[0] *= (1.0f/3.0f); w[1] *= (1.0f/3.0f); w[2] *= (1.0f/3.0f);

    #pragma unroll
    for (int c = 0; c < 8; c++) {
        const int d = c * 128 + lane * 4;
        const float4 bv = *reinterpret_cast<const float4*>(b2 + d);
        float4 g0 = *reinterpret_cast<const float4*>(glb + 0 * 1024 + d);
        float4 g1 = *reinterpret_cast<const float4*>(glb + 1 * 1024 + d);
        float4 g2 = *reinterpret_cast<const float4*>(glb + 2 * 1024 + d);
        float4 o;
        o.x = w[0]*g0.x + w[1]*g1.x + w[2]*g2.x + bv.x;
        o.y = w[0]*g0.y + w[1]*g1.y + w[2]*g2.y + bv.y;
        o.z = w[0]*g0.z + w[1]*g1.z + w[2]*g2.z + bv.z;
        o.w = w[0]*g0.w + w[1]*g1.w + w[2]*g2.w + bv.w;
        *reinterpret_cast<float4*>(out + (size_t)b * 1024 + d) = o;
    }
}

// ---------------------------------------------------------------------------
// Launch
// ---------------------------------------------------------------------------
extern "C" void kernel_launch(void* const* d_in, const int* in_sizes, int n_in,
                              void* d_out, int out_size)
{
    const float* feats[3] = { (const float*)d_in[0], (const float*)d_in[1], (const float*)d_in[2] };
    const float* Wm[3]    = { (const float*)d_in[3], (const float*)d_in[5], (const float*)d_in[7] };
    const float* bt   = (const float*)d_in[4];
    const float* ba   = (const float*)d_in[6];
    const float* bv   = (const float*)d_in[8];
    const float* Wl1  = (const float*)d_in[9];
    const float* Wr1  = (const float*)d_in[10];
    const float* att1 = (const float*)d_in[11];
    const float* b1   = (const float*)d_in[12];
    const float* Wl2  = (const float*)d_in[13];
    const float* Wr2  = (const float*)d_in[14];
    const float* att2 = (const float*)d_in[15];
    const float* b2   = (const float*)d_in[16];
    float* out = (float*)d_out;

    float *Wf, *bf, *gl1, *gr1, *gl2, *gr2;
    fp16 *WmH, *WmL, *WT1H, *WT1L, *WT2H, *WT2L, *WfTH, *WfTL, *feat16, *x1;
    cudaGetSymbolAddress((void**)&Wf,  g_Wf);
    cudaGetSymbolAddress((void**)&bf,  g_bf);
    cudaGetSymbolAddress((void**)&gl1, g_gl1);
    cudaGetSymbolAddress((void**)&gr1, g_gr1);
    cudaGetSymbolAddress((void**)&gl2, g_gl2);
    cudaGetSymbolAddress((void**)&gr2, g_gr2);
    cudaGetSymbolAddress((void**)&WmH,  g_WmH);
    cudaGetSymbolAddress((void**)&WmL,  g_WmL);
    cudaGetSymbolAddress((void**)&WT1H, g_WT1H);
    cudaGetSymbolAddress((void**)&WT1L, g_WT1L);
    cudaGetSymbolAddress((void**)&WT2H, g_WT2H);
    cudaGetSymbolAddress((void**)&WT2L, g_WT2L);
    cudaGetSymbolAddress((void**)&WfTH, g_WfTH);
    cudaGetSymbolAddress((void**)&WfTL, g_WfTL);
    cudaGetSymbolAddress((void**)&feat16, g_feat);
    cudaGetSymbolAddress((void**)&x1, g_x1);

    const int SMEM33 = 3 * 4 * 16384;   // fold kernel (SA && SB): 192 KB
    const int SMEM23 = 3 * 3 * 16384;   // layer kernel (SB only): 144 KB
    cudaFuncSetAttribute(gemm_fp16<true, true>,
                         cudaFuncAttributeMaxDynamicSharedMemorySize, SMEM33);
    cudaFuncSetAttribute(gemm_fp16<false, true>,
                         cudaFuncAttributeMaxDynamicSharedMemorySize, SMEM23);

    const size_t M1 = 1024 * 1024;
    const dim3 tB(32, 8);
    const dim3 tG(32, 32);

    // scales chosen so the fp16 lo parts stay in the normal range
    const float S_FOLD = 1024.0f;           // Wm, W1 pre-scale (2^10)
    const float S_LYR  = 64.0f;             // Wf, W2 pre-scale (2^6)

    // 1. weight splits
    splitT_fp16<<<tG, tB>>>(Wl1, WT1H, WT1L, S_FOLD);
    splitT_fp16<<<tG, tB>>>(Wr1, WT1H + M1, WT1L + M1, S_FOLD);
    splitT_fp16<<<tG, tB>>>(Wl2, WT2H, WT2L, S_LYR);
    splitT_fp16<<<tG, tB>>>(Wr2, WT2H + M1, WT2L + M1, S_LYR);
    for (int m = 0; m < 3; m++)
        split_fp16<<<1024, 256>>>(Wm[m], WmH + m * M1, WmL + m * M1,
                                  1024 * 1024, S_FOLD);

    // 2. fold GEMMs (3-term): Wf[c] = Wm[c%3] @ W{l|r}1
    {
        dim3 grid(8, 8);
        for (int c = 0; c < 6; c++) {
            const fp16* Bh = WT1H + (c < 3 ? 0 : M1);
            const fp16* Bl = WT1L + (c < 3 ? 0 : M1);
            gemm_fp16<true, true><<<grid, 256, SMEM33>>>(1024, 1024, 1024,
                WmH + (c % 3) * M1, WmL + (c % 3) * M1, 1024,
                Bh, Bl, 1024, Wf + (size_t)c * M1, 1024,
                1.0f / (S_FOLD * S_FOLD), nullptr);
        }
    }
    bias_fold_kernel<<<24, 256>>>(bt, ba, bv, Wl1, Wr1, bf);
    for (int c = 0; c < 6; c++)
        splitT_fp16<<<tG, tB>>>(Wf + (size_t)c * M1, WfTH + c * M1, WfTL + c * M1, S_LYR);

    // 3. feature conversion (single fp16)
    for (int m = 0; m < 3; m++)
        tofp16_kernel<<<BATCH, 256>>>(feats[m], feat16 + (size_t)m * BATCH * 1024,
                                      BATCH * 1024);

    // 4. layer-1 GEMMs (2-term): gl1/gr1 (interleaved [B,3,H], ldc=3072)
    {
        dim3 grid(8, BATCH / 128);
        for (int m = 0; m < 3; m++) {
            const fp16* A = feat16 + (size_t)m * BATCH * 1024;
            gemm_fp16<false, true><<<grid, 256, SMEM23>>>(BATCH, 1024, 1024,
                A, nullptr, 1024, WfTH + m * M1, WfTL + m * M1, 1024,
                gl1 + m * 1024, 3072, 1.0f / S_LYR, bf + m * 1024);
            gemm_fp16<false, true><<<grid, 256, SMEM23>>>(BATCH, 1024, 1024,
                A, nullptr, 1024, WfTH + (3 + m) * M1, WfTL + (3 + m) * M1, 1024,
                gr1 + m * 1024, 3072, 1.0f / S_LYR, bf + (3 + m) * 1024);
        }
    }

    // 5. GAT1 -> x1 (fp16)
    gat1_kernel<<<BATCH, 256>>>(gl1, gr1, att1, b1, x1);

    // 6. layer-2 GEMMs (2-term)
    {
        dim3 grid(8, (3 * BATCH) / 128);
        gemm_fp16<false, true><<<grid, 256, SMEM23>>>(3 * BATCH, 1024, 1024,
            x1, nullptr, 1024, WT2H, WT2L, 1024, gl2, 1024, 1.0f / S_LYR, nullptr);
        gemm_fp16<false, true><<<grid, 256, SMEM23>>>(3 * BATCH, 1024, 1024,
            x1, nullptr, 1024, WT2H + M1, WT2L + M1, 1024, gr2, 1024, 1.0f / S_LYR, nullptr);
    }

    // 7. GAT2 -> out
    gat2_kernel<<<BATCH / 8, 256>>>(gl2, gr2, att2, b2, out);
}

// round 6
// speedup vs baseline: 5.4861x; 1.4745x over previous
#include <cuda_runtime.h>
#include <cuda_fp16.h>
#include <cstdint>
#include <math.h>

// ---------------------------------------------------------------------------
// IntraSentenceGNN on GB300 (sm_103 base ISA): GEMMs via mma.sync fp16.
// Big GEMMs single-term (fp16 weights + fp16 activations, fp32 accum);
// the tiny weight-fold GEMM stays 3-term hi/lo so Wf is fp32-accurate.
//
//  1. split/transpose weights
//  2. fold: Wf[c] = Wm[c%3] @ W{l|r}1  (6x 1024^3, 3-term, prescaled)
//  3. gl1/gr1 = feat_m @ Wf + bf      (6x 32768x1024x1024, 1-term)
//  4. GAT1 attention + ELU -> x1 (fp16)
//  5. gl2/gr2 = x1 @ W{l|r}2          (2x 98304x1024x1024, 1-term)
//  6. GAT2 attention + mean-pool -> out
// ---------------------------------------------------------------------------

#define BATCH 32768
#define HDIM  1024

typedef __half fp16;

// ------------------------------ scratch -----------------------------------
__device__ __align__(256) float g_Wf [6 * 1024 * 1024];
__device__ __align__(256) float g_bf [6 * 1024];
__device__ __align__(256) float g_gl1[BATCH * 3 * HDIM];
__device__ __align__(256) float g_gr1[BATCH * 3 * HDIM];
__device__ __align__(256) float g_gl2[BATCH * 3 * HDIM];
__device__ __align__(256) float g_gr2[BATCH * 3 * HDIM];

__device__ __align__(256) fp16 g_WmH [3 * 1024 * 1024];
__device__ __align__(256) fp16 g_WmL [3 * 1024 * 1024];
__device__ __align__(256) fp16 g_WT1H[2 * 1024 * 1024];
__device__ __align__(256) fp16 g_WT1L[2 * 1024 * 1024];
__device__ __align__(256) fp16 g_WT2 [2 * 1024 * 1024];
__device__ __align__(256) fp16 g_WfT [6 * 1024 * 1024];
__device__ __align__(256) fp16 g_feat[3 * BATCH * 1024];
__device__ __align__(256) fp16 g_x1  [BATCH * 3 * 1024];

// --------------------------- PTX helpers ----------------------------------
__device__ __forceinline__ uint32_t smem_u32(const void* p) {
    uint32_t a;
    asm("{ .reg .u64 t; cvta.to.shared.u64 t, %1; cvt.u32.u64 %0, t; }"
        : "=r"(a) : "l"(p));
    return a;
}
__device__ __forceinline__ void cp16(uint32_t sdst, const void* gsrc) {
    asm volatile("cp.async.cg.shared.global [%0], [%1], 16;" :: "r"(sdst), "l"(gsrc));
}
__device__ __forceinline__ void cp_commit() {
    asm volatile("cp.async.commit_group;" ::: "memory");
}
__device__ __forceinline__ void cp_wait1() {
    asm volatile("cp.async.wait_group 1;" ::: "memory");
}
__device__ __forceinline__ void cp_wait0() {
    asm volatile("cp.async.wait_group 0;" ::: "memory");
}

// swizzled 32-bit shared load: tile rows are 128B (64 fp16), SW128 pattern
__device__ __forceinline__ uint32_t lds32_sw(uint32_t base, int row, int col) {
    uint32_t off = (uint32_t)(row * 128 + col * 2);
    off ^= (off >> 3) & 0x70;
    uint32_t v;
    asm volatile("ld.shared.b32 %0, [%1];" : "=r"(v) : "r"(base + off));
    return v;
}

__device__ __forceinline__ void mma16816(float* c, const uint32_t* a, const uint32_t* b) {
    asm volatile(
        "mma.sync.aligned.m16n8k16.row.col.f32.f16.f16.f32 "
        "{%0,%1,%2,%3}, {%4,%5,%6,%7}, {%8,%9}, {%0,%1,%2,%3};"
        : "+f"(c[0]), "+f"(c[1]), "+f"(c[2]), "+f"(c[3])
        : "r"(a[0]), "r"(a[1]), "r"(a[2]), "r"(a[3]), "r"(b[0]), "r"(b[1]));
}

// ---------------------------------------------------------------------------
// fp16 GEMM: C[M,N] = scale * sum_k A[m,k]*BT[n,k] (+ bias[n])
//   SA: A = Ah + Al (extra Al*Bh term). SB: BT = Bh + Bl (extra Ah*Bl term).
// CTA tile 128x128, BK=64, 3-stage cp.async, 8 warps (4m x 2n), warp 32x64.
// ---------------------------------------------------------------------------
template<bool SA, bool SB>
__global__ __launch_bounds__(256, 1) void gemm_fp16(
    int M, int N, int K,
    const fp16* __restrict__ Ah, const fp16* __restrict__ Al, int lda,
    const fp16* __restrict__ Bh, const fp16* __restrict__ Bl, int ldb,
    float* __restrict__ C, int ldc, float scale, const float* __restrict__ bias)
{
    constexpr int NSUB  = 2 + (SA ? 1 : 0) + (SB ? 1 : 0);
    constexpr int STAGE = NSUB * 16384;

    extern __shared__ char smem[];
    const uint32_t sbase = smem_u32(smem);
    const int tid  = threadIdx.x;
    const int wid  = tid >> 5;
    const int lane = tid & 31;
    const int warp_m = wid & 3;
    const int warp_n = wid >> 2;

    const int mblk = blockIdx.y * 128;
    const int nblk = blockIdx.x * 128;
    const int KT = K >> 6;

    auto load_sub = [&](const fp16* src, int blk, int ld, uint32_t rb, int kofs) {
        #pragma unroll
        for (int i = 0; i < 4; i++) {
            const int c = tid + i * 256;
            const int row = c >> 3, kc = c & 7;
            const void* g = src + (size_t)(blk + row) * ld + kofs + kc * 8;
            uint32_t off = (uint32_t)(row * 128 + kc * 16);
            off ^= (off >> 3) & 0x70;
            cp16(rb + off, g);
        }
    };

    auto load_tile = [&](int kt, int s) {
        const uint32_t st = sbase + s * STAGE;
        const int kofs = kt * 64;
        load_sub(Ah, mblk, lda, st, kofs);
        if (SA) load_sub(Al, mblk, lda, st + 16384, kofs);
        load_sub(Bh, nblk, ldb, st + (1 + (SA ? 1 : 0)) * 16384, kofs);
        if (SB) load_sub(Bl, nblk, ldb, st + (2 + (SA ? 1 : 0)) * 16384, kofs);
        cp_commit();
    };

    float acc[2][8][4];
    #pragma unroll
    for (int mt = 0; mt < 2; mt++)
        #pragma unroll
        for (int nt = 0; nt < 8; nt++)
            #pragma unroll
            for (int q = 0; q < 4; q++) acc[mt][nt][q] = 0.0f;

    load_tile(0, 0);
    load_tile(1, 1);

    for (int kt = 0; kt < KT; kt++) {
        if (kt + 1 < KT) cp_wait1(); else cp_wait0();
        __syncthreads();

        const uint32_t st  = sbase + (kt % 3) * STAGE;
        const uint32_t sAh = st;
        const uint32_t sAl = st + 16384;
        const uint32_t sBh = st + (1 + (SA ? 1 : 0)) * 16384;
        const uint32_t sBl = sBh + 16384;

        const int r0 = warp_m * 32 + (lane >> 2);
        const int n0 = warp_n * 64 + (lane >> 2);
        const int c0 = (lane & 3) * 2;

        #pragma unroll
        for (int ks = 0; ks < 4; ks++) {
            const int kb = ks * 16 + c0;
            uint32_t afr[SA ? 2 : 1][2][4];
            #pragma unroll
            for (int mt = 0; mt < 2; mt++) {
                const int rr = r0 + mt * 16;
                afr[0][mt][0] = lds32_sw(sAh, rr,     kb);
                afr[0][mt][1] = lds32_sw(sAh, rr + 8, kb);
                afr[0][mt][2] = lds32_sw(sAh, rr,     kb + 8);
                afr[0][mt][3] = lds32_sw(sAh, rr + 8, kb + 8);
                if (SA) {
                    afr[SA ? 1 : 0][mt][0] = lds32_sw(sAl, rr,     kb);
                    afr[SA ? 1 : 0][mt][1] = lds32_sw(sAl, rr + 8, kb);
                    afr[SA ? 1 : 0][mt][2] = lds32_sw(sAl, rr,     kb + 8);
                    afr[SA ? 1 : 0][mt][3] = lds32_sw(sAl, rr + 8, kb + 8);
                }
            }
            uint32_t bfr[SB ? 2 : 1][8][2];
            #pragma unroll
            for (int nt = 0; nt < 8; nt++) {
                const int nr = n0 + nt * 8;
                bfr[0][nt][0] = lds32_sw(sBh, nr, kb);
                bfr[0][nt][1] = lds32_sw(sBh, nr, kb + 8);
                if (SB) {
                    bfr[SB ? 1 : 0][nt][0] = lds32_sw(sBl, nr, kb);
                    bfr[SB ? 1 : 0][nt][1] = lds32_sw(sBl, nr, kb + 8);
                }
            }
            #pragma unroll
            for (int mt = 0; mt < 2; mt++)
                #pragma unroll
                for (int nt = 0; nt < 8; nt++) {
                    mma16816(acc[mt][nt], afr[0][mt], bfr[0][nt]);
                    if (SB) mma16816(acc[mt][nt], afr[0][mt], bfr[SB ? 1 : 0][nt]);
                    if (SA) mma16816(acc[mt][nt], afr[SA ? 1 : 0][mt], bfr[0][nt]);
                }
        }
        __syncthreads();
        if (kt + 2 < KT) load_tile(kt + 2, (kt + 2) % 3);
    }

    #pragma unroll
    for (int mt = 0; mt < 2; mt++) {
        const int row = mblk + warp_m * 32 + mt * 16 + (lane >> 2);
        #pragma unroll
        for (int nt = 0; nt < 8; nt++) {
            const int col = nblk + warp_n * 64 + nt * 8 + (lane & 3) * 2;
            float b0 = 0.0f, b1 = 0.0f;
            if (bias) { b0 = bias[col]; b1 = bias[col + 1]; }
            float2 v0 = make_float2(acc[mt][nt][0] * scale + b0, acc[mt][nt][1] * scale + b1);
            float2 v1 = make_float2(acc[mt][nt][2] * scale + b0, acc[mt][nt][3] * scale + b1);
            *reinterpret_cast<float2*>(C + (size_t)row * ldc + col) = v0;
            *reinterpret_cast<float2*>(C + (size_t)(row + 8) * ldc + col) = v1;
        }
    }
}

// ---------------------------------------------------------------------------
// fp32 -> fp16 hi/lo split with pre-scale (elementwise, float4)
// ---------------------------------------------------------------------------
__device__ __forceinline__ void split1(float x, fp16& h, fp16& l) {
    h = __float2half(x);
    l = __float2half(x - __half2float(h));
}

__global__ void split_fp16(const float* __restrict__ in,
                           fp16* __restrict__ hi, fp16* __restrict__ lo,
                           int n, float scale)
{
    int i = (blockIdx.x * blockDim.x + threadIdx.x) * 4;
    if (i >= n) return;
    float4 v = *reinterpret_cast<const float4*>(in + i);
    fp16 h[4], l[4];
    split1(v.x * scale, h[0], l[0]); split1(v.y * scale, h[1], l[1]);
    split1(v.z * scale, h[2], l[2]); split1(v.w * scale, h[3], l[3]);
    *reinterpret_cast<__half2*>(hi + i)     = __halves2half2(h[0], h[1]);
    *reinterpret_cast<__half2*>(hi + i + 2) = __halves2half2(h[2], h[3]);
    *reinterpret_cast<__half2*>(lo + i)     = __halves2half2(l[0], l[1]);
    *reinterpret_cast<__half2*>(lo + i + 2) = __halves2half2(l[2], l[3]);
}

// fp32 [1024,1024] -> transposed fp16 hi/lo [1024,1024] with pre-scale
__global__ void splitT_fp16(const float* __restrict__ in,
                            fp16* __restrict__ hi, fp16* __restrict__ lo,
                            float scale)
{
    __shared__ float t[32][33];
    const int x0 = blockIdx.x * 32, y0 = blockIdx.y * 32;
    const int tx = threadIdx.x, ty = threadIdx.y;
    #pragma unroll
    for (int r = ty; r < 32; r += 8)
        t[r][tx] = in[(size_t)(y0 + r) * 1024 + x0 + tx];
    __syncthreads();
    #pragma unroll
    for (int r = ty; r < 32; r += 8) {
        float v = t[tx][r] * scale;
        fp16 h, l;
        split1(v, h, l);
        hi[(size_t)(x0 + r) * 1024 + y0 + tx] = h;
        lo[(size_t)(x0 + r) * 1024 + y0 + tx] = l;
    }
}

// fp32 [1024,1024] -> transposed single fp16 [1024,1024]
__global__ void convT_fp16(const float* __restrict__ in, fp16* __restrict__ outT)
{
    __shared__ float t[32][33];
    const int x0 = blockIdx.x * 32, y0 = blockIdx.y * 32;
    const int tx = threadIdx.x, ty = threadIdx.y;
    #pragma unroll
    for (int r = ty; r < 32; r += 8)
        t[r][tx] = in[(size_t)(y0 + r) * 1024 + x0 + tx];
    __syncthreads();
    #pragma unroll
    for (int r = ty; r < 32; r += 8)
        outT[(size_t)(x0 + r) * 1024 + y0 + tx] = __float2half(t[tx][r]);
}

// fp32 -> single fp16 (activations)
__global__ void tofp16_kernel(const float* __restrict__ in,
                              fp16* __restrict__ out, int n)
{
    int i = (blockIdx.x * blockDim.x + threadIdx.x) * 4;
    if (i >= n) return;
    float4 v = *reinterpret_cast<const float4*>(in + i);
    *reinterpret_cast<__half2*>(out + i)     = __halves2half2(__float2half(v.x), __float2half(v.y));
    *reinterpret_cast<__half2*>(out + i + 2) = __halves2half2(__float2half(v.z), __float2half(v.w));
}

// ---------------------------------------------------------------------------
// bf[c][j] = sum_k bmod[c%3][k] * W{l|r}1[k][j]
// ---------------------------------------------------------------------------
__global__ void bias_fold_kernel(
    const float* __restrict__ bt, const float* __restrict__ ba,
    const float* __restrict__ bv,
    const float* __restrict__ Wl1, const float* __restrict__ Wr1,
    float* __restrict__ bf)
{
    int g = blockIdx.x * blockDim.x + threadIdx.x;
    if (g >= 6 * 1024) return;
    int combo = g >> 10;
    int j = g & 1023;
    int m = combo % 3;
    const float* bvec = (m == 0) ? bt : (m == 1) ? ba : bv;
    const float* W = (combo < 3) ? Wl1 : Wr1;
    float s = 0.0f;
    for (int k = 0; k < 1024; k++) s += bvec[k] * W[k * 1024 + j];
    bf[g] = s;
}

// ---------------------------------------------------------------------------
// GAT1 (8 heads, dh=128): block per sentence, warp per head. x1 -> fp16.
// ---------------------------------------------------------------------------
__device__ __forceinline__ float lrelu02(float x) { return x > 0.0f ? x : 0.2f * x; }

__global__ __launch_bounds__(256) void gat1_kernel(
    const float* __restrict__ gl, const float* __restrict__ gr,
    const float* __restrict__ att, const float* __restrict__ b1,
    fp16* __restrict__ x1)
{
    const int b = blockIdx.x;
    const int h = threadIdx.x >> 5;
    const int lane = threadIdx.x & 31;
    const int dbase = lane * 4;

    const size_t base = (size_t)b * 3072 + h * 128 + dbase;
    float4 glv[3], grv[3];
    #pragma unroll
    for (int j = 0; j < 3; j++)
        glv[j] = *reinterpret_cast<const float4*>(gl + base + j * 1024);
    #pragma unroll
    for (int i = 0; i < 3; i++)
        grv[i] = *reinterpret_cast<const float4*>(gr + base + i * 1024);
    const float4 av = *reinterpret_cast<const float4*>(att + h * 128 + dbase);

    float e[3][3];
    #pragma unroll
    for (int i = 0; i < 3; i++)
        #pragma unroll
        for (int j = 0; j < 3; j++) {
            float s = av.x * lrelu02(glv[j].x + grv[i].x);
            s += av.y * lrelu02(glv[j].y + grv[i].y);
            s += av.z * lrelu02(glv[j].z + grv[i].z);
            s += av.w * lrelu02(glv[j].w + grv[i].w);
            e[i][j] = s;
        }
    #pragma unroll
    for (int i = 0; i < 3; i++)
        #pragma unroll
        for (int j = 0; j < 3; j++)
            #pragma unroll
            for (int o = 16; o > 0; o >>= 1)
                e[i][j] += __shfl_xor_sync(0xFFFFFFFFu, e[i][j], o);

    float alpha[3][3];
    #pragma unroll
    for (int i = 0; i < 3; i++) {
        float mx = fmaxf(e[i][0], fmaxf(e[i][1], e[i][2]));
        float p0 = expf(e[i][0] - mx);
        float p1 = expf(e[i][1] - mx);
        float p2 = expf(e[i][2] - mx);
        float inv = 1.0f / (p0 + p1 + p2);
        alpha[i][0] = p0 * inv; alpha[i][1] = p1 * inv; alpha[i][2] = p2 * inv;
    }

    const float4 bb = *reinterpret_cast<const float4*>(b1 + h * 128 + dbase);
    #pragma unroll
    for (int i = 0; i < 3; i++) {
        float o[4];
        o[0] = alpha[i][0]*glv[0].x + alpha[i][1]*glv[1].x + alpha[i][2]*glv[2].x + bb.x;
        o[1] = alpha[i][0]*glv[0].y + alpha[i][1]*glv[1].y + alpha[i][2]*glv[2].y + bb.y;
        o[2] = alpha[i][0]*glv[0].z + alpha[i][1]*glv[1].z + alpha[i][2]*glv[2].z + bb.z;
        o[3] = alpha[i][0]*glv[0].w + alpha[i][1]*glv[1].w + alpha[i][2]*glv[2].w + bb.w;
        #pragma unroll
        for (int q = 0; q < 4; q++)
            o[q] = o[q] > 0.0f ? o[q] : (expf(o[q]) - 1.0f);
        const size_t idx = (size_t)b * 3072 + i * 1024 + h * 128 + dbase;
        *reinterpret_cast<__half2*>(x1 + idx) =
            __halves2half2(__float2half(o[0]), __float2half(o[1]));
        *reinterpret_cast<__half2*>(x1 + idx + 2) =
            __halves2half2(__float2half(o[2]), __float2half(o[3]));
    }
}

// ---------------------------------------------------------------------------
// GAT2 (1 head, d=1024) + mean pool. One warp per sentence.
// ---------------------------------------------------------------------------
__global__ __launch_bounds__(256) void gat2_kernel(
    const float* __restrict__ gl, const float* __restrict__ gr,
    const float* __restrict__ att, const float* __restrict__ b2,
    float* __restrict__ out)
{
    const int b = blockIdx.x * 8 + (threadIdx.x >> 5);
    const int lane = threadIdx.x & 31;
    const float* glb = gl + (size_t)b * 3072;
    const float* grb = gr + (size_t)b * 3072;

    float e[9] = {0,0,0,0,0,0,0,0,0};
    #pragma unroll
    for (int c = 0; c < 8; c++) {
        const int d = c * 128 + lane * 4;
        const float4 av = *reinterpret_cast<const float4*>(att + d);
        float4 glv[3], grv[3];
        #pragma unroll
        for (int j = 0; j < 3; j++)
            glv[j] = *reinterpret_cast<const float4*>(glb + j * 1024 + d);
        #pragma unroll
        for (int i = 0; i < 3; i++)
            grv[i] = *reinterpret_cast<const float4*>(grb + i * 1024 + d);
        #pragma unroll
        for (int i = 0; i < 3; i++)
            #pragma unroll
            for (int j = 0; j < 3; j++) {
                float s = av.x * lrelu02(glv[j].x + grv[i].x);
                s += av.y * lrelu02(glv[j].y + grv[i].y);
                s += av.z * lrelu02(glv[j].z + grv[i].z);
                s += av.w * lrelu02(glv[j].w + grv[i].w);
                e[i * 3 + j] += s;
            }
    }
    #pragma unroll
    for (int k = 0; k < 9; k++)
        #pragma unroll
        for (int o = 16; o > 0; o >>= 1)
            e[k] += __shfl_xor_sync(0xFFFFFFFFu, e[k], o);

    float w[3] = {0.0f, 0.0f, 0.0f};
    #pragma unroll
    for (int i = 0; i < 3; i++) {
        float mx = fmaxf(e[i*3+0], fmaxf(e[i*3+1], e[i*3+2]));
        float p0 = expf(e[i*3+0] - mx);
        float p1 = expf(e[i*3+1] - mx);
        float p2 = expf(e[i*3+2] - mx);
        float inv = 1.0f / (p0 + p1 + p2);
        w[0] += p0 * inv; w[1] += p1 * inv; w[2] += p2 * inv;
    }
    w[0] *= (1.0f/3.0f); w[1] *= (1.0f/3.0f); w[2] *= (1.0f/3.0f);

    #pragma unroll
    for (int c = 0; c < 8; c++) {
        const int d = c * 128 + lane * 4;
        const float4 bv = *reinterpret_cast<const float4*>(b2 + d);
        float4 g0 = *reinterpret_cast<const float4*>(glb + 0 * 1024 + d);
        float4 g1 = *reinterpret_cast<const float4*>(glb + 1 * 1024 + d);
        float4 g2 = *reinterpret_cast<const float4*>(glb + 2 * 1024 + d);
        float4 o;
        o.x = w[0]*g0.x + w[1]*g1.x + w[2]*g2.x + bv.x;
        o.y = w[0]*g0.y + w[1]*g1.y + w[2]*g2.y + bv.y;
        o.z = w[0]*g0.z + w[1]*g1.z + w[2]*g2.z + bv.z;
        o.w = w[0]*g0.w + w[1]*g1.w + w[2]*g2.w + bv.w;
        *reinterpret_cast<float4*>(out + (size_t)b * 1024 + d) = o;
    }
}

// ---------------------------------------------------------------------------
// Launch
// ---------------------------------------------------------------------------
extern "C" void kernel_launch(void* const* d_in, const int* in_sizes, int n_in,
                              void* d_out, int out_size)
{
    const float* feats[3] = { (const float*)d_in[0], (const float*)d_in[1], (const float*)d_in[2] };
    const float* Wm[3]    = { (const float*)d_in[3], (const float*)d_in[5], (const float*)d_in[7] };
    const float* bt   = (const float*)d_in[4];
    const float* ba   = (const float*)d_in[6];
    const float* bv   = (const float*)d_in[8];
    const float* Wl1  = (const float*)d_in[9];
    const float* Wr1  = (const float*)d_in[10];
    const float* att1 = (const float*)d_in[11];
    const float* b1   = (const float*)d_in[12];
    const float* Wl2  = (const float*)d_in[13];
    const float* Wr2  = (const float*)d_in[14];
    const float* att2 = (const float*)d_in[15];
    const float* b2   = (const float*)d_in[16];
    float* out = (float*)d_out;

    float *Wf, *bf, *gl1, *gr1, *gl2, *gr2;
    fp16 *WmH, *WmL, *WT1H, *WT1L, *WT2, *WfT, *feat16, *x1;
    cudaGetSymbolAddress((void**)&Wf,  g_Wf);
    cudaGetSymbolAddress((void**)&bf,  g_bf);
    cudaGetSymbolAddress((void**)&gl1, g_gl1);
    cudaGetSymbolAddress((void**)&gr1, g_gr1);
    cudaGetSymbolAddress((void**)&gl2, g_gl2);
    cudaGetSymbolAddress((void**)&gr2, g_gr2);
    cudaGetSymbolAddress((void**)&WmH,  g_WmH);
    cudaGetSymbolAddress((void**)&WmL,  g_WmL);
    cudaGetSymbolAddress((void**)&WT1H, g_WT1H);
    cudaGetSymbolAddress((void**)&WT1L, g_WT1L);
    cudaGetSymbolAddress((void**)&WT2,  g_WT2);
    cudaGetSymbolAddress((void**)&WfT,  g_WfT);
    cudaGetSymbolAddress((void**)&feat16, g_feat);
    cudaGetSymbolAddress((void**)&x1, g_x1);

    const int SMEM33 = 3 * 4 * 16384;   // fold kernel (SA && SB): 192 KB
    const int SMEM11 = 3 * 2 * 16384;   // 1-term layer kernel:     96 KB
    cudaFuncSetAttribute(gemm_fp16<true, true>,
                         cudaFuncAttributeMaxDynamicSharedMemorySize, SMEM33);
    cudaFuncSetAttribute(gemm_fp16<false, false>,
                         cudaFuncAttributeMaxDynamicSharedMemorySize, SMEM11);

    const size_t M1 = 1024 * 1024;
    const dim3 tB(32, 8);
    const dim3 tG(32, 32);

    const float S_FOLD = 1024.0f;   // fold pre-scale so fp16 lo stays normal

    // 1. weight splits / conversions
    splitT_fp16<<<tG, tB>>>(Wl1, WT1H, WT1L, S_FOLD);
    splitT_fp16<<<tG, tB>>>(Wr1, WT1H + M1, WT1L + M1, S_FOLD);
    convT_fp16<<<tG, tB>>>(Wl2, WT2);
    convT_fp16<<<tG, tB>>>(Wr2, WT2 + M1);
    for (int m = 0; m < 3; m++)
        split_fp16<<<1024, 256>>>(Wm[m], WmH + m * M1, WmL + m * M1,
                                  1024 * 1024, S_FOLD);

    // 2. fold GEMMs (3-term): Wf[c] = Wm[c%3] @ W{l|r}1
    {
        dim3 grid(8, 8);
        for (int c = 0; c < 6; c++) {
            const fp16* Bh = WT1H + (c < 3 ? 0 : M1);
            const fp16* Bl = WT1L + (c < 3 ? 0 : M1);
            gemm_fp16<true, true><<<grid, 256, SMEM33>>>(1024, 1024, 1024,
                WmH + (c % 3) * M1, WmL + (c % 3) * M1, 1024,
                Bh, Bl, 1024, Wf + (size_t)c * M1, 1024,
                1.0f / (S_FOLD * S_FOLD), nullptr);
        }
    }
    bias_fold_kernel<<<24, 256>>>(bt, ba, bv, Wl1, Wr1, bf);
    for (int c = 0; c < 6; c++)
        convT_fp16<<<tG, tB>>>(Wf + (size_t)c * M1, WfT + c * M1);

    // 3. feature conversion (single fp16)
    for (int m = 0; m < 3; m++)
        tofp16_kernel<<<BATCH, 256>>>(feats[m], feat16 + (size_t)m * BATCH * 1024,
                                      BATCH * 1024);

    // 4. layer-1 GEMMs (1-term): gl1/gr1 (interleaved [B,3,H], ldc=3072)
    {
        dim3 grid(8, BATCH / 128);
        for (int m = 0; m < 3; m++) {
            const fp16* A = feat16 + (size_t)m * BATCH * 1024;
            gemm_fp16<false, false><<<grid, 256, SMEM11>>>(BATCH, 1024, 1024,
                A, nullptr, 1024, WfT + m * M1, nullptr, 1024,
                gl1 + m * 1024, 3072, 1.0f, bf + m * 1024);
            gemm_fp16<false, false><<<grid, 256, SMEM11>>>(BATCH, 1024, 1024,
                A, nullptr, 1024, WfT + (3 + m) * M1, nullptr, 1024,
                gr1 + m * 1024, 3072, 1.0f, bf + (3 + m) * 1024);
        }
    }

    // 5. GAT1 -> x1 (fp16)
    gat1_kernel<<<BATCH, 256>>>(gl1, gr1, att1, b1, x1);

    // 6. layer-2 GEMMs (1-term)
    {
        dim3 grid(8, (3 * BATCH) / 128);
        gemm_fp16<false, false><<<grid, 256, SMEM11>>>(3 * BATCH, 1024, 1024,
            x1, nullptr, 1024, WT2, nullptr, 1024, gl2, 1024, 1.0f, nullptr);
        gemm_fp16<false, false><<<grid, 256, SMEM11>>>(3 * BATCH, 1024, 1024,
            x1, nullptr, 1024, WT2 + M1, nullptr, 1024, gr2, 1024, 1.0f, nullptr);
    }

    // 7. GAT2 -> out
    gat2_kernel<<<BATCH / 8, 256>>>(gl2, gr2, att2, b2, out);
}

// round 7
// speedup vs baseline: 6.9436x; 1.2657x over previous
#include <cuda_runtime.h>
#include <cuda_fp16.h>
#include <cstdint>
#include <math.h>

// ---------------------------------------------------------------------------
// IntraSentenceGNN on GB300 (sm_103 base ISA): mma.sync fp16 GEMMs with
// ldmatrix fragment loads, 2 CTAs/SM, fp16 intermediates.
//
//  1. split/transpose weights
//  2. fold: Wf[c] = Wm[c%3] @ W{l|r}1  (one batched launch, 3-term hi/lo)
//  3. gl1/gr1 = feat_m @ Wf + bf      (1-term fp16, fp16 out)
//  4. GAT1 attention + ELU -> x1 (fp16)
//  5. gl2/gr2 = x1 @ W{l|r}2          (1-term fp16, fp16 out)
//  6. GAT2 attention + mean-pool -> out (fp32)
// ---------------------------------------------------------------------------

#define BATCH 32768
#define HDIM  1024

typedef __half fp16;

// ------------------------------ scratch -----------------------------------
__device__ __align__(256) float g_Wf [6 * 1024 * 1024];
__device__ __align__(256) float g_bf [6 * 1024];
__device__ __align__(256) fp16 g_gl1[BATCH * 3 * HDIM];
__device__ __align__(256) fp16 g_gr1[BATCH * 3 * HDIM];
__device__ __align__(256) fp16 g_gl2[BATCH * 3 * HDIM];
__device__ __align__(256) fp16 g_gr2[BATCH * 3 * HDIM];

__device__ __align__(256) fp16 g_WmH [3 * 1024 * 1024];
__device__ __align__(256) fp16 g_WmL [3 * 1024 * 1024];
__device__ __align__(256) fp16 g_WT1H[2 * 1024 * 1024];
__device__ __align__(256) fp16 g_WT1L[2 * 1024 * 1024];
__device__ __align__(256) fp16 g_WT2 [2 * 1024 * 1024];
__device__ __align__(256) fp16 g_WfT [6 * 1024 * 1024];
__device__ __align__(256) fp16 g_feat[3 * BATCH * 1024];
__device__ __align__(256) fp16 g_x1  [BATCH * 3 * 1024];

// --------------------------- PTX helpers ----------------------------------
__device__ __forceinline__ uint32_t smem_u32(const void* p) {
    uint32_t a;
    asm("{ .reg .u64 t; cvta.to.shared.u64 t, %1; cvt.u32.u64 %0, t; }"
        : "=r"(a) : "l"(p));
    return a;
}
__device__ __forceinline__ void cp16(uint32_t sdst, const void* gsrc) {
    asm volatile("cp.async.cg.shared.global [%0], [%1], 16;" :: "r"(sdst), "l"(gsrc));
}
__device__ __forceinline__ void cp_commit() {
    asm volatile("cp.async.commit_group;" ::: "memory");
}
__device__ __forceinline__ void cp_wait1() {
    asm volatile("cp.async.wait_group 1;" ::: "memory");
}
__device__ __forceinline__ void cp_wait0() {
    asm volatile("cp.async.wait_group 0;" ::: "memory");
}

// SW128-swizzled byte address within a 128B-row tile
__device__ __forceinline__ uint32_t sw_addr(uint32_t base, int row, int colb) {
    uint32_t off = (uint32_t)(row * 128 + colb);
    return base + (off ^ ((off >> 3) & 0x70));
}

// ldmatrix x4, non-transposed (A: [m][k] rows, B: [n][k] rows both match)
__device__ __forceinline__ void ldsm4(uint32_t addr, uint32_t* r) {
    asm volatile("ldmatrix.sync.aligned.m8n8.x4.shared.b16 {%0,%1,%2,%3}, [%4];"
        : "=r"(r[0]), "=r"(r[1]), "=r"(r[2]), "=r"(r[3]) : "r"(addr));
}

__device__ __forceinline__ void mma16816(float* c, const uint32_t* a, const uint32_t* b) {
    asm volatile(
        "mma.sync.aligned.m16n8k16.row.col.f32.f16.f16.f32 "
        "{%0,%1,%2,%3}, {%4,%5,%6,%7}, {%8,%9}, {%0,%1,%2,%3};"
        : "+f"(c[0]), "+f"(c[1]), "+f"(c[2]), "+f"(c[3])
        : "r"(a[0]), "r"(a[1]), "r"(a[2]), "r"(a[3]), "r"(b[0]), "r"(b[1]));
}

// load one 128x64 fp16 subtile (swizzled) via cp.async, 256 threads
__device__ __forceinline__ void load_sub(const fp16* src, int blk, int ld,
                                         uint32_t rb, int kofs, int tid) {
    #pragma unroll
    for (int i = 0; i < 4; i++) {
        const int c = tid + i * 256;
        const int row = c >> 3, kc = c & 7;
        const void* g = src + (size_t)(blk + row) * ld + kofs + kc * 8;
        uint32_t off = (uint32_t)(row * 128 + kc * 16);
        off ^= (off >> 3) & 0x70;
        cp16(rb + off, g);
    }
}

// ---------------------------------------------------------------------------
// 1-term fp16 GEMM: C[M,N] = sum_k A[m,k]*BT[n,k] (+ bias[n]), fp16 output.
// CTA 128x128, BK=64, 3-stage cp.async, 8 warps (4m x 2n), 2 CTAs/SM.
// ---------------------------------------------------------------------------
#define SMEM_1T (3 * 32768)

__global__ __launch_bounds__(256, 2) void gemm_1t(
    int M, int N, int K,
    const fp16* __restrict__ A, int lda,
    const fp16* __restrict__ B, int ldb,
    fp16* __restrict__ C, int ldc, const float* __restrict__ bias)
{
    extern __shared__ char smem[];
    const uint32_t sbase = smem_u32(smem);
    const int tid  = threadIdx.x;
    const int wid  = tid >> 5;
    const int lane = tid & 31;
    const int warp_m = wid & 3;
    const int warp_n = wid >> 2;

    const int mblk = blockIdx.y * 128;
    const int nblk = blockIdx.x * 128;
    const int KT = K >> 6;

    auto load_tile = [&](int kt, int s) {
        const uint32_t st = sbase + s * 32768;
        load_sub(A, mblk, lda, st,         kt * 64, tid);
        load_sub(B, nblk, ldb, st + 16384, kt * 64, tid);
        cp_commit();
    };

    float acc[2][8][4];
    #pragma unroll
    for (int mt = 0; mt < 2; mt++)
        #pragma unroll
        for (int nt = 0; nt < 8; nt++)
            #pragma unroll
            for (int q = 0; q < 4; q++) acc[mt][nt][q] = 0.0f;

    load_tile(0, 0);
    load_tile(1, 1);

    const int qa_r = ((lane >> 3) & 1) * 8 + (lane & 7);  // A row-in-16 + lane row
    const int qa_c = (lane >> 4) * 16;                     // A col bytes
    const int qb_r = (lane >> 4) * 8 + (lane & 7);         // B row
    const int qb_c = ((lane >> 3) & 1) * 16;               // B col bytes

    for (int kt = 0; kt < KT; kt++) {
        if (kt + 1 < KT) cp_wait1(); else cp_wait0();
        __syncthreads();

        const uint32_t st = sbase + (kt % 3) * 32768;
        const uint32_t sA = st, sB = st + 16384;

        #pragma unroll
        for (int ks = 0; ks < 4; ks++) {
            uint32_t afr[2][4];
            #pragma unroll
            for (int mt = 0; mt < 2; mt++)
                ldsm4(sw_addr(sA, warp_m * 32 + mt * 16 + qa_r, ks * 32 + qa_c), afr[mt]);
            uint32_t bfr[8][2];
            #pragma unroll
            for (int p = 0; p < 4; p++) {
                uint32_t r[4];
                ldsm4(sw_addr(sB, warp_n * 64 + p * 16 + qb_r, ks * 32 + qb_c), r);
                bfr[2*p][0] = r[0]; bfr[2*p][1] = r[1];
                bfr[2*p+1][0] = r[2]; bfr[2*p+1][1] = r[3];
            }
            #pragma unroll
            for (int mt = 0; mt < 2; mt++)
                #pragma unroll
                for (int nt = 0; nt < 8; nt++)
                    mma16816(acc[mt][nt], afr[mt], bfr[nt]);
        }
        __syncthreads();
        if (kt + 2 < KT) load_tile(kt + 2, (kt + 2) % 3);
    }

    #pragma unroll
    for (int mt = 0; mt < 2; mt++) {
        const int row = mblk + warp_m * 32 + mt * 16 + (lane >> 2);
        #pragma unroll
        for (int nt = 0; nt < 8; nt++) {
            const int col = nblk + warp_n * 64 + nt * 8 + (lane & 3) * 2;
            float b0 = 0.0f, b1 = 0.0f;
            if (bias) { b0 = bias[col]; b1 = bias[col + 1]; }
            *reinterpret_cast<__half2*>(C + (size_t)row * ldc + col) =
                __floats2half2_rn(acc[mt][nt][0] + b0, acc[mt][nt][1] + b1);
            *reinterpret_cast<__half2*>(C + (size_t)(row + 8) * ldc + col) =
                __floats2half2_rn(acc[mt][nt][2] + b0, acc[mt][nt][3] + b1);
        }
    }
}

// ---------------------------------------------------------------------------
// Batched 3-term fold GEMM: Wf[c] = Wm[c%3] @ W{l|r}1, c = blockIdx.z (0..5).
// A,B both hi/lo split (prescaled); fp32 out with rescale.
// ---------------------------------------------------------------------------
#define SMEM_FOLD (3 * 65536)

__global__ __launch_bounds__(256, 1) void gemm_fold(
    const fp16* __restrict__ WmH, const fp16* __restrict__ WmL,
    const fp16* __restrict__ W1H, const fp16* __restrict__ W1L,
    float* __restrict__ Wf, float scale)
{
    const size_t M1 = 1024 * 1024;
    const int c = blockIdx.z;
    const fp16* Ah = WmH + (size_t)(c % 3) * M1;
    const fp16* Al = WmL + (size_t)(c % 3) * M1;
    const fp16* Bh = W1H + (size_t)(c < 3 ? 0 : 1) * M1;
    const fp16* Bl = W1L + (size_t)(c < 3 ? 0 : 1) * M1;
    float* C = Wf + (size_t)c * M1;

    extern __shared__ char smem[];
    const uint32_t sbase = smem_u32(smem);
    const int tid  = threadIdx.x;
    const int wid  = tid >> 5;
    const int lane = tid & 31;
    const int warp_m = wid & 3;
    const int warp_n = wid >> 2;

    const int mblk = blockIdx.y * 128;
    const int nblk = blockIdx.x * 128;
    const int KT = 16;

    auto load_tile = [&](int kt, int s) {
        const uint32_t st = sbase + s * 65536;
        load_sub(Ah, mblk, 1024, st,         kt * 64, tid);
        load_sub(Al, mblk, 1024, st + 16384, kt * 64, tid);
        load_sub(Bh, nblk, 1024, st + 32768, kt * 64, tid);
        load_sub(Bl, nblk, 1024, st + 49152, kt * 64, tid);
        cp_commit();
    };

    float acc[2][8][4];
    #pragma unroll
    for (int mt = 0; mt < 2; mt++)
        #pragma unroll
        for (int nt = 0; nt < 8; nt++)
            #pragma unroll
            for (int q = 0; q < 4; q++) acc[mt][nt][q] = 0.0f;

    load_tile(0, 0);
    load_tile(1, 1);

    const int qa_r = ((lane >> 3) & 1) * 8 + (lane & 7);
    const int qa_c = (lane >> 4) * 16;
    const int qb_r = (lane >> 4) * 8 + (lane & 7);
    const int qb_c = ((lane >> 3) & 1) * 16;

    for (int kt = 0; kt < KT; kt++) {
        if (kt + 1 < KT) cp_wait1(); else cp_wait0();
        __syncthreads();

        const uint32_t st = sbase + (kt % 3) * 65536;
        const uint32_t sAh = st, sAl = st + 16384, sBh = st + 32768, sBl = st + 49152;

        #pragma unroll
        for (int ks = 0; ks < 4; ks++) {
            uint32_t afH[2][4], afL[2][4];
            #pragma unroll
            for (int mt = 0; mt < 2; mt++) {
                const int rr = warp_m * 32 + mt * 16 + qa_r;
                const int cc = ks * 32 + qa_c;
                ldsm4(sw_addr(sAh, rr, cc), afH[mt]);
                ldsm4(sw_addr(sAl, rr, cc), afL[mt]);
            }
            uint32_t bfH[8][2], bfL[8][2];
            #pragma unroll
            for (int p = 0; p < 4; p++) {
                const int rr = warp_n * 64 + p * 16 + qb_r;
                const int cc = ks * 32 + qb_c;
                uint32_t r[4];
                ldsm4(sw_addr(sBh, rr, cc), r);
                bfH[2*p][0] = r[0]; bfH[2*p][1] = r[1];
                bfH[2*p+1][0] = r[2]; bfH[2*p+1][1] = r[3];
                ldsm4(sw_addr(sBl, rr, cc), r);
                bfL[2*p][0] = r[0]; bfL[2*p][1] = r[1];
                bfL[2*p+1][0] = r[2]; bfL[2*p+1][1] = r[3];
            }
            #pragma unroll
            for (int mt = 0; mt < 2; mt++)
                #pragma unroll
                for (int nt = 0; nt < 8; nt++) {
                    mma16816(acc[mt][nt], afH[mt], bfH[nt]);
                    mma16816(acc[mt][nt], afH[mt], bfL[nt]);
                    mma16816(acc[mt][nt], afL[mt], bfH[nt]);
                }
        }
        __syncthreads();
        if (kt + 2 < KT) load_tile(kt + 2, (kt + 2) % 3);
    }

    #pragma unroll
    for (int mt = 0; mt < 2; mt++) {
        const int row = mblk + warp_m * 32 + mt * 16 + (lane >> 2);
        #pragma unroll
        for (int nt = 0; nt < 8; nt++) {
            const int col = nblk + warp_n * 64 + nt * 8 + (lane & 3) * 2;
            float2 v0 = make_float2(acc[mt][nt][0] * scale, acc[mt][nt][1] * scale);
            float2 v1 = make_float2(acc[mt][nt][2] * scale, acc[mt][nt][3] * scale);
            *reinterpret_cast<float2*>(C + (size_t)row * 1024 + col) = v0;
            *reinterpret_cast<float2*>(C + (size_t)(row + 8) * 1024 + col) = v1;
        }
    }
}

// ---------------------------------------------------------------------------
// conversions
// ---------------------------------------------------------------------------
__device__ __forceinline__ void split1(float x, fp16& h, fp16& l) {
    h = __float2half(x);
    l = __float2half(x - __half2float(h));
}

__global__ void split_fp16(const float* __restrict__ in,
                           fp16* __restrict__ hi, fp16* __restrict__ lo,
                           int n, float scale)
{
    int i = (blockIdx.x * blockDim.x + threadIdx.x) * 4;
    if (i >= n) return;
    float4 v = *reinterpret_cast<const float4*>(in + i);
    fp16 h[4], l[4];
    split1(v.x * scale, h[0], l[0]); split1(v.y * scale, h[1], l[1]);
    split1(v.z * scale, h[2], l[2]); split1(v.w * scale, h[3], l[3]);
    *reinterpret_cast<__half2*>(hi + i)     = __halves2half2(h[0], h[1]);
    *reinterpret_cast<__half2*>(hi + i + 2) = __halves2half2(h[2], h[3]);
    *reinterpret_cast<__half2*>(lo + i)     = __halves2half2(l[0], l[1]);
    *reinterpret_cast<__half2*>(lo + i + 2) = __halves2half2(l[2], l[3]);
}

__global__ void splitT_fp16(const float* __restrict__ in,
                            fp16* __restrict__ hi, fp16* __restrict__ lo,
                            float scale)
{
    __shared__ float t[32][33];
    const int x0 = blockIdx.x * 32, y0 = blockIdx.y * 32;
    const int tx = threadIdx.x, ty = threadIdx.y;
    #pragma unroll
    for (int r = ty; r < 32; r += 8)
        t[r][tx] = in[(size_t)(y0 + r) * 1024 + x0 + tx];
    __syncthreads();
    #pragma unroll
    for (int r = ty; r < 32; r += 8) {
        float v = t[tx][r] * scale;
        fp16 h, l;
        split1(v, h, l);
        hi[(size_t)(x0 + r) * 1024 + y0 + tx] = h;
        lo[(size_t)(x0 + r) * 1024 + y0 + tx] = l;
    }
}

__global__ void convT_fp16(const float* __restrict__ in, fp16* __restrict__ outT)
{
    __shared__ float t[32][33];
    const int x0 = blockIdx.x * 32, y0 = blockIdx.y * 32;
    const int tx = threadIdx.x, ty = threadIdx.y;
    #pragma unroll
    for (int r = ty; r < 32; r += 8)
        t[r][tx] = in[(size_t)(y0 + r) * 1024 + x0 + tx];
    __syncthreads();
    #pragma unroll
    for (int r = ty; r < 32; r += 8)
        outT[(size_t)(x0 + r) * 1024 + y0 + tx] = __float2half(t[tx][r]);
}

__global__ void tofp16_kernel(const float* __restrict__ in,
                              fp16* __restrict__ out, int n)
{
    int i = (blockIdx.x * blockDim.x + threadIdx.x) * 4;
    if (i >= n) return;
    float4 v = *reinterpret_cast<const float4*>(in + i);
    *reinterpret_cast<__half2*>(out + i)     = __floats2half2_rn(v.x, v.y);
    *reinterpret_cast<__half2*>(out + i + 2) = __floats2half2_rn(v.z, v.w);
}

__global__ void bias_fold_kernel(
    const float* __restrict__ bt, const float* __restrict__ ba,
    const float* __restrict__ bv,
    const float* __restrict__ Wl1, const float* __restrict__ Wr1,
    float* __restrict__ bf)
{
    int g = blockIdx.x * blockDim.x + threadIdx.x;
    if (g >= 6 * 1024) return;
    int combo = g >> 10;
    int j = g & 1023;
    int m = combo % 3;
    const float* bvec = (m == 0) ? bt : (m == 1) ? ba : bv;
    const float* W = (combo < 3) ? Wl1 : Wr1;
    float s = 0.0f;
    for (int k = 0; k < 1024; k++) s += bvec[k] * W[k * 1024 + j];
    bf[g] = s;
}

// ---------------------------------------------------------------------------
// attention kernels (fp16 inputs)
// ---------------------------------------------------------------------------
__device__ __forceinline__ float lrelu02(float x) { return x > 0.0f ? x : 0.2f * x; }

__device__ __forceinline__ float4 ld4h(const fp16* p) {
    uint2 u = *reinterpret_cast<const uint2*>(p);
    float2 f01 = __half22float2(*reinterpret_cast<__half2*>(&u.x));
    float2 f23 = __half22float2(*reinterpret_cast<__half2*>(&u.y));
    return make_float4(f01.x, f01.y, f23.x, f23.y);
}

__global__ __launch_bounds__(256) void gat1_kernel(
    const fp16* __restrict__ gl, const fp16* __restrict__ gr,
    const float* __restrict__ att, const float* __restrict__ b1,
    fp16* __restrict__ x1)
{
    const int b = blockIdx.x;
    const int h = threadIdx.x >> 5;
    const int lane = threadIdx.x & 31;
    const int dbase = lane * 4;

    const size_t base = (size_t)b * 3072 + h * 128 + dbase;
    float4 glv[3], grv[3];
    #pragma unroll
    for (int j = 0; j < 3; j++) glv[j] = ld4h(gl + base + j * 1024);
    #pragma unroll
    for (int i = 0; i < 3; i++) grv[i] = ld4h(gr + base + i * 1024);
    const float4 av = *reinterpret_cast<const float4*>(att + h * 128 + dbase);

    float e[3][3];
    #pragma unroll
    for (int i = 0; i < 3; i++)
        #pragma unroll
        for (int j = 0; j < 3; j++) {
            float s = av.x * lrelu02(glv[j].x + grv[i].x);
            s += av.y * lrelu02(glv[j].y + grv[i].y);
            s += av.z * lrelu02(glv[j].z + grv[i].z);
            s += av.w * lrelu02(glv[j].w + grv[i].w);
            e[i][j] = s;
        }
    #pragma unroll
    for (int i = 0; i < 3; i++)
        #pragma unroll
        for (int j = 0; j < 3; j++)
            #pragma unroll
            for (int o = 16; o > 0; o >>= 1)
                e[i][j] += __shfl_xor_sync(0xFFFFFFFFu, e[i][j], o);

    float alpha[3][3];
    #pragma unroll
    for (int i = 0; i < 3; i++) {
        float mx = fmaxf(e[i][0], fmaxf(e[i][1], e[i][2]));
        float p0 = expf(e[i][0] - mx);
        float p1 = expf(e[i][1] - mx);
        float p2 = expf(e[i][2] - mx);
        float inv = 1.0f / (p0 + p1 + p2);
        alpha[i][0] = p0 * inv; alpha[i][1] = p1 * inv; alpha[i][2] = p2 * inv;
    }

    const float4 bb = *reinterpret_cast<const float4*>(b1 + h * 128 + dbase);
    #pragma unroll
    for (int i = 0; i < 3; i++) {
        float o[4];
        o[0] = alpha[i][0]*glv[0].x + alpha[i][1]*glv[1].x + alpha[i][2]*glv[2].x + bb.x;
        o[1] = alpha[i][0]*glv[0].y + alpha[i][1]*glv[1].y + alpha[i][2]*glv[2].y + bb.y;
        o[2] = alpha[i][0]*glv[0].z + alpha[i][1]*glv[1].z + alpha[i][2]*glv[2].z + bb.z;
        o[3] = alpha[i][0]*glv[0].w + alpha[i][1]*glv[1].w + alpha[i][2]*glv[2].w + bb.w;
        #pragma unroll
        for (int q = 0; q < 4; q++)
            o[q] = o[q] > 0.0f ? o[q] : (expf(o[q]) - 1.0f);
        const size_t idx = (size_t)b * 3072 + i * 1024 + h * 128 + dbase;
        *reinterpret_cast<__half2*>(x1 + idx)     = __floats2half2_rn(o[0], o[1]);
        *reinterpret_cast<__half2*>(x1 + idx + 2) = __floats2half2_rn(o[2], o[3]);
    }
}

__global__ __launch_bounds__(256) void gat2_kernel(
    const fp16* __restrict__ gl, const fp16* __restrict__ gr,
    const float* __restrict__ att, const float* __restrict__ b2,
    float* __restrict__ out)
{
    const int b = blockIdx.x * 8 + (threadIdx.x >> 5);
    const int lane = threadIdx.x & 31;
    const fp16* glb = gl + (size_t)b * 3072;
    const fp16* grb = gr + (size_t)b * 3072;

    float e[9] = {0,0,0,0,0,0,0,0,0};
    #pragma unroll
    for (int c = 0; c < 8; c++) {
        const int d = c * 128 + lane * 4;
        const float4 av = *reinterpret_cast<const float4*>(att + d);
        float4 glv[3], grv[3];
        #pragma unroll
        for (int j = 0; j < 3; j++) glv[j] = ld4h(glb + j * 1024 + d);
        #pragma unroll
        for (int i = 0; i < 3; i++) grv[i] = ld4h(grb + i * 1024 + d);
        #pragma unroll
        for (int i = 0; i < 3; i++)
            #pragma unroll
            for (int j = 0; j < 3; j++) {
                float s = av.x * lrelu02(glv[j].x + grv[i].x);
                s += av.y * lrelu02(glv[j].y + grv[i].y);
                s += av.z * lrelu02(glv[j].z + grv[i].z);
                s += av.w * lrelu02(glv[j].w + grv[i].w);
                e[i * 3 + j] += s;
            }
    }
    #pragma unroll
    for (int k = 0; k < 9; k++)
        #pragma unroll
        for (int o = 16; o > 0; o >>= 1)
            e[k] += __shfl_xor_sync(0xFFFFFFFFu, e[k], o);

    float w[3] = {0.0f, 0.0f, 0.0f};
    #pragma unroll
    for (int i = 0; i < 3; i++) {
        float mx = fmaxf(e[i*3+0], fmaxf(e[i*3+1], e[i*3+2]));
        float p0 = expf(e[i*3+0] - mx);
        float p1 = expf(e[i*3+1] - mx);
        float p2 = expf(e[i*3+2] - mx);
        float inv = 1.0f / (p0 + p1 + p2);
        w[0] += p0 * inv; w[1] += p1 * inv; w[2] += p2 * inv;
    }
    w[0] *= (1.0f/3.0f); w[1] *= (1.0f/3.0f); w[2] *= (1.0f/3.0f);

    #pragma unroll
    for (int c = 0; c < 8; c++) {
        const int d = c * 128 + lane * 4;
        const float4 bv = *reinterpret_cast<const float4*>(b2 + d);
        float4 g0 = ld4h(glb + 0 * 1024 + d);
        float4 g1 = ld4h(glb + 1 * 1024 + d);
        float4 g2 = ld4h(glb + 2 * 1024 + d);
        float4 o;
        o.x = w[0]*g0.x + w[1]*g1.x + w[2]*g2.x + bv.x;
        o.y = w[0]*g0.y + w[1]*g1.y + w[2]*g2.y + bv.y;
        o.z = w[0]*g0.z + w[1]*g1.z + w[2]*g2.z + bv.z;
        o.w = w[0]*g0.w + w[1]*g1.w + w[2]*g2.w + bv.w;
        *reinterpret_cast<float4*>(out + (size_t)b * 1024 + d) = o;
    }
}

// ---------------------------------------------------------------------------
// Launch
// ---------------------------------------------------------------------------
extern "C" void kernel_launch(void* const* d_in, const int* in_sizes, int n_in,
                              void* d_out, int out_size)
{
    const float* feats[3] = { (const float*)d_in[0], (const float*)d_in[1], (const float*)d_in[2] };
    const float* Wm[3]    = { (const float*)d_in[3], (const float*)d_in[5], (const float*)d_in[7] };
    const float* bt   = (const float*)d_in[4];
    const float* ba   = (const float*)d_in[6];
    const float* bv   = (const float*)d_in[8];
    const float* Wl1  = (const float*)d_in[9];
    const float* Wr1  = (const float*)d_in[10];
    const float* att1 = (const float*)d_in[11];
    const float* b1   = (const float*)d_in[12];
    const float* Wl2  = (const float*)d_in[13];
    const float* Wr2  = (const float*)d_in[14];
    const float* att2 = (const float*)d_in[15];
    const float* b2   = (const float*)d_in[16];
    float* out = (float*)d_out;

    float *Wf, *bf;
    fp16 *gl1, *gr1, *gl2, *gr2;
    fp16 *WmH, *WmL, *WT1H, *WT1L, *WT2, *WfT, *feat16, *x1;
    cudaGetSymbolAddress((void**)&Wf,  g_Wf);
    cudaGetSymbolAddress((void**)&bf,  g_bf);
    cudaGetSymbolAddress((void**)&gl1, g_gl1);
    cudaGetSymbolAddress((void**)&gr1, g_gr1);
    cudaGetSymbolAddress((void**)&gl2, g_gl2);
    cudaGetSymbolAddress((void**)&gr2, g_gr2);
    cudaGetSymbolAddress((void**)&WmH,  g_WmH);
    cudaGetSymbolAddress((void**)&WmL,  g_WmL);
    cudaGetSymbolAddress((void**)&WT1H, g_WT1H);
    cudaGetSymbolAddress((void**)&WT1L, g_WT1L);
    cudaGetSymbolAddress((void**)&WT2,  g_WT2);
    cudaGetSymbolAddress((void**)&WfT,  g_WfT);
    cudaGetSymbolAddress((void**)&feat16, g_feat);
    cudaGetSymbolAddress((void**)&x1, g_x1);

    cudaFuncSetAttribute(gemm_1t,
                         cudaFuncAttributeMaxDynamicSharedMemorySize, SMEM_1T);
    cudaFuncSetAttribute(gemm_fold,
                         cudaFuncAttributeMaxDynamicSharedMemorySize, SMEM_FOLD);

    const size_t M1 = 1024 * 1024;
    const dim3 tB(32, 8);
    const dim3 tG(32, 32);

    const float S_FOLD = 1024.0f;   // fold pre-scale so fp16 lo stays normal

    // 1. weight splits / conversions
    splitT_fp16<<<tG, tB>>>(Wl1, WT1H, WT1L, S_FOLD);
    splitT_fp16<<<tG, tB>>>(Wr1, WT1H + M1, WT1L + M1, S_FOLD);
    convT_fp16<<<tG, tB>>>(Wl2, WT2);
    convT_fp16<<<tG, tB>>>(Wr2, WT2 + M1);
    for (int m = 0; m < 3; m++)
        split_fp16<<<1024, 256>>>(Wm[m], WmH + m * M1, WmL + m * M1,
                                  1024 * 1024, S_FOLD);

    // 2. fold (one batched launch over c=0..5)
    gemm_fold<<<dim3(8, 8, 6), 256, SMEM_FOLD>>>(WmH, WmL, WT1H, WT1L, Wf,
                                                 1.0f / (S_FOLD * S_FOLD));
    bias_fold_kernel<<<24, 256>>>(bt, ba, bv, Wl1, Wr1, bf);
    for (int c = 0; c < 6; c++)
        convT_fp16<<<tG, tB>>>(Wf + (size_t)c * M1, WfT + c * M1);

    // 3. feature conversion
    for (int m = 0; m < 3; m++)
        tofp16_kernel<<<BATCH, 256>>>(feats[m], feat16 + (size_t)m * BATCH * 1024,
                                      BATCH * 1024);

    // 4. layer-1 GEMMs (fp16 out, interleaved [B,3,H], ldc=3072)
    {
        dim3 grid(8, BATCH / 128);
        for (int m = 0; m < 3; m++) {
            const fp16* A = feat16 + (size_t)m * BATCH * 1024;
            gemm_1t<<<grid, 256, SMEM_1T>>>(BATCH, 1024, 1024,
                A, 1024, WfT + m * M1, 1024,
                gl1 + m * 1024, 3072, bf + m * 1024);
            gemm_1t<<<grid, 256, SMEM_1T>>>(BATCH, 1024, 1024,
                A, 1024, WfT + (3 + m) * M1, 1024,
                gr1 + m * 1024, 3072, bf + (3 + m) * 1024);
        }
    }

    // 5. GAT1 -> x1 (fp16)
    gat1_kernel<<<BATCH, 256>>>(gl1, gr1, att1, b1, x1);

    // 6. layer-2 GEMMs (fp16 out)
    {
        dim3 grid(8, (3 * BATCH) / 128);
        gemm_1t<<<grid, 256, SMEM_1T>>>(3 * BATCH, 1024, 1024,
            x1, 1024, WT2, 1024, gl2, 1024, nullptr);
        gemm_1t<<<grid, 256, SMEM_1T>>>(3 * BATCH, 1024, 1024,
            x1, 1024, WT2 + M1, 1024, gr2, 1024, nullptr);
    }

    // 7. GAT2 -> out
    gat2_kernel<<<BATCH / 8, 256>>>(gl2, gr2, att2, b2, out);
}

// round 8
// speedup vs baseline: 7.0237x; 1.0115x over previous
#include <cuda_runtime.h>
#include <cuda_fp16.h>
#include <cstdint>
#include <math.h>

// ---------------------------------------------------------------------------
// IntraSentenceGNN on GB300 (sm_103 base ISA): mma.sync fp16 GEMMs with
// ldmatrix fragment loads, 2 CTAs/SM, fp16 intermediates, and merged
// N=2048 gl/gr GEMMs (shared-A pairs computed in one launch).
//
//  1. split/transpose weights
//  2. fold: Wf[2m+side] = Wm[m] @ W{l|r}1 (one batched launch, 3-term hi/lo)
//  3. [gl1|gr1] = feat_m @ [Wfl_m|Wfr_m] + bf   (3 launches, N=2048)
//  4. GAT1 attention + ELU -> x1 (fp16)
//  5. [gl2|gr2] = x1 @ [Wl2|Wr2]                (1 launch, N=2048)
//  6. GAT2 attention + mean-pool -> out (fp32)
// ---------------------------------------------------------------------------

#define BATCH 32768
#define HDIM  1024

typedef __half fp16;

// ------------------------------ scratch -----------------------------------
__device__ __align__(256) float g_Wf [6 * 1024 * 1024];
__device__ __align__(256) float g_bf [6 * 1024];
__device__ __align__(256) fp16 g_gl1[BATCH * 3 * HDIM];
__device__ __align__(256) fp16 g_gr1[BATCH * 3 * HDIM];
__device__ __align__(256) fp16 g_gl2[BATCH * 3 * HDIM];
__device__ __align__(256) fp16 g_gr2[BATCH * 3 * HDIM];

__device__ __align__(256) fp16 g_WmH [3 * 1024 * 1024];
__device__ __align__(256) fp16 g_WmL [3 * 1024 * 1024];
__device__ __align__(256) fp16 g_WT1H[2 * 1024 * 1024];
__device__ __align__(256) fp16 g_WT1L[2 * 1024 * 1024];
__device__ __align__(256) fp16 g_WT2 [2 * 1024 * 1024];   // [Wl2^T | Wr2^T] = [2048,1024]
__device__ __align__(256) fp16 g_WfT [6 * 1024 * 1024];   // c = 2m+side ordering
__device__ __align__(256) fp16 g_feat[3 * BATCH * 1024];
__device__ __align__(256) fp16 g_x1  [BATCH * 3 * 1024];

// --------------------------- PTX helpers ----------------------------------
__device__ __forceinline__ uint32_t smem_u32(const void* p) {
    uint32_t a;
    asm("{ .reg .u64 t; cvta.to.shared.u64 t, %1; cvt.u32.u64 %0, t; }"
        : "=r"(a) : "l"(p));
    return a;
}
__device__ __forceinline__ void cp16(uint32_t sdst, const void* gsrc) {
    asm volatile("cp.async.cg.shared.global [%0], [%1], 16;" :: "r"(sdst), "l"(gsrc));
}
__device__ __forceinline__ void cp_commit() {
    asm volatile("cp.async.commit_group;" ::: "memory");
}
__device__ __forceinline__ void cp_wait1() {
    asm volatile("cp.async.wait_group 1;" ::: "memory");
}
__device__ __forceinline__ void cp_wait0() {
    asm volatile("cp.async.wait_group 0;" ::: "memory");
}

// SW128-swizzled byte address within a 128B-row tile
__device__ __forceinline__ uint32_t sw_addr(uint32_t base, int row, int colb) {
    uint32_t off = (uint32_t)(row * 128 + colb);
    return base + (off ^ ((off >> 3) & 0x70));
}

__device__ __forceinline__ void ldsm4(uint32_t addr, uint32_t* r) {
    asm volatile("ldmatrix.sync.aligned.m8n8.x4.shared.b16 {%0,%1,%2,%3}, [%4];"
        : "=r"(r[0]), "=r"(r[1]), "=r"(r[2]), "=r"(r[3]) : "r"(addr));
}

__device__ __forceinline__ void mma16816(float* c, const uint32_t* a, const uint32_t* b) {
    asm volatile(
        "mma.sync.aligned.m16n8k16.row.col.f32.f16.f16.f32 "
        "{%0,%1,%2,%3}, {%4,%5,%6,%7}, {%8,%9}, {%0,%1,%2,%3};"
        : "+f"(c[0]), "+f"(c[1]), "+f"(c[2]), "+f"(c[3])
        : "r"(a[0]), "r"(a[1]), "r"(a[2]), "r"(a[3]), "r"(b[0]), "r"(b[1]));
}

// load one 128x64 fp16 subtile (swizzled) via cp.async, 256 threads
__device__ __forceinline__ void load_sub(const fp16* src, int blk, int ld,
                                         uint32_t rb, int kofs, int tid) {
    #pragma unroll
    for (int i = 0; i < 4; i++) {
        const int c = tid + i * 256;
        const int row = c >> 3, kc = c & 7;
        const void* g = src + (size_t)(blk + row) * ld + kofs + kc * 8;
        uint32_t off = (uint32_t)(row * 128 + kc * 16);
        off ^= (off >> 3) & 0x70;
        cp16(rb + off, g);
    }
}

// ---------------------------------------------------------------------------
// 1-term fp16 GEMM over [M,2048]: col<1024 -> Cl, col>=1024 -> Cr.
// CTA 128x128, BK=64, 3-stage cp.async, 8 warps (4m x 2n), 2 CTAs/SM.
// B is [2048, K] K-major (two stacked 1024-row weight blocks).
// ---------------------------------------------------------------------------
#define SMEM_1T (3 * 32768)

__global__ __launch_bounds__(256, 2) void gemm_1t(
    int M, int K,
    const fp16* __restrict__ A, int lda,
    const fp16* __restrict__ B, int ldb,
    fp16* __restrict__ Cl, fp16* __restrict__ Cr, int ldc,
    const float* __restrict__ biasL, const float* __restrict__ biasR)
{
    extern __shared__ char smem[];
    const uint32_t sbase = smem_u32(smem);
    const int tid  = threadIdx.x;
    const int wid  = tid >> 5;
    const int lane = tid & 31;
    const int warp_m = wid & 3;
    const int warp_n = wid >> 2;

    const int mblk = blockIdx.y * 128;
    const int nblk = blockIdx.x * 128;            // 0..1920 over N=2048
    const int side = nblk >> 10;                  // 0: l, 1: r
    fp16* C = side ? Cr : Cl;
    const float* bias = side ? biasR : biasL;
    const int colbase = nblk & 1023;
    const int KT = K >> 6;

    auto load_tile = [&](int kt, int s) {
        const uint32_t st = sbase + s * 32768;
        load_sub(A, mblk, lda, st,         kt * 64, tid);
        load_sub(B, nblk, ldb, st + 16384, kt * 64, tid);
        cp_commit();
    };

    float acc[2][8][4];
    #pragma unroll
    for (int mt = 0; mt < 2; mt++)
        #pragma unroll
        for (int nt = 0; nt < 8; nt++)
            #pragma unroll
            for (int q = 0; q < 4; q++) acc[mt][nt][q] = 0.0f;

    load_tile(0, 0);
    load_tile(1, 1);

    const int qa_r = ((lane >> 3) & 1) * 8 + (lane & 7);
    const int qa_c = (lane >> 4) * 16;
    const int qb_r = (lane >> 4) * 8 + (lane & 7);
    const int qb_c = ((lane >> 3) & 1) * 16;

    for (int kt = 0; kt < KT; kt++) {
        if (kt + 1 < KT) cp_wait1(); else cp_wait0();
        __syncthreads();

        const uint32_t st = sbase + (kt % 3) * 32768;
        const uint32_t sA = st, sB = st + 16384;

        #pragma unroll
        for (int ks = 0; ks < 4; ks++) {
            uint32_t afr[2][4];
            #pragma unroll
            for (int mt = 0; mt < 2; mt++)
                ldsm4(sw_addr(sA, warp_m * 32 + mt * 16 + qa_r, ks * 32 + qa_c), afr[mt]);
            uint32_t bfr[8][2];
            #pragma unroll
            for (int p = 0; p < 4; p++) {
                uint32_t r[4];
                ldsm4(sw_addr(sB, warp_n * 64 + p * 16 + qb_r, ks * 32 + qb_c), r);
                bfr[2*p][0] = r[0]; bfr[2*p][1] = r[1];
                bfr[2*p+1][0] = r[2]; bfr[2*p+1][1] = r[3];
            }
            #pragma unroll
            for (int mt = 0; mt < 2; mt++)
                #pragma unroll
                for (int nt = 0; nt < 8; nt++)
                    mma16816(acc[mt][nt], afr[mt], bfr[nt]);
        }
        __syncthreads();
        if (kt + 2 < KT) load_tile(kt + 2, (kt + 2) % 3);
    }

    #pragma unroll
    for (int mt = 0; mt < 2; mt++) {
        const int row = mblk + warp_m * 32 + mt * 16 + (lane >> 2);
        #pragma unroll
        for (int nt = 0; nt < 8; nt++) {
            const int col = colbase + warp_n * 64 + nt * 8 + (lane & 3) * 2;
            float b0 = 0.0f, b1 = 0.0f;
            if (bias) { b0 = bias[col]; b1 = bias[col + 1]; }
            *reinterpret_cast<__half2*>(C + (size_t)row * ldc + col) =
                __floats2half2_rn(acc[mt][nt][0] + b0, acc[mt][nt][1] + b1);
            *reinterpret_cast<__half2*>(C + (size_t)(row + 8) * ldc + col) =
                __floats2half2_rn(acc[mt][nt][2] + b0, acc[mt][nt][3] + b1);
        }
    }
}

// ---------------------------------------------------------------------------
// Batched 3-term fold GEMM: c = blockIdx.z = 2m+side; Wf[c] = Wm[m] @ W{l|r}1.
// ---------------------------------------------------------------------------
#define SMEM_FOLD (3 * 65536)

__global__ __launch_bounds__(256, 1) void gemm_fold(
    const fp16* __restrict__ WmH, const fp16* __restrict__ WmL,
    const fp16* __restrict__ W1H, const fp16* __restrict__ W1L,
    float* __restrict__ Wf, float scale)
{
    const size_t M1 = 1024 * 1024;
    const int c = blockIdx.z;
    const int m = c >> 1, side = c & 1;
    const fp16* Ah = WmH + (size_t)m * M1;
    const fp16* Al = WmL + (size_t)m * M1;
    const fp16* Bh = W1H + (size_t)side * M1;
    const fp16* Bl = W1L + (size_t)side * M1;
    float* C = Wf + (size_t)c * M1;

    extern __shared__ char smem[];
    const uint32_t sbase = smem_u32(smem);
    const int tid  = threadIdx.x;
    const int wid  = tid >> 5;
    const int lane = tid & 31;
    const int warp_m = wid & 3;
    const int warp_n = wid >> 2;

    const int mblk = blockIdx.y * 128;
    const int nblk = blockIdx.x * 128;
    const int KT = 16;

    auto load_tile = [&](int kt, int s) {
        const uint32_t st = sbase + s * 65536;
        load_sub(Ah, mblk, 1024, st,         kt * 64, tid);
        load_sub(Al, mblk, 1024, st + 16384, kt * 64, tid);
        load_sub(Bh, nblk, 1024, st + 32768, kt * 64, tid);
        load_sub(Bl, nblk, 1024, st + 49152, kt * 64, tid);
        cp_commit();
    };

    float acc[2][8][4];
    #pragma unroll
    for (int mt = 0; mt < 2; mt++)
        #pragma unroll
        for (int nt = 0; nt < 8; nt++)
            #pragma unroll
            for (int q = 0; q < 4; q++) acc[mt][nt][q] = 0.0f;

    load_tile(0, 0);
    load_tile(1, 1);

    const int qa_r = ((lane >> 3) & 1) * 8 + (lane & 7);
    const int qa_c = (lane >> 4) * 16;
    const int qb_r = (lane >> 4) * 8 + (lane & 7);
    const int qb_c = ((lane >> 3) & 1) * 16;

    for (int kt = 0; kt < KT; kt++) {
        if (kt + 1 < KT) cp_wait1(); else cp_wait0();
        __syncthreads();

        const uint32_t st = sbase + (kt % 3) * 65536;
        const uint32_t sAh = st, sAl = st + 16384, sBh = st + 32768, sBl = st + 49152;

        #pragma unroll
        for (int ks = 0; ks < 4; ks++) {
            uint32_t afH[2][4], afL[2][4];
            #pragma unroll
            for (int mt = 0; mt < 2; mt++) {
                const int rr = warp_m * 32 + mt * 16 + qa_r;
                const int cc = ks * 32 + qa_c;
                ldsm4(sw_addr(sAh, rr, cc), afH[mt]);
                ldsm4(sw_addr(sAl, rr, cc), afL[mt]);
            }
            uint32_t bfH[8][2], bfL[8][2];
            #pragma unroll
            for (int p = 0; p < 4; p++) {
                const int rr = warp_n * 64 + p * 16 + qb_r;
                const int cc = ks * 32 + qb_c;
                uint32_t r[4];
                ldsm4(sw_addr(sBh, rr, cc), r);
                bfH[2*p][0] = r[0]; bfH[2*p][1] = r[1];
                bfH[2*p+1][0] = r[2]; bfH[2*p+1][1] = r[3];
                ldsm4(sw_addr(sBl, rr, cc), r);
                bfL[2*p][0] = r[0]; bfL[2*p][1] = r[1];
                bfL[2*p+1][0] = r[2]; bfL[2*p+1][1] = r[3];
            }
            #pragma unroll
            for (int mt = 0; mt < 2; mt++)
                #pragma unroll
                for (int nt = 0; nt < 8; nt++) {
                    mma16816(acc[mt][nt], afH[mt], bfH[nt]);
                    mma16816(acc[mt][nt], afH[mt], bfL[nt]);
                    mma16816(acc[mt][nt], afL[mt], bfH[nt]);
                }
        }
        __syncthreads();
        if (kt + 2 < KT) load_tile(kt + 2, (kt + 2) % 3);
    }

    #pragma unroll
    for (int mt = 0; mt < 2; mt++) {
        const int row = mblk + warp_m * 32 + mt * 16 + (lane >> 2);
        #pragma unroll
        for (int nt = 0; nt < 8; nt++) {
            const int col = nblk + warp_n * 64 + nt * 8 + (lane & 3) * 2;
            float2 v0 = make_float2(acc[mt][nt][0] * scale, acc[mt][nt][1] * scale);
            float2 v1 = make_float2(acc[mt][nt][2] * scale, acc[mt][nt][3] * scale);
            *reinterpret_cast<float2*>(C + (size_t)row * 1024 + col) = v0;
            *reinterpret_cast<float2*>(C + (size_t)(row + 8) * 1024 + col) = v1;
        }
    }
}

// ---------------------------------------------------------------------------
// conversions
// ---------------------------------------------------------------------------
__device__ __forceinline__ void split1(float x, fp16& h, fp16& l) {
    h = __float2half(x);
    l = __float2half(x - __half2float(h));
}

__global__ void split_fp16(const float* __restrict__ in,
                           fp16* __restrict__ hi, fp16* __restrict__ lo,
                           int n, float scale)
{
    int i = (blockIdx.x * blockDim.x + threadIdx.x) * 4;
    if (i >= n) return;
    float4 v = *reinterpret_cast<const float4*>(in + i);
    fp16 h[4], l[4];
    split1(v.x * scale, h[0], l[0]); split1(v.y * scale, h[1], l[1]);
    split1(v.z * scale, h[2], l[2]); split1(v.w * scale, h[3], l[3]);
    *reinterpret_cast<__half2*>(hi + i)     = __halves2half2(h[0], h[1]);
    *reinterpret_cast<__half2*>(hi + i + 2) = __halves2half2(h[2], h[3]);
    *reinterpret_cast<__half2*>(lo + i)     = __halves2half2(l[0], l[1]);
    *reinterpret_cast<__half2*>(lo + i + 2) = __halves2half2(l[2], l[3]);
}

__global__ void splitT_fp16(const float* __restrict__ in,
                            fp16* __restrict__ hi, fp16* __restrict__ lo,
                            float scale)
{
    __shared__ float t[32][33];
    const int x0 = blockIdx.x * 32, y0 = blockIdx.y * 32;
    const int tx = threadIdx.x, ty = threadIdx.y;
    #pragma unroll
    for (int r = ty; r < 32; r += 8)
        t[r][tx] = in[(size_t)(y0 + r) * 1024 + x0 + tx];
    __syncthreads();
    #pragma unroll
    for (int r = ty; r < 32; r += 8) {
        float v = t[tx][r] * scale;
        fp16 h, l;
        split1(v, h, l);
        hi[(size_t)(x0 + r) * 1024 + y0 + tx] = h;
        lo[(size_t)(x0 + r) * 1024 + y0 + tx] = l;
    }
}

// batched fp32 [1024,1024] -> transposed fp16, z matrices (in/out offset z*M1)
__global__ void convT_fp16(const float* __restrict__ in, fp16* __restrict__ outT)
{
    const size_t zo = (size_t)blockIdx.z * 1024 * 1024;
    __shared__ float t[32][33];
    const int x0 = blockIdx.x * 32, y0 = blockIdx.y * 32;
    const int tx = threadIdx.x, ty = threadIdx.y;
    #pragma unroll
    for (int r = ty; r < 32; r += 8)
        t[r][tx] = in[zo + (size_t)(y0 + r) * 1024 + x0 + tx];
    __syncthreads();
    #pragma unroll
    for (int r = ty; r < 32; r += 8)
        outT[zo + (size_t)(x0 + r) * 1024 + y0 + tx] = __float2half(t[tx][r]);
}

__global__ void tofp16_kernel(const float* __restrict__ in,
                              fp16* __restrict__ out, int n)
{
    int i = (blockIdx.x * blockDim.x + threadIdx.x) * 4;
    if (i >= n) return;
    float4 v = *reinterpret_cast<const float4*>(in + i);
    *reinterpret_cast<__half2*>(out + i)     = __floats2half2_rn(v.x, v.y);
    *reinterpret_cast<__half2*>(out + i + 2) = __floats2half2_rn(v.z, v.w);
}

__global__ void bias_fold_kernel(
    const float* __restrict__ bt, const float* __restrict__ ba,
    const float* __restrict__ bv,
    const float* __restrict__ Wl1, const float* __restrict__ Wr1,
    float* __restrict__ bf)
{
    int g = blockIdx.x * blockDim.x + threadIdx.x;
    if (g >= 6 * 1024) return;
    int combo = g >> 10;
    int j = g & 1023;
    int m = combo % 3;
    const float* bvec = (m == 0) ? bt : (m == 1) ? ba : bv;
    const float* W = (combo < 3) ? Wl1 : Wr1;
    float s = 0.0f;
    for (int k = 0; k < 1024; k++) s += bvec[k] * W[k * 1024 + j];
    bf[g] = s;
}

// ---------------------------------------------------------------------------
// attention kernels (fp16 inputs)
// ---------------------------------------------------------------------------
__device__ __forceinline__ float lrelu02(float x) { return x > 0.0f ? x : 0.2f * x; }

__device__ __forceinline__ float4 ld4h(const fp16* p) {
    uint2 u = *reinterpret_cast<const uint2*>(p);
    float2 f01 = __half22float2(*reinterpret_cast<__half2*>(&u.x));
    float2 f23 = __half22float2(*reinterpret_cast<__half2*>(&u.y));
    return make_float4(f01.x, f01.y, f23.x, f23.y);
}

__global__ __launch_bounds__(256) void gat1_kernel(
    const fp16* __restrict__ gl, const fp16* __restrict__ gr,
    const float* __restrict__ att, const float* __restrict__ b1,
    fp16* __restrict__ x1)
{
    const int b = blockIdx.x;
    const int h = threadIdx.x >> 5;
    const int lane = threadIdx.x & 31;
    const int dbase = lane * 4;

    const size_t base = (size_t)b * 3072 + h * 128 + dbase;
    float4 glv[3], grv[3];
    #pragma unroll
    for (int j = 0; j < 3; j++) glv[j] = ld4h(gl + base + j * 1024);
    #pragma unroll
    for (int i = 0; i < 3; i++) grv[i] = ld4h(gr + base + i * 1024);
    const float4 av = *reinterpret_cast<const float4*>(att + h * 128 + dbase);

    float e[3][3];
    #pragma unroll
    for (int i = 0; i < 3; i++)
        #pragma unroll
        for (int j = 0; j < 3; j++) {
            float s = av.x * lrelu02(glv[j].x + grv[i].x);
            s += av.y * lrelu02(glv[j].y + grv[i].y);
            s += av.z * lrelu02(glv[j].z + grv[i].z);
            s += av.w * lrelu02(glv[j].w + grv[i].w);
            e[i][j] = s;
        }
    #pragma unroll
    for (int i = 0; i < 3; i++)
        #pragma unroll
        for (int j = 0; j < 3; j++)
            #pragma unroll
            for (int o = 16; o > 0; o >>= 1)
                e[i][j] += __shfl_xor_sync(0xFFFFFFFFu, e[i][j], o);

    float alpha[3][3];
    #pragma unroll
    for (int i = 0; i < 3; i++) {
        float mx = fmaxf(e[i][0], fmaxf(e[i][1], e[i][2]));
        float p0 = expf(e[i][0] - mx);
        float p1 = expf(e[i][1] - mx);
        float p2 = expf(e[i][2] - mx);
        float inv = 1.0f / (p0 + p1 + p2);
        alpha[i][0] = p0 * inv; alpha[i][1] = p1 * inv; alpha[i][2] = p2 * inv;
    }

    const float4 bb = *reinterpret_cast<const float4*>(b1 + h * 128 + dbase);
    #pragma unroll
    for (int i = 0; i < 3; i++) {
        float o[4];
        o[0] = alpha[i][0]*glv[0].x + alpha[i][1]*glv[1].x + alpha[i][2]*glv[2].x + bb.x;
        o[1] = alpha[i][0]*glv[0].y + alpha[i][1]*glv[1].y + alpha[i][2]*glv[2].y + bb.y;
        o[2] = alpha[i][0]*glv[0].z + alpha[i][1]*glv[1].z + alpha[i][2]*glv[2].z + bb.z;
        o[3] = alpha[i][0]*glv[0].w + alpha[i][1]*glv[1].w + alpha[i][2]*glv[2].w + bb.w;
        #pragma unroll
        for (int q = 0; q < 4; q++)
            o[q] = o[q] > 0.0f ? o[q] : (expf(o[q]) - 1.0f);
        const size_t idx = (size_t)b * 3072 + i * 1024 + h * 128 + dbase;
        *reinterpret_cast<__half2*>(x1 + idx)     = __floats2half2_rn(o[0], o[1]);
        *reinterpret_cast<__half2*>(x1 + idx + 2) = __floats2half2_rn(o[2], o[3]);
    }
}

__global__ __launch_bounds__(256) void gat2_kernel(
    const fp16* __restrict__ gl, const fp16* __restrict__ gr,
    const float* __restrict__ att, const float* __restrict__ b2,
    float* __restrict__ out)
{
    const int b = blockIdx.x * 8 + (threadIdx.x >> 5);
    const int lane = threadIdx.x & 31;
    const fp16* glb = gl + (size_t)b * 3072;
    const fp16* grb = gr + (size_t)b * 3072;

    float e[9] = {0,0,0,0,0,0,0,0,0};
    #pragma unroll
    for (int c = 0; c < 8; c++) {
        const int d = c * 128 + lane * 4;
        const float4 av = *reinterpret_cast<const float4*>(att + d);
        float4 glv[3], grv[3];
        #pragma unroll
        for (int j = 0; j < 3; j++) glv[j] = ld4h(glb + j * 1024 + d);
        #pragma unroll
        for (int i = 0; i < 3; i++) grv[i] = ld4h(grb + i * 1024 + d);
        #pragma unroll
        for (int i = 0; i < 3; i++)
            #pragma unroll
            for (int j = 0; j < 3; j++) {
                float s = av.x * lrelu02(glv[j].x + grv[i].x);
                s += av.y * lrelu02(glv[j].y + grv[i].y);
                s += av.z * lrelu02(glv[j].z + grv[i].z);
                s += av.w * lrelu02(glv[j].w + grv[i].w);
                e[i * 3 + j] += s;
            }
    }
    #pragma unroll
    for (int k = 0; k < 9; k++)
        #pragma unroll
        for (int o = 16; o > 0; o >>= 1)
            e[k] += __shfl_xor_sync(0xFFFFFFFFu, e[k], o);

    float w[3] = {0.0f, 0.0f, 0.0f};
    #pragma unroll
    for (int i = 0; i < 3; i++) {
        float mx = fmaxf(e[i*3+0], fmaxf(e[i*3+1], e[i*3+2]));
        float p0 = expf(e[i*3+0] - mx);
        float p1 = expf(e[i*3+1] - mx);
        float p2 = expf(e[i*3+2] - mx);
        float inv = 1.0f / (p0 + p1 + p2);
        w[0] += p0 * inv; w[1] += p1 * inv; w[2] += p2 * inv;
    }
    w[0] *= (1.0f/3.0f); w[1] *= (1.0f/3.0f); w[2] *= (1.0f/3.0f);

    #pragma unroll
    for (int c = 0; c < 8; c++) {
        const int d = c * 128 + lane * 4;
        const float4 bv = *reinterpret_cast<const float4*>(b2 + d);
        float4 g0 = ld4h(glb + 0 * 1024 + d);
        float4 g1 = ld4h(glb + 1 * 1024 + d);
        float4 g2 = ld4h(glb + 2 * 1024 + d);
        float4 o;
        o.x = w[0]*g0.x + w[1]*g1.x + w[2]*g2.x + bv.x;
        o.y = w[0]*g0.y + w[1]*g1.y + w[2]*g2.y + bv.y;
        o.z = w[0]*g0.z + w[1]*g1.z + w[2]*g2.z + bv.z;
        o.w = w[0]*g0.w + w[1]*g1.w + w[2]*g2.w + bv.w;
        *reinterpret_cast<float4*>(out + (size_t)b * 1024 + d) = o;
    }
}

// ---------------------------------------------------------------------------
// Launch
// ---------------------------------------------------------------------------
extern "C" void kernel_launch(void* const* d_in, const int* in_sizes, int n_in,
                              void* d_out, int out_size)
{
    const float* feats[3] = { (const float*)d_in[0], (const float*)d_in[1], (const float*)d_in[2] };
    const float* Wm[3]    = { (const float*)d_in[3], (const float*)d_in[5], (const float*)d_in[7] };
    const float* bt   = (const float*)d_in[4];
    const float* ba   = (const float*)d_in[6];
    const float* bv   = (const float*)d_in[8];
    const float* Wl1  = (const float*)d_in[9];
    const float* Wr1  = (const float*)d_in[10];
    const float* att1 = (const float*)d_in[11];
    const float* b1   = (const float*)d_in[12];
    const float* Wl2  = (const float*)d_in[13];
    const float* Wr2  = (const float*)d_in[14];
    const float* att2 = (const float*)d_in[15];
    const float* b2   = (const float*)d_in[16];
    float* out = (float*)d_out;

    float *Wf, *bf;
    fp16 *gl1, *gr1, *gl2, *gr2;
    fp16 *WmH, *WmL, *WT1H, *WT1L, *WT2, *WfT, *feat16, *x1;
    cudaGetSymbolAddress((void**)&Wf,  g_Wf);
    cudaGetSymbolAddress((void**)&bf,  g_bf);
    cudaGetSymbolAddress((void**)&gl1, g_gl1);
    cudaGetSymbolAddress((void**)&gr1, g_gr1);
    cudaGetSymbolAddress((void**)&gl2, g_gl2);
    cudaGetSymbolAddress((void**)&gr2, g_gr2);
    cudaGetSymbolAddress((void**)&WmH,  g_WmH);
    cudaGetSymbolAddress((void**)&WmL,  g_WmL);
    cudaGetSymbolAddress((void**)&WT1H, g_WT1H);
    cudaGetSymbolAddress((void**)&WT1L, g_WT1L);
    cudaGetSymbolAddress((void**)&WT2,  g_WT2);
    cudaGetSymbolAddress((void**)&WfT,  g_WfT);
    cudaGetSymbolAddress((void**)&feat16, g_feat);
    cudaGetSymbolAddress((void**)&x1, g_x1);

    cudaFuncSetAttribute(gemm_1t,
                         cudaFuncAttributeMaxDynamicSharedMemorySize, SMEM_1T);
    cudaFuncSetAttribute(gemm_fold,
                         cudaFuncAttributeMaxDynamicSharedMemorySize, SMEM_FOLD);

    const size_t M1 = 1024 * 1024;
    const dim3 tB(32, 8);
    const dim3 tG(32, 32);

    const float S_FOLD = 1024.0f;   // fold pre-scale so fp16 lo stays normal

    // 1. weight splits / conversions
    splitT_fp16<<<tG, tB>>>(Wl1, WT1H, WT1L, S_FOLD);
    splitT_fp16<<<tG, tB>>>(Wr1, WT1H + M1, WT1L + M1, S_FOLD);
    convT_fp16<<<tG, tB>>>(Wl2, WT2);
    convT_fp16<<<tG, tB>>>(Wr2, WT2 + M1);
    for (int m = 0; m < 3; m++)
        split_fp16<<<1024, 256>>>(Wm[m], WmH + m * M1, WmL + m * M1,
                                  1024 * 1024, S_FOLD);

    // 2. fold (batched, c = 2m+side ordering)
    gemm_fold<<<dim3(8, 8, 6), 256, SMEM_FOLD>>>(WmH, WmL, WT1H, WT1L, Wf,
                                                 1.0f / (S_FOLD * S_FOLD));
    bias_fold_kernel<<<24, 256>>>(bt, ba, bv, Wl1, Wr1, bf);
    convT_fp16<<<dim3(32, 32, 6), tB>>>(Wf, WfT);   // batched transpose-convert

    // 3. feature conversion
    for (int m = 0; m < 3; m++)
        tofp16_kernel<<<BATCH, 256>>>(feats[m], feat16 + (size_t)m * BATCH * 1024,
                                      BATCH * 1024);

    // 4. layer-1 merged GEMMs: [gl1|gr1] = feat_m @ [Wfl_m|Wfr_m] + bf
    {
        dim3 grid(16, BATCH / 128);
        for (int m = 0; m < 3; m++) {
            gemm_1t<<<grid, 256, SMEM_1T>>>(BATCH, 1024,
                feat16 + (size_t)m * BATCH * 1024, 1024,
                WfT + (size_t)(2 * m) * M1, 1024,
                gl1 + m * 1024, gr1 + m * 1024, 3072,
                bf + m * 1024, bf + (3 + m) * 1024);
        }
    }

    // 5. GAT1 -> x1 (fp16)
    gat1_kernel<<<BATCH, 256>>>(gl1, gr1, att1, b1, x1);

    // 6. layer-2 merged GEMM: [gl2|gr2] = x1 @ [Wl2|Wr2]
    {
        dim3 grid(16, (3 * BATCH) / 128);
        gemm_1t<<<grid, 256, SMEM_1T>>>(3 * BATCH, 1024,
            x1, 1024, WT2, 1024, gl2, gr2, 1024, nullptr, nullptr);
    }

    // 7. GAT2 -> out
    gat2_kernel<<<BATCH / 8, 256>>>(gl2, gr2, att2, b2, out);
}

// round 9
// speedup vs baseline: 7.1857x; 1.0231x over previous
#include <cuda_runtime.h>
#include <cuda_fp16.h>
#include <cstdint>
#include <math.h>

// ---------------------------------------------------------------------------
// IntraSentenceGNN on GB300 (sm_103 base ISA): mma.sync fp16 GEMMs with
// ldmatrix fragment loads, 2 CTAs/SM, single-sync mainloop, batched grid.z
// launches, fp16 intermediates, __expf attention.
// ---------------------------------------------------------------------------

#define BATCH 32768
#define HDIM  1024

typedef __half fp16;

// ------------------------------ scratch -----------------------------------
__device__ __align__(256) float g_Wf [6 * 1024 * 1024];
__device__ __align__(256) float g_bf [6 * 1024];
__device__ __align__(256) fp16 g_gl1[BATCH * 3 * HDIM];
__device__ __align__(256) fp16 g_gr1[BATCH * 3 * HDIM];
__device__ __align__(256) fp16 g_gl2[BATCH * 3 * HDIM];
__device__ __align__(256) fp16 g_gr2[BATCH * 3 * HDIM];

__device__ __align__(256) fp16 g_WmH [3 * 1024 * 1024];
__device__ __align__(256) fp16 g_WmL [3 * 1024 * 1024];
__device__ __align__(256) fp16 g_WT1H[2 * 1024 * 1024];
__device__ __align__(256) fp16 g_WT1L[2 * 1024 * 1024];
__device__ __align__(256) fp16 g_WT2 [2 * 1024 * 1024];   // [Wl2^T | Wr2^T]
__device__ __align__(256) fp16 g_WfT [6 * 1024 * 1024];   // c = 2m+side
__device__ __align__(256) fp16 g_feat[3 * BATCH * 1024];
__device__ __align__(256) fp16 g_x1  [BATCH * 3 * 1024];

// --------------------------- PTX helpers ----------------------------------
__device__ __forceinline__ uint32_t smem_u32(const void* p) {
    uint32_t a;
    asm("{ .reg .u64 t; cvta.to.shared.u64 t, %1; cvt.u32.u64 %0, t; }"
        : "=r"(a) : "l"(p));
    return a;
}
__device__ __forceinline__ void cp16(uint32_t sdst, const void* gsrc) {
    asm volatile("cp.async.cg.shared.global [%0], [%1], 16;" :: "r"(sdst), "l"(gsrc));
}
__device__ __forceinline__ void cp_commit() {
    asm volatile("cp.async.commit_group;" ::: "memory");
}
__device__ __forceinline__ void cp_wait1() {
    asm volatile("cp.async.wait_group 1;" ::: "memory");
}
__device__ __forceinline__ void cp_wait0() {
    asm volatile("cp.async.wait_group 0;" ::: "memory");
}

__device__ __forceinline__ uint32_t sw_addr(uint32_t base, int row, int colb) {
    uint32_t off = (uint32_t)(row * 128 + colb);
    return base + (off ^ ((off >> 3) & 0x70));
}

__device__ __forceinline__ void ldsm4(uint32_t addr, uint32_t* r) {
    asm volatile("ldmatrix.sync.aligned.m8n8.x4.shared.b16 {%0,%1,%2,%3}, [%4];"
        : "=r"(r[0]), "=r"(r[1]), "=r"(r[2]), "=r"(r[3]) : "r"(addr));
}

__device__ __forceinline__ void mma16816(float* c, const uint32_t* a, const uint32_t* b) {
    asm volatile(
        "mma.sync.aligned.m16n8k16.row.col.f32.f16.f16.f32 "
        "{%0,%1,%2,%3}, {%4,%5,%6,%7}, {%8,%9}, {%0,%1,%2,%3};"
        : "+f"(c[0]), "+f"(c[1]), "+f"(c[2]), "+f"(c[3])
        : "r"(a[0]), "r"(a[1]), "r"(a[2]), "r"(a[3]), "r"(b[0]), "r"(b[1]));
}

__device__ __forceinline__ void load_sub(const fp16* src, int blk, int ld,
                                         uint32_t rb, int kofs, int tid) {
    #pragma unroll
    for (int i = 0; i < 4; i++) {
        const int c = tid + i * 256;
        const int row = c >> 3, kc = c & 7;
        const void* g = src + (size_t)(blk + row) * ld + kofs + kc * 8;
        uint32_t off = (uint32_t)(row * 128 + kc * 16);
        off ^= (off >> 3) & 0x70;
        cp16(rb + off, g);
    }
}

// ---------------------------------------------------------------------------
// 1-term fp16 GEMM over [M,2048] with grid.z batching:
//   z selects A += z*aZ, B += z*bZ, C += z*cZ, bias += z*biasZ.
//   col<1024 -> Cl, col>=1024 -> Cr. Single __syncthreads per k-tile.
// ---------------------------------------------------------------------------
#define SMEM_1T (3 * 32768)

__global__ __launch_bounds__(256, 2) void gemm_1t(
    int M, int K,
    const fp16* __restrict__ A, int lda, size_t aZ,
    const fp16* __restrict__ B, int ldb, size_t bZ,
    fp16* __restrict__ Cl, fp16* __restrict__ Cr, int ldc, size_t cZ,
    const float* __restrict__ biasL, const float* __restrict__ biasR, int biasZ)
{
    const int z = blockIdx.z;
    A += (size_t)z * aZ;
    B += (size_t)z * bZ;
    Cl += (size_t)z * cZ;
    Cr += (size_t)z * cZ;
    if (biasL) { biasL += (size_t)z * biasZ; biasR += (size_t)z * biasZ; }

    extern __shared__ char smem[];
    const uint32_t sbase = smem_u32(smem);
    const int tid  = threadIdx.x;
    const int wid  = tid >> 5;
    const int lane = tid & 31;
    const int warp_m = wid & 3;
    const int warp_n = wid >> 2;

    const int mblk = blockIdx.y * 128;
    const int nblk = blockIdx.x * 128;
    const int side = nblk >> 10;
    fp16* C = side ? Cr : Cl;
    const float* bias = side ? biasR : biasL;
    const int colbase = nblk & 1023;
    const int KT = K >> 6;

    auto load_tile = [&](int kt, int s) {
        const uint32_t st = sbase + s * 32768;
        load_sub(A, mblk, lda, st,         kt * 64, tid);
        load_sub(B, nblk, ldb, st + 16384, kt * 64, tid);
        cp_commit();
    };

    float acc[2][8][4];
    #pragma unroll
    for (int mt = 0; mt < 2; mt++)
        #pragma unroll
        for (int nt = 0; nt < 8; nt++)
            #pragma unroll
            for (int q = 0; q < 4; q++) acc[mt][nt][q] = 0.0f;

    load_tile(0, 0);
    load_tile(1, 1);

    const int qa_r = ((lane >> 3) & 1) * 8 + (lane & 7);
    const int qa_c = (lane >> 4) * 16;
    const int qb_r = (lane >> 4) * 8 + (lane & 7);
    const int qb_c = ((lane >> 3) & 1) * 16;

    for (int kt = 0; kt < KT; kt++) {
        if (kt + 1 < KT) cp_wait1(); else cp_wait0();
        __syncthreads();            // single sync per k-tile (see R9 notes)

        const uint32_t st = sbase + (kt % 3) * 32768;
        const uint32_t sA = st, sB = st + 16384;

        #pragma unroll
        for (int ks = 0; ks < 4; ks++) {
            uint32_t afr[2][4];
            #pragma unroll
            for (int mt = 0; mt < 2; mt++)
                ldsm4(sw_addr(sA, warp_m * 32 + mt * 16 + qa_r, ks * 32 + qa_c), afr[mt]);
            uint32_t bfr[8][2];
            #pragma unroll
            for (int p = 0; p < 4; p++) {
                uint32_t r[4];
                ldsm4(sw_addr(sB, warp_n * 64 + p * 16 + qb_r, ks * 32 + qb_c), r);
                bfr[2*p][0] = r[0]; bfr[2*p][1] = r[1];
                bfr[2*p+1][0] = r[2]; bfr[2*p+1][1] = r[3];
            }
            #pragma unroll
            for (int mt = 0; mt < 2; mt++)
                #pragma unroll
                for (int nt = 0; nt < 8; nt++)
                    mma16816(acc[mt][nt], afr[mt], bfr[nt]);
        }
        // loads for stage (kt+2)%3 == (kt-1)%3: all reads of that stage
        // completed in compute(kt-1), ordered by this iteration's sync.
        if (kt + 2 < KT) load_tile(kt + 2, (kt + 2) % 3);
    }

    #pragma unroll
    for (int mt = 0; mt < 2; mt++) {
        const int row = mblk + warp_m * 32 + mt * 16 + (lane >> 2);
        #pragma unroll
        for (int nt = 0; nt < 8; nt++) {
            const int col = colbase + warp_n * 64 + nt * 8 + (lane & 3) * 2;
            float b0 = 0.0f, b1 = 0.0f;
            if (bias) { b0 = bias[col]; b1 = bias[col + 1]; }
            *reinterpret_cast<__half2*>(C + (size_t)row * ldc + col) =
                __floats2half2_rn(acc[mt][nt][0] + b0, acc[mt][nt][1] + b1);
            *reinterpret_cast<__half2*>(C + (size_t)(row + 8) * ldc + col) =
                __floats2half2_rn(acc[mt][nt][2] + b0, acc[mt][nt][3] + b1);
        }
    }
}

// ---------------------------------------------------------------------------
// Batched 3-term fold GEMM: c = blockIdx.z = 2m+side; Wf[c] = Wm[m] @ W{l|r}1.
// ---------------------------------------------------------------------------
#define SMEM_FOLD (3 * 65536)

__global__ __launch_bounds__(256, 1) void gemm_fold(
    const fp16* __restrict__ WmH, const fp16* __restrict__ WmL,
    const fp16* __restrict__ W1H, const fp16* __restrict__ W1L,
    float* __restrict__ Wf, float scale)
{
    const size_t M1 = 1024 * 1024;
    const int c = blockIdx.z;
    const int m = c >> 1, side = c & 1;
    const fp16* Ah = WmH + (size_t)m * M1;
    const fp16* Al = WmL + (size_t)m * M1;
    const fp16* Bh = W1H + (size_t)side * M1;
    const fp16* Bl = W1L + (size_t)side * M1;
    float* C = Wf + (size_t)c * M1;

    extern __shared__ char smem[];
    const uint32_t sbase = smem_u32(smem);
    const int tid  = threadIdx.x;
    const int wid  = tid >> 5;
    const int lane = tid & 31;
    const int warp_m = wid & 3;
    const int warp_n = wid >> 2;

    const int mblk = blockIdx.y * 128;
    const int nblk = blockIdx.x * 128;
    const int KT = 16;

    auto load_tile = [&](int kt, int s) {
        const uint32_t st = sbase + s * 65536;
        load_sub(Ah, mblk, 1024, st,         kt * 64, tid);
        load_sub(Al, mblk, 1024, st + 16384, kt * 64, tid);
        load_sub(Bh, nblk, 1024, st + 32768, kt * 64, tid);
        load_sub(Bl, nblk, 1024, st + 49152, kt * 64, tid);
        cp_commit();
    };

    float acc[2][8][4];
    #pragma unroll
    for (int mt = 0; mt < 2; mt++)
        #pragma unroll
        for (int nt = 0; nt < 8; nt++)
            #pragma unroll
            for (int q = 0; q < 4; q++) acc[mt][nt][q] = 0.0f;

    load_tile(0, 0);
    load_tile(1, 1);

    const int qa_r = ((lane >> 3) & 1) * 8 + (lane & 7);
    const int qa_c = (lane >> 4) * 16;
    const int qb_r = (lane >> 4) * 8 + (lane & 7);
    const int qb_c = ((lane >> 3) & 1) * 16;

    for (int kt = 0; kt < KT; kt++) {
        if (kt + 1 < KT) cp_wait1(); else cp_wait0();
        __syncthreads();

        const uint32_t st = sbase + (kt % 3) * 65536;
        const uint32_t sAh = st, sAl = st + 16384, sBh = st + 32768, sBl = st + 49152;

        #pragma unroll
        for (int ks = 0; ks < 4; ks++) {
            uint32_t afH[2][4], afL[2][4];
            #pragma unroll
            for (int mt = 0; mt < 2; mt++) {
                const int rr = warp_m * 32 + mt * 16 + qa_r;
                const int cc = ks * 32 + qa_c;
                ldsm4(sw_addr(sAh, rr, cc), afH[mt]);
                ldsm4(sw_addr(sAl, rr, cc), afL[mt]);
            }
            uint32_t bfH[8][2], bfL[8][2];
            #pragma unroll
            for (int p = 0; p < 4; p++) {
                const int rr = warp_n * 64 + p * 16 + qb_r;
                const int cc = ks * 32 + qb_c;
                uint32_t r[4];
                ldsm4(sw_addr(sBh, rr, cc), r);
                bfH[2*p][0] = r[0]; bfH[2*p][1] = r[1];
                bfH[2*p+1][0] = r[2]; bfH[2*p+1][1] = r[3];
                ldsm4(sw_addr(sBl, rr, cc), r);
                bfL[2*p][0] = r[0]; bfL[2*p][1] = r[1];
                bfL[2*p+1][0] = r[2]; bfL[2*p+1][1] = r[3];
            }
            #pragma unroll
            for (int mt = 0; mt < 2; mt++)
                #pragma unroll
                for (int nt = 0; nt < 8; nt++) {
                    mma16816(acc[mt][nt], afH[mt], bfH[nt]);
                    mma16816(acc[mt][nt], afH[mt], bfL[nt]);
                    mma16816(acc[mt][nt], afL[mt], bfH[nt]);
                }
        }
        if (kt + 2 < KT) load_tile(kt + 2, (kt + 2) % 3);
    }

    #pragma unroll
    for (int mt = 0; mt < 2; mt++) {
        const int row = mblk + warp_m * 32 + mt * 16 + (lane >> 2);
        #pragma unroll
        for (int nt = 0; nt < 8; nt++) {
            const int col = nblk + warp_n * 64 + nt * 8 + (lane & 3) * 2;
            float2 v0 = make_float2(acc[mt][nt][0] * scale, acc[mt][nt][1] * scale);
            float2 v1 = make_float2(acc[mt][nt][2] * scale, acc[mt][nt][3] * scale);
            *reinterpret_cast<float2*>(C + (size_t)row * 1024 + col) = v0;
            *reinterpret_cast<float2*>(C + (size_t)(row + 8) * 1024 + col) = v1;
        }
    }
}

// ---------------------------------------------------------------------------
// conversions
// ---------------------------------------------------------------------------
__device__ __forceinline__ void split1(float x, fp16& h, fp16& l) {
    h = __float2half(x);
    l = __float2half(x - __half2float(h));
}

// batched over z=0..2: three separate Wm inputs
__global__ void split_fp16_b(const float* __restrict__ in0,
                             const float* __restrict__ in1,
                             const float* __restrict__ in2,
                             fp16* __restrict__ hi, fp16* __restrict__ lo,
                             float scale)
{
    const int z = blockIdx.z;
    const float* in = (z == 0) ? in0 : (z == 1) ? in1 : in2;
    const size_t zo = (size_t)z * 1024 * 1024;
    int i = (blockIdx.x * blockDim.x + threadIdx.x) * 4;
    float4 v = *reinterpret_cast<const float4*>(in + i);
    fp16 h[4], l[4];
    split1(v.x * scale, h[0], l[0]); split1(v.y * scale, h[1], l[1]);
    split1(v.z * scale, h[2], l[2]); split1(v.w * scale, h[3], l[3]);
    *reinterpret_cast<__half2*>(hi + zo + i)     = __halves2half2(h[0], h[1]);
    *reinterpret_cast<__half2*>(hi + zo + i + 2) = __halves2half2(h[2], h[3]);
    *reinterpret_cast<__half2*>(lo + zo + i)     = __halves2half2(l[0], l[1]);
    *reinterpret_cast<__half2*>(lo + zo + i + 2) = __halves2half2(l[2], l[3]);
}

__global__ void splitT_fp16(const float* __restrict__ in,
                            fp16* __restrict__ hi, fp16* __restrict__ lo,
                            float scale)
{
    __shared__ float t[32][33];
    const int x0 = blockIdx.x * 32, y0 = blockIdx.y * 32;
    const int tx = threadIdx.x, ty = threadIdx.y;
    #pragma unroll
    for (int r = ty; r < 32; r += 8)
        t[r][tx] = in[(size_t)(y0 + r) * 1024 + x0 + tx];
    __syncthreads();
    #pragma unroll
    for (int r = ty; r < 32; r += 8) {
        float v = t[tx][r] * scale;
        fp16 h, l;
        split1(v, h, l);
        hi[(size_t)(x0 + r) * 1024 + y0 + tx] = h;
        lo[(size_t)(x0 + r) * 1024 + y0 + tx] = l;
    }
}

// batched transpose-convert: z matrices contiguous at in/out + z*M1
__global__ void convT_fp16(const float* __restrict__ in, fp16* __restrict__ outT)
{
    const size_t zo = (size_t)blockIdx.z * 1024 * 1024;
    __shared__ float t[32][33];
    const int x0 = blockIdx.x * 32, y0 = blockIdx.y * 32;
    const int tx = threadIdx.x, ty = threadIdx.y;
    #pragma unroll
    for (int r = ty; r < 32; r += 8)
        t[r][tx] = in[zo + (size_t)(y0 + r) * 1024 + x0 + tx];
    __syncthreads();
    #pragma unroll
    for (int r = ty; r < 32; r += 8)
        outT[zo + (size_t)(x0 + r) * 1024 + y0 + tx] = __float2half(t[tx][r]);
}

// transpose-convert two non-contiguous inputs (Wl2, Wr2)
__global__ void convT_fp16_pair(const float* __restrict__ in0,
                                const float* __restrict__ in1,
                                fp16* __restrict__ outT)
{
    const int z = blockIdx.z;
    const float* in = z ? in1 : in0;
    const size_t zo = (size_t)z * 1024 * 1024;
    __shared__ float t[32][33];
    const int x0 = blockIdx.x * 32, y0 = blockIdx.y * 32;
    const int tx = threadIdx.x, ty = threadIdx.y;
    #pragma unroll
    for (int r = ty; r < 32; r += 8)
        t[r][tx] = in[(size_t)(y0 + r) * 1024 + x0 + tx];
    __syncthreads();
    #pragma unroll
    for (int r = ty; r < 32; r += 8)
        outT[zo + (size_t)(x0 + r) * 1024 + y0 + tx] = __float2half(t[tx][r]);
}

// batched feature conversion (z selects modality)
__global__ void tofp16_b(const float* __restrict__ in0,
                         const float* __restrict__ in1,
                         const float* __restrict__ in2,
                         fp16* __restrict__ out)
{
    const int z = blockIdx.z;
    const float* in = (z == 0) ? in0 : (z == 1) ? in1 : in2;
    fp16* o = out + (size_t)z * BATCH * 1024;
    int i = (blockIdx.x * blockDim.x + threadIdx.x) * 4;
    float4 v = *reinterpret_cast<const float4*>(in + i);
    *reinterpret_cast<__half2*>(o + i)     = __floats2half2_rn(v.x, v.y);
    *reinterpret_cast<__half2*>(o + i + 2) = __floats2half2_rn(v.z, v.w);
}

__global__ void bias_fold_kernel(
    const float* __restrict__ bt, const float* __restrict__ ba,
    const float* __restrict__ bv,
    const float* __restrict__ Wl1, const float* __restrict__ Wr1,
    float* __restrict__ bf)
{
    int g = blockIdx.x * blockDim.x + threadIdx.x;
    if (g >= 6 * 1024) return;
    int combo = g >> 10;
    int j = g & 1023;
    int m = combo % 3;
    const float* bvec = (m == 0) ? bt : (m == 1) ? ba : bv;
    const float* W = (combo < 3) ? Wl1 : Wr1;
    float s = 0.0f;
    for (int k = 0; k < 1024; k++) s += bvec[k] * W[k * 1024 + j];
    bf[g] = s;
}

// ---------------------------------------------------------------------------
// attention kernels (fp16 inputs, __expf fast path)
// ---------------------------------------------------------------------------
__device__ __forceinline__ float lrelu02(float x) { return x > 0.0f ? x : 0.2f * x; }

__device__ __forceinline__ float4 ld4h(const fp16* p) {
    uint2 u = *reinterpret_cast<const uint2*>(p);
    float2 f01 = __half22float2(*reinterpret_cast<__half2*>(&u.x));
    float2 f23 = __half22float2(*reinterpret_cast<__half2*>(&u.y));
    return make_float4(f01.x, f01.y, f23.x, f23.y);
}

__global__ __launch_bounds__(256) void gat1_kernel(
    const fp16* __restrict__ gl, const fp16* __restrict__ gr,
    const float* __restrict__ att, const float* __restrict__ b1,
    fp16* __restrict__ x1)
{
    const int b = blockIdx.x;
    const int h = threadIdx.x >> 5;
    const int lane = threadIdx.x & 31;
    const int dbase = lane * 4;

    const size_t base = (size_t)b * 3072 + h * 128 + dbase;
    float4 glv[3], grv[3];
    #pragma unroll
    for (int j = 0; j < 3; j++) glv[j] = ld4h(gl + base + j * 1024);
    #pragma unroll
    for (int i = 0; i < 3; i++) grv[i] = ld4h(gr + base + i * 1024);
    const float4 av = *reinterpret_cast<const float4*>(att + h * 128 + dbase);

    float e[3][3];
    #pragma unroll
    for (int i = 0; i < 3; i++)
        #pragma unroll
        for (int j = 0; j < 3; j++) {
            float s = av.x * lrelu02(glv[j].x + grv[i].x);
            s += av.y * lrelu02(glv[j].y + grv[i].y);
            s += av.z * lrelu02(glv[j].z + grv[i].z);
            s += av.w * lrelu02(glv[j].w + grv[i].w);
            e[i][j] = s;
        }
    #pragma unroll
    for (int i = 0; i < 3; i++)
        #pragma unroll
        for (int j = 0; j < 3; j++)
            #pragma unroll
            for (int o = 16; o > 0; o >>= 1)
                e[i][j] += __shfl_xor_sync(0xFFFFFFFFu, e[i][j], o);

    float alpha[3][3];
    #pragma unroll
    for (int i = 0; i < 3; i++) {
        float mx = fmaxf(e[i][0], fmaxf(e[i][1], e[i][2]));
        float p0 = __expf(e[i][0] - mx);
        float p1 = __expf(e[i][1] - mx);
        float p2 = __expf(e[i][2] - mx);
        float inv = 1.0f / (p0 + p1 + p2);
        alpha[i][0] = p0 * inv; alpha[i][1] = p1 * inv; alpha[i][2] = p2 * inv;
    }

    const float4 bb = *reinterpret_cast<const float4*>(b1 + h * 128 + dbase);
    #pragma unroll
    for (int i = 0; i < 3; i++) {
        float o[4];
        o[0] = alpha[i][0]*glv[0].x + alpha[i][1]*glv[1].x + alpha[i][2]*glv[2].x + bb.x;
        o[1] = alpha[i][0]*glv[0].y + alpha[i][1]*glv[1].y + alpha[i][2]*glv[2].y + bb.y;
        o[2] = alpha[i][0]*glv[0].z + alpha[i][1]*glv[1].z + alpha[i][2]*glv[2].z + bb.z;
        o[3] = alpha[i][0]*glv[0].w + alpha[i][1]*glv[1].w + alpha[i][2]*glv[2].w + bb.w;
        #pragma unroll
        for (int q = 0; q < 4; q++)
            o[q] = o[q] > 0.0f ? o[q] : (__expf(o[q]) - 1.0f);
        const size_t idx = (size_t)b * 3072 + i * 1024 + h * 128 + dbase;
        *reinterpret_cast<__half2*>(x1 + idx)     = __floats2half2_rn(o[0], o[1]);
        *reinterpret_cast<__half2*>(x1 + idx + 2) = __floats2half2_rn(o[2], o[3]);
    }
}

__global__ __launch_bounds__(256) void gat2_kernel(
    const fp16* __restrict__ gl, const fp16* __restrict__ gr,
    const float* __restrict__ att, const float* __restrict__ b2,
    float* __restrict__ out)
{
    const int b = blockIdx.x * 8 + (threadIdx.x >> 5);
    const int lane = threadIdx.x & 31;
    const fp16* glb = gl + (size_t)b * 3072;
    const fp16* grb = gr + (size_t)b * 3072;

    float e[9] = {0,0,0,0,0,0,0,0,0};
    #pragma unroll
    for (int c = 0; c < 8; c++) {
        const int d = c * 128 + lane * 4;
        const float4 av = *reinterpret_cast<const float4*>(att + d);
        float4 glv[3], grv[3];
        #pragma unroll
        for (int j = 0; j < 3; j++) glv[j] = ld4h(glb + j * 1024 + d);
        #pragma unroll
        for (int i = 0; i < 3; i++) grv[i] = ld4h(grb + i * 1024 + d);
        #pragma unroll
        for (int i = 0; i < 3; i++)
            #pragma unroll
            for (int j = 0; j < 3; j++) {
                float s = av.x * lrelu02(glv[j].x + grv[i].x);
                s += av.y * lrelu02(glv[j].y + grv[i].y);
                s += av.z * lrelu02(glv[j].z + grv[i].z);
                s += av.w * lrelu02(glv[j].w + grv[i].w);
                e[i * 3 + j] += s;
            }
    }
    #pragma unroll
    for (int k = 0; k < 9; k++)
        #pragma unroll
        for (int o = 16; o > 0; o >>= 1)
            e[k] += __shfl_xor_sync(0xFFFFFFFFu, e[k], o);

    float w[3] = {0.0f, 0.0f, 0.0f};
    #pragma unroll
    for (int i = 0; i < 3; i++) {
        float mx = fmaxf(e[i*3+0], fmaxf(e[i*3+1], e[i*3+2]));
        float p0 = __expf(e[i*3+0] - mx);
        float p1 = __expf(e[i*3+1] - mx);
        float p2 = __expf(e[i*3+2] - mx);
        float inv = 1.0f / (p0 + p1 + p2);
        w[0] += p0 * inv; w[1] += p1 * inv; w[2] += p2 * inv;
    }
    w[0] *= (1.0f/3.0f); w[1] *= (1.0f/3.0f); w[2] *= (1.0f/3.0f);

    #pragma unroll
    for (int c = 0; c < 8; c++) {
        const int d = c * 128 + lane * 4;
        const float4 bv = *reinterpret_cast<const float4*>(b2 + d);
        float4 g0 = ld4h(glb + 0 * 1024 + d);
        float4 g1 = ld4h(glb + 1 * 1024 + d);
        float4 g2 = ld4h(glb + 2 * 1024 + d);
        float4 o;
        o.x = w[0]*g0.x + w[1]*g1.x + w[2]*g2.x + bv.x;
        o.y = w[0]*g0.y + w[1]*g1.y + w[2]*g2.y + bv.y;
        o.z = w[0]*g0.z + w[1]*g1.z + w[2]*g2.z + bv.z;
        o.w = w[0]*g0.w + w[1]*g1.w + w[2]*g2.w + bv.w;
        *reinterpret_cast<float4*>(out + (size_t)b * 1024 + d) = o;
    }
}

// ---------------------------------------------------------------------------
// Launch
// ---------------------------------------------------------------------------
extern "C" void kernel_launch(void* const* d_in, const int* in_sizes, int n_in,
                              void* d_out, int out_size)
{
    const float* feats[3] = { (const float*)d_in[0], (const float*)d_in[1], (const float*)d_in[2] };
    const float* Wm[3]    = { (const float*)d_in[3], (const float*)d_in[5], (const float*)d_in[7] };
    const float* bt   = (const float*)d_in[4];
    const float* ba   = (const float*)d_in[6];
    const float* bv   = (const float*)d_in[8];
    const float* Wl1  = (const float*)d_in[9];
    const float* Wr1  = (const float*)d_in[10];
    const float* att1 = (const float*)d_in[11];
    const float* b1   = (const float*)d_in[12];
    const float* Wl2  = (const float*)d_in[13];
    const float* Wr2  = (const float*)d_in[14];
    const float* att2 = (const float*)d_in[15];
    const float* b2   = (const float*)d_in[16];
    float* out = (float*)d_out;

    float *Wf, *bf;
    fp16 *gl1, *gr1, *gl2, *gr2;
    fp16 *WmH, *WmL, *WT1H, *WT1L, *WT2, *WfT, *feat16, *x1;
    cudaGetSymbolAddress((void**)&Wf,  g_Wf);
    cudaGetSymbolAddress((void**)&bf,  g_bf);
    cudaGetSymbolAddress((void**)&gl1, g_gl1);
    cudaGetSymbolAddress((void**)&gr1, g_gr1);
    cudaGetSymbolAddress((void**)&gl2, g_gl2);
    cudaGetSymbolAddress((void**)&gr2, g_gr2);
    cudaGetSymbolAddress((void**)&WmH,  g_WmH);
    cudaGetSymbolAddress((void**)&WmL,  g_WmL);
    cudaGetSymbolAddress((void**)&WT1H, g_WT1H);
    cudaGetSymbolAddress((void**)&WT1L, g_WT1L);
    cudaGetSymbolAddress((void**)&WT2,  g_WT2);
    cudaGetSymbolAddress((void**)&WfT,  g_WfT);
    cudaGetSymbolAddress((void**)&feat16, g_feat);
    cudaGetSymbolAddress((void**)&x1, g_x1);

    cudaFuncSetAttribute(gemm_1t,
                         cudaFuncAttributeMaxDynamicSharedMemorySize, SMEM_1T);
    cudaFuncSetAttribute(gemm_fold,
                         cudaFuncAttributeMaxDynamicSharedMemorySize, SMEM_FOLD);

    const size_t M1 = 1024 * 1024;
    const dim3 tB(32, 8);

    const float S_FOLD = 1024.0f;

    // 1. weight splits / conversions (batched where possible)
    splitT_fp16<<<dim3(32, 32), tB>>>(Wl1, WT1H, WT1L, S_FOLD);
    splitT_fp16<<<dim3(32, 32), tB>>>(Wr1, WT1H + M1, WT1L + M1, S_FOLD);
    convT_fp16_pair<<<dim3(32, 32, 2), tB>>>(Wl2, Wr2, WT2);
    split_fp16_b<<<dim3(1024, 1, 3), 256>>>(Wm[0], Wm[1], Wm[2], WmH, WmL, S_FOLD);

    // 2. fold (batched, c = 2m+side)
    gemm_fold<<<dim3(8, 8, 6), 256, SMEM_FOLD>>>(WmH, WmL, WT1H, WT1L, Wf,
                                                 1.0f / (S_FOLD * S_FOLD));
    bias_fold_kernel<<<24, 256>>>(bt, ba, bv, Wl1, Wr1, bf);
    convT_fp16<<<dim3(32, 32, 6), tB>>>(Wf, WfT);

    // 3. feature conversion (one batched launch)
    tofp16_b<<<dim3(BATCH, 1, 3), 256>>>(feats[0], feats[1], feats[2], feat16);

    // 4. layer-1 merged GEMMs, all 3 modalities in one launch (grid.z=3)
    gemm_1t<<<dim3(16, BATCH / 128, 3), 256, SMEM_1T>>>(
        BATCH, 1024,
        feat16, 1024, (size_t)BATCH * 1024,
        WfT, 1024, 2 * M1,
        gl1, gr1, 3072, 1024,
        bf, bf + 3 * 1024, 1024);

    // 5. GAT1 -> x1 (fp16)
    gat1_kernel<<<BATCH, 256>>>(gl1, gr1, att1, b1, x1);

    // 6. layer-2 merged GEMM
    gemm_1t<<<dim3(16, (3 * BATCH) / 128, 1), 256, SMEM_1T>>>(
        3 * BATCH, 1024,
        x1, 1024, 0,
        WT2, 1024, 0,
        gl2, gr2, 1024, 0,
        nullptr, nullptr, 0);

    // 7. GAT2 -> out
    gat2_kernel<<<BATCH / 8, 256>>>(gl2, gr2, att2, b2, out);
}

// round 10
// speedup vs baseline: 7.2624x; 1.0107x over previous
#include <cuda_runtime.h>
#include <cuda_fp16.h>
#include <cstdint>
#include <math.h>

// ---------------------------------------------------------------------------
// IntraSentenceGNN on GB300 (sm_103 base ISA): mma.sync fp16 GEMMs with
// ldmatrix fragment loads, 2 CTAs/SM, single-sync mainloop, mega-batched
// prologue (one launch), 2-term fold, fp16 intermediates, __expf attention.
//
// Launches: mega_prep -> gemm_fold -> convT(Wf) -> gemm_1t(L1,z=3) -> gat1
//           -> gemm_1t(L2) -> gat2   (7 total)
// ---------------------------------------------------------------------------

#define BATCH 32768
#define HDIM  1024

typedef __half fp16;

// ------------------------------ scratch -----------------------------------
__device__ __align__(256) float g_Wf [6 * 1024 * 1024];
__device__ __align__(256) float g_bf [6 * 1024];
__device__ __align__(256) fp16 g_gl1[BATCH * 3 * HDIM];
__device__ __align__(256) fp16 g_gr1[BATCH * 3 * HDIM];
__device__ __align__(256) fp16 g_gl2[BATCH * 3 * HDIM];
__device__ __align__(256) fp16 g_gr2[BATCH * 3 * HDIM];

__device__ __align__(256) fp16 g_WmH [3 * 1024 * 1024];
__device__ __align__(256) fp16 g_WT1H[2 * 1024 * 1024];
__device__ __align__(256) fp16 g_WT1L[2 * 1024 * 1024];
__device__ __align__(256) fp16 g_WT2 [2 * 1024 * 1024];   // [Wl2^T | Wr2^T]
__device__ __align__(256) fp16 g_WfT [6 * 1024 * 1024];   // c = 2m+side
__device__ __align__(256) fp16 g_feat[3 * BATCH * 1024];
__device__ __align__(256) fp16 g_x1  [BATCH * 3 * 1024];

// --------------------------- PTX helpers ----------------------------------
__device__ __forceinline__ uint32_t smem_u32(const void* p) {
    uint32_t a;
    asm("{ .reg .u64 t; cvta.to.shared.u64 t, %1; cvt.u32.u64 %0, t; }"
        : "=r"(a) : "l"(p));
    return a;
}
__device__ __forceinline__ void cp16(uint32_t sdst, const void* gsrc) {
    asm volatile("cp.async.cg.shared.global [%0], [%1], 16;" :: "r"(sdst), "l"(gsrc));
}
__device__ __forceinline__ void cp_commit() {
    asm volatile("cp.async.commit_group;" ::: "memory");
}
__device__ __forceinline__ void cp_wait1() {
    asm volatile("cp.async.wait_group 1;" ::: "memory");
}
__device__ __forceinline__ void cp_wait0() {
    asm volatile("cp.async.wait_group 0;" ::: "memory");
}

__device__ __forceinline__ uint32_t sw_addr(uint32_t base, int row, int colb) {
    uint32_t off = (uint32_t)(row * 128 + colb);
    return base + (off ^ ((off >> 3) & 0x70));
}

__device__ __forceinline__ void ldsm4(uint32_t addr, uint32_t* r) {
    asm volatile("ldmatrix.sync.aligned.m8n8.x4.shared.b16 {%0,%1,%2,%3}, [%4];"
        : "=r"(r[0]), "=r"(r[1]), "=r"(r[2]), "=r"(r[3]) : "r"(addr));
}

__device__ __forceinline__ void mma16816(float* c, const uint32_t* a, const uint32_t* b) {
    asm volatile(
        "mma.sync.aligned.m16n8k16.row.col.f32.f16.f16.f32 "
        "{%0,%1,%2,%3}, {%4,%5,%6,%7}, {%8,%9}, {%0,%1,%2,%3};"
        : "+f"(c[0]), "+f"(c[1]), "+f"(c[2]), "+f"(c[3])
        : "r"(a[0]), "r"(a[1]), "r"(a[2]), "r"(a[3]), "r"(b[0]), "r"(b[1]));
}

__device__ __forceinline__ void load_sub(const fp16* src, int blk, int ld,
                                         uint32_t rb, int kofs, int tid) {
    #pragma unroll
    for (int i = 0; i < 4; i++) {
        const int c = tid + i * 256;
        const int row = c >> 3, kc = c & 7;
        const void* g = src + (size_t)(blk + row) * ld + kofs + kc * 8;
        uint32_t off = (uint32_t)(row * 128 + kc * 16);
        off ^= (off >> 3) & 0x70;
        cp16(rb + off, g);
    }
}

// ---------------------------------------------------------------------------
// 1-term fp16 GEMM over [M,2048] with grid.z batching (unchanged from R9).
// ---------------------------------------------------------------------------
#define SMEM_1T (3 * 32768)

__global__ __launch_bounds__(256, 2) void gemm_1t(
    int M, int K,
    const fp16* __restrict__ A, int lda, size_t aZ,
    const fp16* __restrict__ B, int ldb, size_t bZ,
    fp16* __restrict__ Cl, fp16* __restrict__ Cr, int ldc, size_t cZ,
    const float* __restrict__ biasL, const float* __restrict__ biasR, int biasZ)
{
    const int z = blockIdx.z;
    A += (size_t)z * aZ;
    B += (size_t)z * bZ;
    Cl += (size_t)z * cZ;
    Cr += (size_t)z * cZ;
    if (biasL) { biasL += (size_t)z * biasZ; biasR += (size_t)z * biasZ; }

    extern __shared__ char smem[];
    const uint32_t sbase = smem_u32(smem);
    const int tid  = threadIdx.x;
    const int wid  = tid >> 5;
    const int lane = tid & 31;
    const int warp_m = wid & 3;
    const int warp_n = wid >> 2;

    const int mblk = blockIdx.y * 128;
    const int nblk = blockIdx.x * 128;
    const int side = nblk >> 10;
    fp16* C = side ? Cr : Cl;
    const float* bias = side ? biasR : biasL;
    const int colbase = nblk & 1023;
    const int KT = K >> 6;

    auto load_tile = [&](int kt, int s) {
        const uint32_t st = sbase + s * 32768;
        load_sub(A, mblk, lda, st,         kt * 64, tid);
        load_sub(B, nblk, ldb, st + 16384, kt * 64, tid);
        cp_commit();
    };

    float acc[2][8][4];
    #pragma unroll
    for (int mt = 0; mt < 2; mt++)
        #pragma unroll
        for (int nt = 0; nt < 8; nt++)
            #pragma unroll
            for (int q = 0; q < 4; q++) acc[mt][nt][q] = 0.0f;

    load_tile(0, 0);
    load_tile(1, 1);

    const int qa_r = ((lane >> 3) & 1) * 8 + (lane & 7);
    const int qa_c = (lane >> 4) * 16;
    const int qb_r = (lane >> 4) * 8 + (lane & 7);
    const int qb_c = ((lane >> 3) & 1) * 16;

    for (int kt = 0; kt < KT; kt++) {
        if (kt + 1 < KT) cp_wait1(); else cp_wait0();
        __syncthreads();

        const uint32_t st = sbase + (kt % 3) * 32768;
        const uint32_t sA = st, sB = st + 16384;

        #pragma unroll
        for (int ks = 0; ks < 4; ks++) {
            uint32_t afr[2][4];
            #pragma unroll
            for (int mt = 0; mt < 2; mt++)
                ldsm4(sw_addr(sA, warp_m * 32 + mt * 16 + qa_r, ks * 32 + qa_c), afr[mt]);
            uint32_t bfr[8][2];
            #pragma unroll
            for (int p = 0; p < 4; p++) {
                uint32_t r[4];
                ldsm4(sw_addr(sB, warp_n * 64 + p * 16 + qb_r, ks * 32 + qb_c), r);
                bfr[2*p][0] = r[0]; bfr[2*p][1] = r[1];
                bfr[2*p+1][0] = r[2]; bfr[2*p+1][1] = r[3];
            }
            #pragma unroll
            for (int mt = 0; mt < 2; mt++)
                #pragma unroll
                for (int nt = 0; nt < 8; nt++)
                    mma16816(acc[mt][nt], afr[mt], bfr[nt]);
        }
        if (kt + 2 < KT) load_tile(kt + 2, (kt + 2) % 3);
    }

    #pragma unroll
    for (int mt = 0; mt < 2; mt++) {
        const int row = mblk + warp_m * 32 + mt * 16 + (lane >> 2);
        #pragma unroll
        for (int nt = 0; nt < 8; nt++) {
            const int col = colbase + warp_n * 64 + nt * 8 + (lane & 3) * 2;
            float b0 = 0.0f, b1 = 0.0f;
            if (bias) { b0 = bias[col]; b1 = bias[col + 1]; }
            *reinterpret_cast<__half2*>(C + (size_t)row * ldc + col) =
                __floats2half2_rn(acc[mt][nt][0] + b0, acc[mt][nt][1] + b1);
            *reinterpret_cast<__half2*>(C + (size_t)(row + 8) * ldc + col) =
                __floats2half2_rn(acc[mt][nt][2] + b0, acc[mt][nt][3] + b1);
        }
    }
}

// ---------------------------------------------------------------------------
// 2-term fold GEMM: c = blockIdx.z = 2m+side; Wf[c] = Wm[m] @ W{l|r}1.
// A = WmH single fp16 (unscaled); B = W1 * S_FOLD as hi/lo split.
// ---------------------------------------------------------------------------
#define SMEM_FOLD (3 * 49152)

__global__ __launch_bounds__(256, 1) void gemm_fold(
    const fp16* __restrict__ WmH,
    const fp16* __restrict__ W1H, const fp16* __restrict__ W1L,
    float* __restrict__ Wf, float scale)
{
    const size_t M1 = 1024 * 1024;
    const int c = blockIdx.z;
    const int m = c >> 1, side = c & 1;
    const fp16* A  = WmH + (size_t)m * M1;
    const fp16* Bh = W1H + (size_t)side * M1;
    const fp16* Bl = W1L + (size_t)side * M1;
    float* C = Wf + (size_t)c * M1;

    extern __shared__ char smem[];
    const uint32_t sbase = smem_u32(smem);
    const int tid  = threadIdx.x;
    const int wid  = tid >> 5;
    const int lane = tid & 31;
    const int warp_m = wid & 3;
    const int warp_n = wid >> 2;

    const int mblk = blockIdx.y * 128;
    const int nblk = blockIdx.x * 128;
    const int KT = 16;

    auto load_tile = [&](int kt, int s) {
        const uint32_t st = sbase + s * 49152;
        load_sub(A,  mblk, 1024, st,         kt * 64, tid);
        load_sub(Bh, nblk, 1024, st + 16384, kt * 64, tid);
        load_sub(Bl, nblk, 1024, st + 32768, kt * 64, tid);
        cp_commit();
    };

    float acc[2][8][4];
    #pragma unroll
    for (int mt = 0; mt < 2; mt++)
        #pragma unroll
        for (int nt = 0; nt < 8; nt++)
            #pragma unroll
            for (int q = 0; q < 4; q++) acc[mt][nt][q] = 0.0f;

    load_tile(0, 0);
    load_tile(1, 1);

    const int qa_r = ((lane >> 3) & 1) * 8 + (lane & 7);
    const int qa_c = (lane >> 4) * 16;
    const int qb_r = (lane >> 4) * 8 + (lane & 7);
    const int qb_c = ((lane >> 3) & 1) * 16;

    for (int kt = 0; kt < KT; kt++) {
        if (kt + 1 < KT) cp_wait1(); else cp_wait0();
        __syncthreads();

        const uint32_t st = sbase + (kt % 3) * 49152;
        const uint32_t sA = st, sBh = st + 16384, sBl = st + 32768;

        #pragma unroll
        for (int ks = 0; ks < 4; ks++) {
            uint32_t afr[2][4];
            #pragma unroll
            for (int mt = 0; mt < 2; mt++)
                ldsm4(sw_addr(sA, warp_m * 32 + mt * 16 + qa_r, ks * 32 + qa_c), afr[mt]);
            uint32_t bfH[8][2], bfL[8][2];
            #pragma unroll
            for (int p = 0; p < 4; p++) {
                const int rr = warp_n * 64 + p * 16 + qb_r;
                const int cc = ks * 32 + qb_c;
                uint32_t r[4];
                ldsm4(sw_addr(sBh, rr, cc), r);
                bfH[2*p][0] = r[0]; bfH[2*p][1] = r[1];
                bfH[2*p+1][0] = r[2]; bfH[2*p+1][1] = r[3];
                ldsm4(sw_addr(sBl, rr, cc), r);
                bfL[2*p][0] = r[0]; bfL[2*p][1] = r[1];
                bfL[2*p+1][0] = r[2]; bfL[2*p+1][1] = r[3];
            }
            #pragma unroll
            for (int mt = 0; mt < 2; mt++)
                #pragma unroll
                for (int nt = 0; nt < 8; nt++) {
                    mma16816(acc[mt][nt], afr[mt], bfH[nt]);
                    mma16816(acc[mt][nt], afr[mt], bfL[nt]);
                }
        }
        if (kt + 2 < KT) load_tile(kt + 2, (kt + 2) % 3);
    }

    #pragma unroll
    for (int mt = 0; mt < 2; mt++) {
        const int row = mblk + warp_m * 32 + mt * 16 + (lane >> 2);
        #pragma unroll
        for (int nt = 0; nt < 8; nt++) {
            const int col = nblk + warp_n * 64 + nt * 8 + (lane & 3) * 2;
            float2 v0 = make_float2(acc[mt][nt][0] * scale, acc[mt][nt][1] * scale);
            float2 v1 = make_float2(acc[mt][nt][2] * scale, acc[mt][nt][3] * scale);
            *reinterpret_cast<float2*>(C + (size_t)row * 1024 + col) = v0;
            *reinterpret_cast<float2*>(C + (size_t)(row + 8) * 1024 + col) = v1;
        }
    }
}

// ---------------------------------------------------------------------------
// mega_prep: ALL independent prologue work in one launch (flat grid dispatch)
//   [0,2048)      splitT of Wl1 (z=0) / Wr1 (z=1) -> WT1H/WT1L (prescaled)
//   [2048,4096)   transpose-convert Wl2 (z=0) / Wr2 (z=1) -> WT2
//   [4096,7168)   Wm -> WmH plain fp16 (1024 elems/block)
//   [7168,19456)  feats -> feat16 (8192 elems/block)
//   [19456,19480) bias fold: bf[c][j] = b_{c%3} . W{l|r}1[:,j]
// ---------------------------------------------------------------------------
__device__ __forceinline__ void split1(float x, fp16& h, fp16& l) {
    h = __float2half(x);
    l = __float2half(x - __half2float(h));
}

#define PREP_BLOCKS 19480

__global__ __launch_bounds__(256) void mega_prep(
    const float* __restrict__ Wl1, const float* __restrict__ Wr1,
    const float* __restrict__ Wl2, const float* __restrict__ Wr2,
    const float* __restrict__ Wm0, const float* __restrict__ Wm1,
    const float* __restrict__ Wm2,
    const float* __restrict__ f0, const float* __restrict__ f1,
    const float* __restrict__ f2,
    const float* __restrict__ bt, const float* __restrict__ ba,
    const float* __restrict__ bv,
    fp16* __restrict__ WT1H, fp16* __restrict__ WT1L, fp16* __restrict__ WT2,
    fp16* __restrict__ WmH, fp16* __restrict__ feat16,
    float* __restrict__ bf, float sfold)
{
    const size_t M1 = 1024 * 1024;
    __shared__ float t[32][33];
    const int bid = blockIdx.x;
    const int tid = threadIdx.x;
    const int tx = tid & 31, ty = tid >> 5;

    if (bid < 2048) {
        // splitT + prescale: W1^T hi/lo
        const int z = bid >> 10, tl = bid & 1023;
        const float* in = z ? Wr1 : Wl1;
        fp16* hi = WT1H + (size_t)z * M1;
        fp16* lo = WT1L + (size_t)z * M1;
        const int x0 = (tl & 31) * 32, y0 = (tl >> 5) * 32;
        #pragma unroll
        for (int r = ty; r < 32; r += 8)
            t[r][tx] = in[(size_t)(y0 + r) * 1024 + x0 + tx];
        __syncthreads();
        #pragma unroll
        for (int r = ty; r < 32; r += 8) {
            float v = t[tx][r] * sfold;
            fp16 h, l;
            split1(v, h, l);
            hi[(size_t)(x0 + r) * 1024 + y0 + tx] = h;
            lo[(size_t)(x0 + r) * 1024 + y0 + tx] = l;
        }
    } else if (bid < 4096) {
        // transpose-convert W2
        const int rel = bid - 2048;
        const int z = rel >> 10, tl = rel & 1023;
        const float* in = z ? Wr2 : Wl2;
        fp16* o = WT2 + (size_t)z * M1;
        const int x0 = (tl & 31) * 32, y0 = (tl >> 5) * 32;
        #pragma unroll
        for (int r = ty; r < 32; r += 8)
            t[r][tx] = in[(size_t)(y0 + r) * 1024 + x0 + tx];
        __syncthreads();
        #pragma unroll
        for (int r = ty; r < 32; r += 8)
            o[(size_t)(x0 + r) * 1024 + y0 + tx] = __float2half(t[tx][r]);
    } else if (bid < 7168) {
        // Wm plain fp16 conversion (row-major preserved; Wm is A side, [D,H] row-major
        // -> used as A [1024,1024] with lda=1024; K-major rows ✓)
        const int rel = bid - 4096;
        const int m = rel >> 10, blk = rel & 1023;
        const float* in = (m == 0) ? Wm0 : (m == 1) ? Wm1 : Wm2;
        fp16* o = WmH + (size_t)m * M1;
        const int i = blk * 1024 + tid * 4;
        float4 v = *reinterpret_cast<const float4*>(in + i);
        *reinterpret_cast<__half2*>(o + i)     = __floats2half2_rn(v.x, v.y);
        *reinterpret_cast<__half2*>(o + i + 2) = __floats2half2_rn(v.z, v.w);
    } else if (bid < 19456) {
        // feature conversion, 8192 elems per block
        const int rel = bid - 7168;
        const int m = rel / 4096, blk = rel % 4096;
        const float* in = (m == 0) ? f0 : (m == 1) ? f1 : f2;
        fp16* o = feat16 + (size_t)m * BATCH * 1024;
        const int base = blk * 8192;
        #pragma unroll
        for (int u = 0; u < 8; u++) {
            const int i = base + (u * 256 + tid) * 4;
            float4 v = *reinterpret_cast<const float4*>(in + i);
            *reinterpret_cast<__half2*>(o + i)     = __floats2half2_rn(v.x, v.y);
            *reinterpret_cast<__half2*>(o + i + 2) = __floats2half2_rn(v.z, v.w);
        }
    } else {
        // bias fold
        const int g = (bid - 19456) * 256 + tid;
        const int combo = g >> 10, j = g & 1023;
        const int m = combo % 3;
        const float* bvec = (m == 0) ? bt : (m == 1) ? ba : bv;
        const float* W = (combo < 3) ? Wl1 : Wr1;
        float s = 0.0f;
        for (int k = 0; k < 1024; k++) s += bvec[k] * W[k * 1024 + j];
        bf[g] = s;
    }
}

// batched transpose-convert: z matrices contiguous at in/out + z*M1 (Wf->WfT)
__global__ void convT_fp16(const float* __restrict__ in, fp16* __restrict__ outT)
{
    const size_t zo = (size_t)blockIdx.z * 1024 * 1024;
    __shared__ float t[32][33];
    const int x0 = blockIdx.x * 32, y0 = blockIdx.y * 32;
    const int tx = threadIdx.x, ty = threadIdx.y;
    #pragma unroll
    for (int r = ty; r < 32; r += 8)
        t[r][tx] = in[zo + (size_t)(y0 + r) * 1024 + x0 + tx];
    __syncthreads();
    #pragma unroll
    for (int r = ty; r < 32; r += 8)
        outT[zo + (size_t)(x0 + r) * 1024 + y0 + tx] = __float2half(t[tx][r]);
}

// ---------------------------------------------------------------------------
// attention kernels (fp16 inputs, __expf fast path)
// ---------------------------------------------------------------------------
__device__ __forceinline__ float lrelu02(float x) { return x > 0.0f ? x : 0.2f * x; }

__device__ __forceinline__ float4 ld4h(const fp16* p) {
    uint2 u = *reinterpret_cast<const uint2*>(p);
    float2 f01 = __half22float2(*reinterpret_cast<__half2*>(&u.x));
    float2 f23 = __half22float2(*reinterpret_cast<__half2*>(&u.y));
    return make_float4(f01.x, f01.y, f23.x, f23.y);
}

__global__ __launch_bounds__(256) void gat1_kernel(
    const fp16* __restrict__ gl, const fp16* __restrict__ gr,
    const float* __restrict__ att, const float* __restrict__ b1,
    fp16* __restrict__ x1)
{
    const int b = blockIdx.x;
    const int h = threadIdx.x >> 5;
    const int lane = threadIdx.x & 31;
    const int dbase = lane * 4;

    const size_t base = (size_t)b * 3072 + h * 128 + dbase;
    float4 glv[3], grv[3];
    #pragma unroll
    for (int j = 0; j < 3; j++) glv[j] = ld4h(gl + base + j * 1024);
    #pragma unroll
    for (int i = 0; i < 3; i++) grv[i] = ld4h(gr + base + i * 1024);
    const float4 av = *reinterpret_cast<const float4*>(att + h * 128 + dbase);

    float e[3][3];
    #pragma unroll
    for (int i = 0; i < 3; i++)
        #pragma unroll
        for (int j = 0; j < 3; j++) {
            float s = av.x * lrelu02(glv[j].x + grv[i].x);
            s += av.y * lrelu02(glv[j].y + grv[i].y);
            s += av.z * lrelu02(glv[j].z + grv[i].z);
            s += av.w * lrelu02(glv[j].w + grv[i].w);
            e[i][j] = s;
        }
    #pragma unroll
    for (int i = 0; i < 3; i++)
        #pragma unroll
        for (int j = 0; j < 3; j++)
            #pragma unroll
            for (int o = 16; o > 0; o >>= 1)
                e[i][j] += __shfl_xor_sync(0xFFFFFFFFu, e[i][j], o);

    float alpha[3][3];
    #pragma unroll
    for (int i = 0; i < 3; i++) {
        float mx = fmaxf(e[i][0], fmaxf(e[i][1], e[i][2]));
        float p0 = __expf(e[i][0] - mx);
        float p1 = __expf(e[i][1] - mx);
        float p2 = __expf(e[i][2] - mx);
        float inv = 1.0f / (p0 + p1 + p2);
        alpha[i][0] = p0 * inv; alpha[i][1] = p1 * inv; alpha[i][2] = p2 * inv;
    }

    const float4 bb = *reinterpret_cast<const float4*>(b1 + h * 128 + dbase);
    #pragma unroll
    for (int i = 0; i < 3; i++) {
        float o[4];
        o[0] = alpha[i][0]*glv[0].x + alpha[i][1]*glv[1].x + alpha[i][2]*glv[2].x + bb.x;
        o[1] = alpha[i][0]*glv[0].y + alpha[i][1]*glv[1].y + alpha[i][2]*glv[2].y + bb.y;
        o[2] = alpha[i][0]*glv[0].z + alpha[i][1]*glv[1].z + alpha[i][2]*glv[2].z + bb.z;
        o[3] = alpha[i][0]*glv[0].w + alpha[i][1]*glv[1].w + alpha[i][2]*glv[2].w + bb.w;
        #pragma unroll
        for (int q = 0; q < 4; q++)
            o[q] = o[q] > 0.0f ? o[q] : (__expf(o[q]) - 1.0f);
        const size_t idx = (size_t)b * 3072 + i * 1024 + h * 128 + dbase;
        *reinterpret_cast<__half2*>(x1 + idx)     = __floats2half2_rn(o[0], o[1]);
        *reinterpret_cast<__half2*>(x1 + idx + 2) = __floats2half2_rn(o[2], o[3]);
    }
}

__global__ __launch_bounds__(256) void gat2_kernel(
    const fp16* __restrict__ gl, const fp16* __restrict__ gr,
    const float* __restrict__ att, const float* __restrict__ b2,
    float* __restrict__ out)
{
    const int b = blockIdx.x * 8 + (threadIdx.x >> 5);
    const int lane = threadIdx.x & 31;
    const fp16* glb = gl + (size_t)b * 3072;
    const fp16* grb = gr + (size_t)b * 3072;

    float e[9] = {0,0,0,0,0,0,0,0,0};
    #pragma unroll
    for (int c = 0; c < 8; c++) {
        const int d = c * 128 + lane * 4;
        const float4 av = *reinterpret_cast<const float4*>(att + d);
        float4 glv[3], grv[3];
        #pragma unroll
        for (int j = 0; j < 3; j++) glv[j] = ld4h(glb + j * 1024 + d);
        #pragma unroll
        for (int i = 0; i < 3; i++) grv[i] = ld4h(grb + i * 1024 + d);
        #pragma unroll
        for (int i = 0; i < 3; i++)
            #pragma unroll
            for (int j = 0; j < 3; j++) {
                float s = av.x * lrelu02(glv[j].x + grv[i].x);
                s += av.y * lrelu02(glv[j].y + grv[i].y);
                s += av.z * lrelu02(glv[j].z + grv[i].z);
                s += av.w * lrelu02(glv[j].w + grv[i].w);
                e[i * 3 + j] += s;
            }
    }
    #pragma unroll
    for (int k = 0; k < 9; k++)
        #pragma unroll
        for (int o = 16; o > 0; o >>= 1)
            e[k] += __shfl_xor_sync(0xFFFFFFFFu, e[k], o);

    float w[3] = {0.0f, 0.0f, 0.0f};
    #pragma unroll
    for (int i = 0; i < 3; i++) {
        float mx = fmaxf(e[i*3+0], fmaxf(e[i*3+1], e[i*3+2]));
        float p0 = __expf(e[i*3+0] - mx);
        float p1 = __expf(e[i*3+1] - mx);
        float p2 = __expf(e[i*3+2] - mx);
        float inv = 1.0f / (p0 + p1 + p2);
        w[0] += p0 * inv; w[1] += p1 * inv; w[2] += p2 * inv;
    }
    w[0] *= (1.0f/3.0f); w[1] *= (1.0f/3.0f); w[2] *= (1.0f/3.0f);

    #pragma unroll
    for (int c = 0; c < 8; c++) {
        const int d = c * 128 + lane * 4;
        const float4 bv = *reinterpret_cast<const float4*>(b2 + d);
        float4 g0 = ld4h(glb + 0 * 1024 + d);
        float4 g1 = ld4h(glb + 1 * 1024 + d);
        float4 g2 = ld4h(glb + 2 * 1024 + d);
        float4 o;
        o.x = w[0]*g0.x + w[1]*g1.x + w[2]*g2.x + bv.x;
        o.y = w[0]*g0.y + w[1]*g1.y + w[2]*g2.y + bv.y;
        o.z = w[0]*g0.z + w[1]*g1.z + w[2]*g2.z + bv.z;
        o.w = w[0]*g0.w + w[1]*g1.w + w[2]*g2.w + bv.w;
        *reinterpret_cast<float4*>(out + (size_t)b * 1024 + d) = o;
    }
}

// ---------------------------------------------------------------------------
// Launch
// ---------------------------------------------------------------------------
extern "C" void kernel_launch(void* const* d_in, const int* in_sizes, int n_in,
                              void* d_out, int out_size)
{
    const float* feats[3] = { (const float*)d_in[0], (const float*)d_in[1], (const float*)d_in[2] };
    const float* Wm[3]    = { (const float*)d_in[3], (const float*)d_in[5], (const float*)d_in[7] };
    const float* bt   = (const float*)d_in[4];
    const float* ba   = (const float*)d_in[6];
    const float* bv   = (const float*)d_in[8];
    const float* Wl1  = (const float*)d_in[9];
    const float* Wr1  = (const float*)d_in[10];
    const float* att1 = (const float*)d_in[11];
    const float* b1   = (const float*)d_in[12];
    const float* Wl2  = (const float*)d_in[13];
    const float* Wr2  = (const float*)d_in[14];
    const float* att2 = (const float*)d_in[15];
    const float* b2   = (const float*)d_in[16];
    float* out = (float*)d_out;

    float *Wf, *bf;
    fp16 *gl1, *gr1, *gl2, *gr2;
    fp16 *WmH, *WT1H, *WT1L, *WT2, *WfT, *feat16, *x1;
    cudaGetSymbolAddress((void**)&Wf,  g_Wf);
    cudaGetSymbolAddress((void**)&bf,  g_bf);
    cudaGetSymbolAddress((void**)&gl1, g_gl1);
    cudaGetSymbolAddress((void**)&gr1, g_gr1);
    cudaGetSymbolAddress((void**)&gl2, g_gl2);
    cudaGetSymbolAddress((void**)&gr2, g_gr2);
    cudaGetSymbolAddress((void**)&WmH,  g_WmH);
    cudaGetSymbolAddress((void**)&WT1H, g_WT1H);
    cudaGetSymbolAddress((void**)&WT1L, g_WT1L);
    cudaGetSymbolAddress((void**)&WT2,  g_WT2);
    cudaGetSymbolAddress((void**)&WfT,  g_WfT);
    cudaGetSymbolAddress((void**)&feat16, g_feat);
    cudaGetSymbolAddress((void**)&x1, g_x1);

    cudaFuncSetAttribute(gemm_1t,
                         cudaFuncAttributeMaxDynamicSharedMemorySize, SMEM_1T);
    cudaFuncSetAttribute(gemm_fold,
                         cudaFuncAttributeMaxDynamicSharedMemorySize, SMEM_FOLD);

    const size_t M1 = 1024 * 1024;
    const float S_FOLD = 1024.0f;

    // 1. ALL prologue conversions + bias fold in one launch
    mega_prep<<<PREP_BLOCKS, 256>>>(
        Wl1, Wr1, Wl2, Wr2, Wm[0], Wm[1], Wm[2],
        feats[0], feats[1], feats[2], bt, ba, bv,
        WT1H, WT1L, WT2, WmH, feat16, bf, S_FOLD);

    // 2. fold GEMM (2-term, batched c = 2m+side)
    gemm_fold<<<dim3(8, 8, 6), 256, SMEM_FOLD>>>(WmH, WT1H, WT1L, Wf,
                                                 1.0f / S_FOLD);
    convT_fp16<<<dim3(32, 32, 6), dim3(32, 8)>>>(Wf, WfT);

    // 3. layer-1 merged GEMMs, all 3 modalities in one launch (grid.z=3)
    gemm_1t<<<dim3(16, BATCH / 128, 3), 256, SMEM_1T>>>(
        BATCH, 1024,
        feat16, 1024, (size_t)BATCH * 1024,
        WfT, 1024, 2 * M1,
        gl1, gr1, 3072, 1024,
        bf, bf + 3 * 1024, 1024);

    // 4. GAT1 -> x1 (fp16)
    gat1_kernel<<<BATCH, 256>>>(gl1, gr1, att1, b1, x1);

    // 5. layer-2 merged GEMM
    gemm_1t<<<dim3(16, (3 * BATCH) / 128, 1), 256, SMEM_1T>>>(
        3 * BATCH, 1024,
        x1, 1024, 0,
        WT2, 1024, 0,
        gl2, gr2, 1024, 0,
        nullptr, nullptr, 0);

    // 6. GAT2 -> out
    gat2_kernel<<<BATCH / 8, 256>>>(gl2, gr2, att2, b2, out);
}